// round 9
// baseline (speedup 1.0000x reference)
#include <cuda_runtime.h>
#include <cuda_fp16.h>
#include <cstdint>

#define B_   8
#define N_   4096
#define D_   1024

// scratch (device globals; no allocations allowed)
__device__ float g_v [(size_t)B_ * N_ * D_];   // v projection      128 MB
__device__ float g_G [(size_t)B_ * D_ * D_];   // G = x^T x          32 MB
__device__ float g_T1[(size_t)B_ * D_ * D_];   // T1 = G Wk^T        32 MB
__device__ float g_L [(size_t)B_ * D_ * D_];   // logits -> attn     32 MB
__device__ float g_s [(size_t)B_ * D_];        // s = x^T 1
__device__ float g_u [(size_t)B_ * D_];        // u = Wq s
__device__ float g_w [(size_t)B_ * D_];        // w' = Wk s + N*bk

__device__ __forceinline__ void mma16(float* c, const uint32_t* a,
                                      const uint32_t* b) {
    asm("mma.sync.aligned.m16n8k16.row.col.f32.f16.f16.f32 "
        "{%0,%1,%2,%3}, {%4,%5,%6,%7}, {%8,%9}, {%0,%1,%2,%3};"
        : "+f"(c[0]), "+f"(c[1]), "+f"(c[2]), "+f"(c[3])
        : "r"(a[0]), "r"(a[1]), "r"(a[2]), "r"(a[3]), "r"(b[0]), "r"(b[1]));
}

// split x = hi + lo, both fp16 (11-bit mantissa each -> ~22-bit coverage)
__device__ __forceinline__ void split_h(float x, uint16_t& h, uint16_t& l) {
    __half hh = __float2half_rn(x);
    float hf = __half2float(hh);
    h = __half_as_ushort(hh);
    l = __half_as_ushort(__float2half_rn(x - hf));
}
__device__ __forceinline__ uint32_t pack2h(uint16_t lo, uint16_t hi) {
    return (uint32_t)lo | ((uint32_t)hi << 16);
}

// ---------------------------------------------------------------------------
// FP16 (3x split) mma.sync m16n8k16 GEMM: C[M,N] = A * B^T (+bias)
//   A_KM=false: A stored [M,K] (k contig), true: [K,M] (m contig)
//   B_KN=false: B stored [N,K] (k contig), true: [K,N] (n contig)
// CTA 128x128, 256 threads, 8 warps (grid 2x4), warp tile 64x32.
// K-stage 32 (2 k16-steps), double-buffered; hi/lo split once at store time.
// 2 CTAs/SM.
// KEY (R9): in K-major source layouts each thread loads 4 k-STRIDED scalars
// of one m/n (still coalesced across lanes), so ALL layouts store with the
// same packed 2x STS.32 per operand-quad -- no u16 scatter stores.
// Fragment-order SMEM, words are f16x2 pairs:
//   A: word idx = ks*1060 + mt*132 + lane*4 + reg   (mt<8, reg<4)
//   B: word idx = ks*1058 + nt*66  + lane*2 + reg   (nt<16, reg<2)
// Regions: Ahi[2 buf] | Alo[2 buf] | Bhi[2 buf] | Blo[2 buf]
// ---------------------------------------------------------------------------
constexpr int ASTG = 2120, BSTG = 2116;
constexpr int AHI0 = 0;
constexpr int ALO0 = 2 * ASTG;
constexpr int BHI0 = 4 * ASTG;
constexpr int BLO0 = 4 * ASTG + 2 * BSTG;
constexpr int SMEM_BYTES = (4 * ASTG + 4 * BSTG) * 4;  // 67,776 B

template <bool A_KM, bool B_KN, bool HAS_BIAS>
__global__ void __launch_bounds__(256, 2)
mma_gemm(const float* __restrict__ A, const float* __restrict__ Bm,
         const float* __restrict__ bias, float* __restrict__ C,
         int M, int Nn, int K, int lda, int ldb,
         size_t aB, size_t bB, size_t cB) {
    extern __shared__ float sm[];
    uint32_t* smu = reinterpret_cast<uint32_t*>(sm);
    const int tid = threadIdx.x;
    const int lane = tid & 31, wid = tid >> 5;
    const int wm = wid & 1, wn = wid >> 1;  // warp grid 2(M) x 4(N)
    const float* Ab = A + (size_t)blockIdx.z * aB;
    const float* Bb = Bm + (size_t)blockIdx.z * bB;
    const int m0 = blockIdx.y * 128;
    const int n0 = blockIdx.x * 128;

    float acc[4][4][4];
#pragma unroll
    for (int i = 0; i < 4; ++i)
#pragma unroll
        for (int j = 0; j < 4; ++j)
#pragma unroll
            for (int e = 0; e < 4; ++e) acc[i][j][e] = 0.f;

    // per stage: 128 (m|n) x 32 k f32 per operand; 256 thr x 4 it x 4 elems
    float4 ra[4], rb[4];
    auto ldg = [&](int kt) {
#pragma unroll
        for (int it = 0; it < 4; ++it) {
            int idx = tid + (it << 8);
            if (A_KM) {
                // 4 k-strided scalars for one m (coalesced across lanes)
                int mm = idx & 127, kg = idx >> 7;
                const float* p =
                    Ab + (size_t)(kt * 32 + (kg << 2)) * lda + m0 + mm;
                ra[it].x = p[0];
                ra[it].y = p[lda];
                ra[it].z = p[2 * lda];
                ra[it].w = p[3 * lda];
            } else {
                int mm = idx >> 3, k4 = idx & 7;
                ra[it] = *reinterpret_cast<const float4*>(
                    Ab + (size_t)(m0 + mm) * lda + kt * 32 + (k4 << 2));
            }
            if (B_KN) {
                int nn = idx & 127, kg = idx >> 7;
                const float* p =
                    Bb + (size_t)(kt * 32 + (kg << 2)) * ldb + n0 + nn;
                rb[it].x = p[0];
                rb[it].y = p[ldb];
                rb[it].z = p[2 * ldb];
                rb[it].w = p[3 * ldb];
            } else {
                int nn = idx >> 3, k4 = idx & 7;
                rb[it] = *reinterpret_cast<const float4*>(
                    Bb + (size_t)(n0 + nn) * ldb + kt * 32 + (k4 << 2));
            }
        }
    };
    auto sts = [&](int buf) {
        uint32_t* Ah = smu + AHI0 + buf * ASTG;
        uint32_t* Al = smu + ALO0 + buf * ASTG;
        uint32_t* Bh = smu + BHI0 + buf * BSTG;
        uint32_t* Bl = smu + BLO0 + buf * BSTG;
#pragma unroll
        for (int it = 0; it < 4; ++it) {
            int idx = tid + (it << 8);
            float va[4] = {ra[it].x, ra[it].y, ra[it].z, ra[it].w};
            float vb[4] = {rb[it].x, rb[it].y, rb[it].z, rb[it].w};
            uint16_t hA[4], lA[4], hB[4], lB[4];
#pragma unroll
            for (int c = 0; c < 4; ++c) {
                split_h(va[c], hA[c], lA[c]);
                split_h(vb[c], hB[c], lB[c]);
            }
            {   // A: thread owns (row mm, k0..k0+3) -> 2 packed words
                int mm, k0;
                if (A_KM) { mm = idx & 127; k0 = (idx >> 7) << 2; }
                else      { mm = idx >> 3;  k0 = (idx & 7) << 2; }
                int ks = k0 >> 4, kk = k0 & 15;
                int rr = mm & 15, mt = mm >> 4;
                int reg = (rr >> 3) + ((kk >> 3) << 1);
                int o = ks * 1060 + mt * 132 +
                        (((rr & 7) << 2) + ((kk & 7) >> 1)) * 4 + reg;
                Ah[o] = pack2h(hA[0], hA[1]);
                Ah[o + 4] = pack2h(hA[2], hA[3]);
                Al[o] = pack2h(lA[0], lA[1]);
                Al[o + 4] = pack2h(lA[2], lA[3]);
            }
            {   // B: thread owns (row nn, k0..k0+3) -> 2 packed words
                int nn, k0;
                if (B_KN) { nn = idx & 127; k0 = (idx >> 7) << 2; }
                else      { nn = idx >> 3;  k0 = (idx & 7) << 2; }
                int ks = k0 >> 4, kk = k0 & 15;
                int nt = nn >> 3;
                int reg = kk >> 3;
                int o = ks * 1058 + nt * 66 +
                        (((nn & 7) << 2) + ((kk & 7) >> 1)) * 2 + reg;
                Bh[o] = pack2h(hB[0], hB[1]);
                Bh[o + 2] = pack2h(hB[2], hB[3]);
                Bl[o] = pack2h(lB[0], lB[1]);
                Bl[o + 2] = pack2h(lB[2], lB[3]);
            }
        }
    };
    auto compute = [&](int buf) {
        const uint32_t* Ah = smu + AHI0 + buf * ASTG;
        const uint32_t* Al = smu + ALO0 + buf * ASTG;
        const uint32_t* Bh = smu + BHI0 + buf * BSTG;
        const uint32_t* Bl = smu + BLO0 + buf * BSTG;
#pragma unroll
        for (int ks = 0; ks < 2; ++ks) {
            uint32_t bh[4][2], bl[4][2];
#pragma unroll
            for (int j = 0; j < 4; ++j) {
                const int o = ks * 1058 + ((wn << 2) + j) * 66 + (lane << 1);
                *reinterpret_cast<uint2*>(bh[j]) =
                    *reinterpret_cast<const uint2*>(Bh + o);
                *reinterpret_cast<uint2*>(bl[j]) =
                    *reinterpret_cast<const uint2*>(Bl + o);
            }
#pragma unroll
            for (int i = 0; i < 4; ++i) {
                uint32_t ah[4], al[4];
                const int o = ks * 1060 + ((wm << 2) + i) * 132 + (lane << 2);
                *reinterpret_cast<uint4*>(ah) =
                    *reinterpret_cast<const uint4*>(Ah + o);
                *reinterpret_cast<uint4*>(al) =
                    *reinterpret_cast<const uint4*>(Al + o);
#pragma unroll
                for (int j = 0; j < 4; ++j) {
                    mma16(acc[i][j], ah, bh[j]);
                    mma16(acc[i][j], ah, bl[j]);
                    mma16(acc[i][j], al, bh[j]);
                }
            }
        }
    };

    ldg(0);
    sts(0);
    __syncthreads();
    const int nt = K >> 5;
    for (int t = 0; t < nt; ++t) {
        if (t + 1 < nt) ldg(t + 1);
        compute(t & 1);
        if (t + 1 < nt) sts((t + 1) & 1);  // other buffer: no conflict
        __syncthreads();
    }

    const int r = lane >> 2, cq = (lane & 3) << 1;
    float* Cb = C + (size_t)blockIdx.z * cB;
#pragma unroll
    for (int i = 0; i < 4; ++i) {
#pragma unroll
        for (int j = 0; j < 4; ++j) {
            const int row = m0 + (wm << 6) + (i << 4) + r;
            const int col = n0 + (wn << 5) + (j << 3) + cq;
            float o0 = acc[i][j][0], o1 = acc[i][j][1];
            float o2 = acc[i][j][2], o3 = acc[i][j][3];
            if (HAS_BIAS) {
                float b0 = bias[col], b1 = bias[col + 1];
                o0 += b0; o1 += b1; o2 += b0; o3 += b1;
            }
            *reinterpret_cast<float2*>(Cb + (size_t)row * Nn + col) =
                make_float2(o0, o1);
            *reinterpret_cast<float2*>(Cb + (size_t)(row + 8) * Nn + col) =
                make_float2(o2, o3);
        }
    }
}

// ---------------------------------------------------------------------------
// s[b][e] = sum_n x[b][n][e]
// ---------------------------------------------------------------------------
__global__ void __launch_bounds__(256)
colsum_kernel(const float* __restrict__ x, float* __restrict__ s) {
    const int e = blockIdx.x * 256 + threadIdx.x;
    const int b = blockIdx.y;
    const float* p = x + (size_t)b * N_ * D_ + e;
    float a0 = 0.f, a1 = 0.f, a2 = 0.f, a3 = 0.f;
    for (int n = 0; n < N_; n += 4) {
        a0 += p[(size_t)n * D_];
        a1 += p[(size_t)(n + 1) * D_];
        a2 += p[(size_t)(n + 2) * D_];
        a3 += p[(size_t)(n + 3) * D_];
    }
    s[b * D_ + e] = (a0 + a1) + (a2 + a3);
}

// u[b][e] = Wq[e].s[b] ;  w'[b][f] = Wk[f].s[b] + N*bk[f]
__global__ void __launch_bounds__(256)
gemv_kernel(const float* __restrict__ Wq, const float* __restrict__ Wk,
            const float* __restrict__ bk, const float* __restrict__ s,
            float* __restrict__ u, float* __restrict__ w) {
    const int wg = blockIdx.x * 8 + (threadIdx.x >> 5);
    const int lane = threadIdx.x & 31;
    const int b = wg >> 11;           // 2048 outputs per batch
    const int o = wg & 2047;
    const bool is_u = o < 1024;
    const int row = is_u ? o : o - 1024;
    const float* W = (is_u ? Wq : Wk) + (size_t)row * D_;
    const float* sb = s + b * D_;
    float acc = 0.f;
#pragma unroll
    for (int i = 0; i < 32; ++i) acc += W[lane + (i << 5)] * sb[lane + (i << 5)];
#pragma unroll
    for (int off = 16; off; off >>= 1)
        acc += __shfl_xor_sync(0xffffffffu, acc, off);
    if (lane == 0) {
        if (is_u) u[b * D_ + row] = acc;
        else      w[b * D_ + row] = acc + (float)N_ * bk[row];
    }
}

// ---------------------------------------------------------------------------
// softmax with fused rank-1 corrections:
// logit[b][e][f] = L + u[b][e]*bk[f] + bq[e]*w'[b][f]; softmax over f, inplace
// ---------------------------------------------------------------------------
__global__ void __launch_bounds__(256)
softmax_fused(float* __restrict__ L, const float* __restrict__ u,
              const float* __restrict__ w, const float* __restrict__ bq,
              const float* __restrict__ bk) {
    const int row = blockIdx.x;
    const int b = row >> 10, e = row & 1023;
    float* p = L + (size_t)row * 1024;
    const float uu = u[b * D_ + e];
    const float bb = bq[e];
    const float* wb = w + b * D_;
    const int t = threadIdx.x;
    const int lane = t & 31, wid = t >> 5;
    __shared__ float red[8];

    float v[4];
#pragma unroll
    for (int i = 0; i < 4; ++i) {
        const int f = t + (i << 8);
        v[i] = p[f] + uu * bk[f] + bb * wb[f];
    }

    float m = fmaxf(fmaxf(v[0], v[1]), fmaxf(v[2], v[3]));
#pragma unroll
    for (int o = 16; o; o >>= 1) m = fmaxf(m, __shfl_xor_sync(0xffffffffu, m, o));
    if (lane == 0) red[wid] = m;
    __syncthreads();
    if (t < 32) {
        float x = (t < 8) ? red[t] : -3.4e38f;
#pragma unroll
        for (int o = 4; o; o >>= 1) x = fmaxf(x, __shfl_xor_sync(0xffffffffu, x, o));
        if (t == 0) red[0] = x;
    }
    __syncthreads();
    m = red[0];
    __syncthreads();

    float ssum = 0.f;
#pragma unroll
    for (int i = 0; i < 4; ++i) {
        v[i] = expf(v[i] - m);
        ssum += v[i];
    }
#pragma unroll
    for (int o = 16; o; o >>= 1) ssum += __shfl_xor_sync(0xffffffffu, ssum, o);
    if (lane == 0) red[wid] = ssum;
    __syncthreads();
    if (t < 32) {
        float x = (t < 8) ? red[t] : 0.f;
#pragma unroll
        for (int o = 4; o; o >>= 1) x += __shfl_xor_sync(0xffffffffu, x, o);
        if (t == 0) red[0] = x;
    }
    __syncthreads();
    const float inv = 1.0f / red[0];
#pragma unroll
    for (int i = 0; i < 4; ++i) p[t + (i << 8)] = v[i] * inv;
}

extern "C" void kernel_launch(void* const* d_in, const int* in_sizes, int n_in,
                              void* d_out, int out_size) {
    const float* x  = (const float*)d_in[0];
    const float* Wq = (const float*)d_in[1];
    const float* bq = (const float*)d_in[2];
    const float* Wk = (const float*)d_in[3];
    const float* bk = (const float*)d_in[4];
    const float* Wv = (const float*)d_in[5];
    const float* bv = (const float*)d_in[6];
    float* out = (float*)d_out;

    float *v, *G, *T1, *L, *s, *u, *w;
    cudaGetSymbolAddress((void**)&v, g_v);
    cudaGetSymbolAddress((void**)&G, g_G);
    cudaGetSymbolAddress((void**)&T1, g_T1);
    cudaGetSymbolAddress((void**)&L, g_L);
    cudaGetSymbolAddress((void**)&s, g_s);
    cudaGetSymbolAddress((void**)&u, g_u);
    cudaGetSymbolAddress((void**)&w, g_w);

    cudaFuncSetAttribute(mma_gemm<false, false, true>,
                         cudaFuncAttributeMaxDynamicSharedMemorySize, SMEM_BYTES);
    cudaFuncSetAttribute(mma_gemm<true, true, false>,
                         cudaFuncAttributeMaxDynamicSharedMemorySize, SMEM_BYTES);
    cudaFuncSetAttribute(mma_gemm<false, false, false>,
                         cudaFuncAttributeMaxDynamicSharedMemorySize, SMEM_BYTES);
    cudaFuncSetAttribute(mma_gemm<false, true, false>,
                         cudaFuncAttributeMaxDynamicSharedMemorySize, SMEM_BYTES);

    const dim3 blk(256);

    // v = x @ Wv^T + bv      [32768,1024] x [1024,1024]
    mma_gemm<false, false, true><<<dim3(8, 256, 1), blk, SMEM_BYTES>>>(
        x, Wv, bv, v, B_ * N_, D_, D_, D_, D_, 0, 0, 0);

    // s = x^T 1 ; u = Wq s ; w' = Wk s + N bk
    colsum_kernel<<<dim3(4, 8), 256>>>(x, s);
    gemv_kernel<<<2048, 256>>>(Wq, Wk, bk, s, u, w);

    // G[b] = x[b]^T x[b]     M=N=1024, K=4096
    mma_gemm<true, true, false><<<dim3(8, 8, B_), blk, SMEM_BYTES>>>(
        x, x, nullptr, G, D_, D_, N_, D_, D_,
        (size_t)N_ * D_, (size_t)N_ * D_, (size_t)D_ * D_);

    // T1[b] = G[b] @ Wk^T    M=N=K=1024
    mma_gemm<false, false, false><<<dim3(8, 8, B_), blk, SMEM_BYTES>>>(
        G, Wk, nullptr, T1, D_, D_, D_, D_, D_,
        (size_t)D_ * D_, 0, (size_t)D_ * D_);

    // L[b] = Wq @ T1[b]      M=N=K=1024
    mma_gemm<false, true, false><<<dim3(8, 8, B_), blk, SMEM_BYTES>>>(
        Wq, T1, nullptr, L, D_, D_, D_, D_, D_,
        0, (size_t)D_ * D_, (size_t)D_ * D_);

    // softmax with rank-1 corrections, in place -> attn
    softmax_fused<<<B_ * D_, 256>>>(L, u, w, bq, bk);

    // out[b] = v[b] @ attn[b]   M=4096, N=1024, K=1024
    mma_gemm<false, true, false><<<dim3(8, 32, B_), blk, SMEM_BYTES>>>(
        v, L, nullptr, out, N_, D_, D_, D_, D_,
        (size_t)N_ * D_, (size_t)D_ * D_, (size_t)N_ * D_);
}

// round 10
// speedup vs baseline: 1.6977x; 1.6977x over previous
#include <cuda_runtime.h>
#include <cuda_fp16.h>
#include <cstdint>

#define B_   8
#define N_   4096
#define D_   1024

// scratch (device globals; no allocations allowed)
__device__ float g_xT[(size_t)B_ * D_ * N_];   // x^T per batch     128 MB
__device__ float g_v [(size_t)B_ * N_ * D_];   // v projection      128 MB
__device__ float g_G [(size_t)B_ * D_ * D_];   // G = x^T x          32 MB
__device__ float g_T1[(size_t)B_ * D_ * D_];   // T1t = Wk G         32 MB
__device__ float g_L [(size_t)B_ * D_ * D_];   // logits -> attn     32 MB
__device__ float g_aT[(size_t)B_ * D_ * D_];   // attn^T             32 MB
__device__ float g_s [(size_t)B_ * D_];        // s = x^T 1
__device__ float g_u [(size_t)B_ * D_];        // u = Wq s
__device__ float g_w [(size_t)B_ * D_];        // w' = Wk s + N*bk

__device__ __forceinline__ void mma16(float* c, const uint32_t* a,
                                      const uint32_t* b) {
    asm("mma.sync.aligned.m16n8k16.row.col.f32.f16.f16.f32 "
        "{%0,%1,%2,%3}, {%4,%5,%6,%7}, {%8,%9}, {%0,%1,%2,%3};"
        : "+f"(c[0]), "+f"(c[1]), "+f"(c[2]), "+f"(c[3])
        : "r"(a[0]), "r"(a[1]), "r"(a[2]), "r"(a[3]), "r"(b[0]), "r"(b[1]));
}

// split x = hi + lo, both fp16 (11-bit mantissa each -> ~22-bit coverage)
__device__ __forceinline__ void split_h(float x, uint16_t& h, uint16_t& l) {
    __half hh = __float2half_rn(x);
    float hf = __half2float(hh);
    h = __half_as_ushort(hh);
    l = __half_as_ushort(__float2half_rn(x - hf));
}
__device__ __forceinline__ uint32_t pack2h(uint16_t lo, uint16_t hi) {
    return (uint32_t)lo | ((uint32_t)hi << 16);
}

// ---------------------------------------------------------------------------
// FP16 (3x split) mma.sync m16n8k16 GEMM: C[M,N] = A * B^T (+bias)
// NATURAL layouts only: A [M,K] k-contig, B [N,K] k-contig (the proven fast
// path: LDG.128 loads + packed STS.32 stores, no u16 scatter).
// CTA 128x128, 256 threads, 8 warps (grid 2x4), warp tile 64x32.
// K-stage 32 (2 k16-steps), double-buffered; hi/lo split once at store time.
// 2 CTAs/SM.
// SYM: C is symmetric (A==B) -> CTAs with by<bx exit; epilogue mirror-writes.
// Fragment-order SMEM, words are f16x2 pairs:
//   A: word idx = ks*1060 + mt*132 + lane*4 + reg   (mt<8, reg<4)
//   B: word idx = ks*1058 + nt*66  + lane*2 + reg   (nt<16, reg<2)
// Regions: Ahi[2 buf] | Alo[2 buf] | Bhi[2 buf] | Blo[2 buf]
// ---------------------------------------------------------------------------
constexpr int ASTG = 2120, BSTG = 2116;
constexpr int AHI0 = 0;
constexpr int ALO0 = 2 * ASTG;
constexpr int BHI0 = 4 * ASTG;
constexpr int BLO0 = 4 * ASTG + 2 * BSTG;
constexpr int SMEM_BYTES = (4 * ASTG + 4 * BSTG) * 4;  // 67,776 B

template <bool HAS_BIAS, bool SYM>
__global__ void __launch_bounds__(256, 2)
mma_gemm(const float* __restrict__ A, const float* __restrict__ Bm,
         const float* __restrict__ bias, float* __restrict__ C,
         int M, int Nn, int K, int lda, int ldb,
         size_t aB, size_t bB, size_t cB) {
    if (SYM && blockIdx.y < blockIdx.x) return;  // lower triangle only
    extern __shared__ float sm[];
    uint32_t* smu = reinterpret_cast<uint32_t*>(sm);
    const int tid = threadIdx.x;
    const int lane = tid & 31, wid = tid >> 5;
    const int wm = wid & 1, wn = wid >> 1;  // warp grid 2(M) x 4(N)
    const float* Ab = A + (size_t)blockIdx.z * aB;
    const float* Bb = Bm + (size_t)blockIdx.z * bB;
    const int m0 = blockIdx.y * 128;
    const int n0 = blockIdx.x * 128;

    float acc[4][4][4];
#pragma unroll
    for (int i = 0; i < 4; ++i)
#pragma unroll
        for (int j = 0; j < 4; ++j)
#pragma unroll
            for (int e = 0; e < 4; ++e) acc[i][j][e] = 0.f;

    // per stage: A tile 128x32 f32 = 1024 float4; 256 threads -> 4 each
    float4 ra[4], rb[4];
    auto ldg = [&](int kt) {
#pragma unroll
        for (int it = 0; it < 4; ++it) {
            int idx = tid + (it << 8);
            int mm = idx >> 3, k4 = idx & 7;
            ra[it] = *reinterpret_cast<const float4*>(
                Ab + (size_t)(m0 + mm) * lda + kt * 32 + (k4 << 2));
            rb[it] = *reinterpret_cast<const float4*>(
                Bb + (size_t)(n0 + mm) * ldb + kt * 32 + (k4 << 2));
        }
    };
    auto sts = [&](int buf) {
        uint32_t* Ah = smu + AHI0 + buf * ASTG;
        uint32_t* Al = smu + ALO0 + buf * ASTG;
        uint32_t* Bh = smu + BHI0 + buf * BSTG;
        uint32_t* Bl = smu + BLO0 + buf * BSTG;
#pragma unroll
        for (int it = 0; it < 4; ++it) {
            int idx = tid + (it << 8);
            int mm = idx >> 3, k4 = idx & 7;
            float va[4] = {ra[it].x, ra[it].y, ra[it].z, ra[it].w};
            float vb[4] = {rb[it].x, rb[it].y, rb[it].z, rb[it].w};
            uint16_t hA[4], lA[4], hB[4], lB[4];
#pragma unroll
            for (int c = 0; c < 4; ++c) {
                split_h(va[c], hA[c], lA[c]);
                split_h(vb[c], hB[c], lB[c]);
            }
            {   // A: (row mm, k0..k0+3) -> 2 packed words
                int k0 = k4 << 2;
                int ks = k0 >> 4, kk = k0 & 15;
                int rr = mm & 15, mt = mm >> 4;
                int reg = (rr >> 3) + ((kk >> 3) << 1);
                int o = ks * 1060 + mt * 132 +
                        (((rr & 7) << 2) + ((kk & 7) >> 1)) * 4 + reg;
                Ah[o] = pack2h(hA[0], hA[1]);
                Ah[o + 4] = pack2h(hA[2], hA[3]);
                Al[o] = pack2h(lA[0], lA[1]);
                Al[o + 4] = pack2h(lA[2], lA[3]);
            }
            {   // B: (row nn, k0..k0+3) -> 2 packed words
                int k0 = k4 << 2;
                int ks = k0 >> 4, kk = k0 & 15;
                int nt = mm >> 3;
                int reg = kk >> 3;
                int o = ks * 1058 + nt * 66 +
                        (((mm & 7) << 2) + ((kk & 7) >> 1)) * 2 + reg;
                Bh[o] = pack2h(hB[0], hB[1]);
                Bh[o + 2] = pack2h(hB[2], hB[3]);
                Bl[o] = pack2h(lB[0], lB[1]);
                Bl[o + 2] = pack2h(lB[2], lB[3]);
            }
        }
    };
    auto compute = [&](int buf) {
        const uint32_t* Ah = smu + AHI0 + buf * ASTG;
        const uint32_t* Al = smu + ALO0 + buf * ASTG;
        const uint32_t* Bh = smu + BHI0 + buf * BSTG;
        const uint32_t* Bl = smu + BLO0 + buf * BSTG;
#pragma unroll
        for (int ks = 0; ks < 2; ++ks) {
            uint32_t bh[4][2], bl[4][2];
#pragma unroll
            for (int j = 0; j < 4; ++j) {
                const int o = ks * 1058 + ((wn << 2) + j) * 66 + (lane << 1);
                *reinterpret_cast<uint2*>(bh[j]) =
                    *reinterpret_cast<const uint2*>(Bh + o);
                *reinterpret_cast<uint2*>(bl[j]) =
                    *reinterpret_cast<const uint2*>(Bl + o);
            }
#pragma unroll
            for (int i = 0; i < 4; ++i) {
                uint32_t ah[4], al[4];
                const int o = ks * 1060 + ((wm << 2) + i) * 132 + (lane << 2);
                *reinterpret_cast<uint4*>(ah) =
                    *reinterpret_cast<const uint4*>(Ah + o);
                *reinterpret_cast<uint4*>(al) =
                    *reinterpret_cast<const uint4*>(Al + o);
#pragma unroll
                for (int j = 0; j < 4; ++j) {
                    mma16(acc[i][j], ah, bh[j]);
                    mma16(acc[i][j], ah, bl[j]);
                    mma16(acc[i][j], al, bh[j]);
                }
            }
        }
    };

    ldg(0);
    sts(0);
    __syncthreads();
    const int nt = K >> 5;
    for (int t = 0; t < nt; ++t) {
        if (t + 1 < nt) ldg(t + 1);
        compute(t & 1);
        if (t + 1 < nt) sts((t + 1) & 1);  // other buffer: no conflict
        __syncthreads();
    }

    const int r = lane >> 2, cq = (lane & 3) << 1;
    float* Cb = C + (size_t)blockIdx.z * cB;
    const bool mirror = SYM && (blockIdx.y != blockIdx.x);
#pragma unroll
    for (int i = 0; i < 4; ++i) {
#pragma unroll
        for (int j = 0; j < 4; ++j) {
            const int row = m0 + (wm << 6) + (i << 4) + r;
            const int col = n0 + (wn << 5) + (j << 3) + cq;
            float o0 = acc[i][j][0], o1 = acc[i][j][1];
            float o2 = acc[i][j][2], o3 = acc[i][j][3];
            if (HAS_BIAS) {
                float b0 = bias[col], b1 = bias[col + 1];
                o0 += b0; o1 += b1; o2 += b0; o3 += b1;
            }
            *reinterpret_cast<float2*>(Cb + (size_t)row * Nn + col) =
                make_float2(o0, o1);
            *reinterpret_cast<float2*>(Cb + (size_t)(row + 8) * Nn + col) =
                make_float2(o2, o3);
            if (mirror) {  // C[col][row] = C[row][col] (G symmetric)
                Cb[(size_t)col * Nn + row] = o0;
                Cb[(size_t)(col + 1) * Nn + row] = o1;
                Cb[(size_t)col * Nn + row + 8] = o2;
                Cb[(size_t)(col + 1) * Nn + row + 8] = o3;
            }
        }
    }
}

// ---------------------------------------------------------------------------
// tiled transpose: out[b][j][i] = in[b][i][j], per-batch RxCc -> CcxR
// ---------------------------------------------------------------------------
__global__ void __launch_bounds__(256)
transpose_kernel(const float* __restrict__ in, float* __restrict__ out,
                 int R, int Cc) {
    __shared__ float t[32][33];
    const float* ib = in + (size_t)blockIdx.z * R * Cc;
    float* ob = out + (size_t)blockIdx.z * R * Cc;
    const int c = blockIdx.x * 32 + threadIdx.x;   // col in input
    const int r0 = blockIdx.y * 32;
#pragma unroll
    for (int j = threadIdx.y; j < 32; j += 8)
        t[j][threadIdx.x] = ib[(size_t)(r0 + j) * Cc + c];
    __syncthreads();
    const int ro = blockIdx.x * 32;                 // row in output
    const int co = r0 + threadIdx.x;                // col in output
#pragma unroll
    for (int j = threadIdx.y; j < 32; j += 8)
        ob[(size_t)(ro + j) * R + co] = t[threadIdx.x][j];
}

// ---------------------------------------------------------------------------
// s[b][e] = sum_n x[b][n][e]
// ---------------------------------------------------------------------------
__global__ void __launch_bounds__(256)
colsum_kernel(const float* __restrict__ x, float* __restrict__ s) {
    const int e = blockIdx.x * 256 + threadIdx.x;
    const int b = blockIdx.y;
    const float* p = x + (size_t)b * N_ * D_ + e;
    float a0 = 0.f, a1 = 0.f, a2 = 0.f, a3 = 0.f;
    for (int n = 0; n < N_; n += 4) {
        a0 += p[(size_t)n * D_];
        a1 += p[(size_t)(n + 1) * D_];
        a2 += p[(size_t)(n + 2) * D_];
        a3 += p[(size_t)(n + 3) * D_];
    }
    s[b * D_ + e] = (a0 + a1) + (a2 + a3);
}

// u[b][e] = Wq[e].s[b] ;  w'[b][f] = Wk[f].s[b] + N*bk[f]
__global__ void __launch_bounds__(256)
gemv_kernel(const float* __restrict__ Wq, const float* __restrict__ Wk,
            const float* __restrict__ bk, const float* __restrict__ s,
            float* __restrict__ u, float* __restrict__ w) {
    const int wg = blockIdx.x * 8 + (threadIdx.x >> 5);
    const int lane = threadIdx.x & 31;
    const int b = wg >> 11;           // 2048 outputs per batch
    const int o = wg & 2047;
    const bool is_u = o < 1024;
    const int row = is_u ? o : o - 1024;
    const float* W = (is_u ? Wq : Wk) + (size_t)row * D_;
    const float* sb = s + b * D_;
    float acc = 0.f;
#pragma unroll
    for (int i = 0; i < 32; ++i) acc += W[lane + (i << 5)] * sb[lane + (i << 5)];
#pragma unroll
    for (int off = 16; off; off >>= 1)
        acc += __shfl_xor_sync(0xffffffffu, acc, off);
    if (lane == 0) {
        if (is_u) u[b * D_ + row] = acc;
        else      w[b * D_ + row] = acc + (float)N_ * bk[row];
    }
}

// ---------------------------------------------------------------------------
// softmax with fused rank-1 corrections:
// logit[b][e][f] = L + u[b][e]*bk[f] + bq[e]*w'[b][f]; softmax over f, inplace
// ---------------------------------------------------------------------------
__global__ void __launch_bounds__(256)
softmax_fused(float* __restrict__ L, const float* __restrict__ u,
              const float* __restrict__ w, const float* __restrict__ bq,
              const float* __restrict__ bk) {
    const int row = blockIdx.x;
    const int b = row >> 10, e = row & 1023;
    float* p = L + (size_t)row * 1024;
    const float uu = u[b * D_ + e];
    const float bb = bq[e];
    const float* wb = w + b * D_;
    const int t = threadIdx.x;
    const int lane = t & 31, wid = t >> 5;
    __shared__ float red[8];

    float v[4];
#pragma unroll
    for (int i = 0; i < 4; ++i) {
        const int f = t + (i << 8);
        v[i] = p[f] + uu * bk[f] + bb * wb[f];
    }

    float m = fmaxf(fmaxf(v[0], v[1]), fmaxf(v[2], v[3]));
#pragma unroll
    for (int o = 16; o; o >>= 1) m = fmaxf(m, __shfl_xor_sync(0xffffffffu, m, o));
    if (lane == 0) red[wid] = m;
    __syncthreads();
    if (t < 32) {
        float x = (t < 8) ? red[t] : -3.4e38f;
#pragma unroll
        for (int o = 4; o; o >>= 1) x = fmaxf(x, __shfl_xor_sync(0xffffffffu, x, o));
        if (t == 0) red[0] = x;
    }
    __syncthreads();
    m = red[0];
    __syncthreads();

    float ssum = 0.f;
#pragma unroll
    for (int i = 0; i < 4; ++i) {
        v[i] = expf(v[i] - m);
        ssum += v[i];
    }
#pragma unroll
    for (int o = 16; o; o >>= 1) ssum += __shfl_xor_sync(0xffffffffu, ssum, o);
    if (lane == 0) red[wid] = ssum;
    __syncthreads();
    if (t < 32) {
        float x = (t < 8) ? red[t] : 0.f;
#pragma unroll
        for (int o = 4; o; o >>= 1) x += __shfl_xor_sync(0xffffffffu, x, o);
        if (t == 0) red[0] = x;
    }
    __syncthreads();
    const float inv = 1.0f / red[0];
#pragma unroll
    for (int i = 0; i < 4; ++i) p[t + (i << 8)] = v[i] * inv;
}

extern "C" void kernel_launch(void* const* d_in, const int* in_sizes, int n_in,
                              void* d_out, int out_size) {
    const float* x  = (const float*)d_in[0];
    const float* Wq = (const float*)d_in[1];
    const float* bq = (const float*)d_in[2];
    const float* Wk = (const float*)d_in[3];
    const float* bk = (const float*)d_in[4];
    const float* Wv = (const float*)d_in[5];
    const float* bv = (const float*)d_in[6];
    float* out = (float*)d_out;

    float *xT, *v, *G, *T1, *L, *aT, *s, *u, *w;
    cudaGetSymbolAddress((void**)&xT, g_xT);
    cudaGetSymbolAddress((void**)&v, g_v);
    cudaGetSymbolAddress((void**)&G, g_G);
    cudaGetSymbolAddress((void**)&T1, g_T1);
    cudaGetSymbolAddress((void**)&L, g_L);
    cudaGetSymbolAddress((void**)&aT, g_aT);
    cudaGetSymbolAddress((void**)&s, g_s);
    cudaGetSymbolAddress((void**)&u, g_u);
    cudaGetSymbolAddress((void**)&w, g_w);

    cudaFuncSetAttribute(mma_gemm<true, false>,
                         cudaFuncAttributeMaxDynamicSharedMemorySize, SMEM_BYTES);
    cudaFuncSetAttribute(mma_gemm<false, false>,
                         cudaFuncAttributeMaxDynamicSharedMemorySize, SMEM_BYTES);
    cudaFuncSetAttribute(mma_gemm<false, true>,
                         cudaFuncAttributeMaxDynamicSharedMemorySize, SMEM_BYTES);

    const dim3 blk(256);

    // xT[b][e][n] = x[b][n][e]
    transpose_kernel<<<dim3(32, 128, B_), dim3(32, 8)>>>(x, xT, N_, D_);

    // v = x @ Wv^T + bv      [32768,1024] x [1024,1024]
    mma_gemm<true, false><<<dim3(8, 256, 1), blk, SMEM_BYTES>>>(
        x, Wv, bv, v, B_ * N_, D_, D_, D_, D_, 0, 0, 0);

    // s = x^T 1 ; u = Wq s ; w' = Wk s + N bk
    colsum_kernel<<<dim3(4, 8), 256>>>(x, s);
    gemv_kernel<<<2048, 256>>>(Wq, Wk, bk, s, u, w);

    // G[b] = xT[b] @ xT[b]^T  (M=N=1024, K=4096), symmetric -> triangle+mirror
    mma_gemm<false, true><<<dim3(8, 8, B_), blk, SMEM_BYTES>>>(
        xT, xT, nullptr, G, D_, D_, N_, N_, N_,
        (size_t)D_ * N_, (size_t)D_ * N_, (size_t)D_ * D_);

    // T1t[b][f][g] = sum_h Wk[f][h] G[b][g][h]  (G symmetric: = (Wk G)[f][g])
    mma_gemm<false, false><<<dim3(8, 8, B_), blk, SMEM_BYTES>>>(
        Wk, G, nullptr, T1, D_, D_, D_, D_, D_,
        0, (size_t)D_ * D_, (size_t)D_ * D_);

    // L[b][e][f] = sum_g Wq[e][g] T1t[b][f][g]
    mma_gemm<false, false><<<dim3(8, 8, B_), blk, SMEM_BYTES>>>(
        Wq, T1, nullptr, L, D_, D_, D_, D_, D_,
        0, (size_t)D_ * D_, (size_t)D_ * D_);

    // softmax with rank-1 corrections, in place -> attn
    softmax_fused<<<B_ * D_, 256>>>(L, u, w, bq, bk);

    // aT[b][f][e] = attn[b][e][f]
    transpose_kernel<<<dim3(32, 32, B_), dim3(32, 8)>>>(L, aT, D_, D_);

    // out[b][n][f] = sum_e v[b][n][e] aT[b][f][e]   (natural/natural)
    mma_gemm<false, false><<<dim3(8, 32, B_), blk, SMEM_BYTES>>>(
        v, aT, nullptr, out, N_, D_, D_, D_, D_,
        (size_t)N_ * D_, (size_t)D_ * D_, (size_t)N_ * D_);
}

// round 11
// speedup vs baseline: 2.0686x; 1.2185x over previous
#include <cuda_runtime.h>
#include <cuda_fp16.h>
#include <cstdint>

#define B_   8
#define N_   4096
#define D_   1024

// scratch (device globals; no allocations allowed)
__device__ float g_xT [(size_t)B_ * D_ * N_];   // x^T per batch    128 MB
__device__ float g_G  [(size_t)B_ * D_ * D_];   // G = x^T x         32 MB
__device__ float g_T1 [(size_t)B_ * D_ * D_];   // T1t = Wk G        32 MB
__device__ float g_L  [(size_t)B_ * D_ * D_];   // logits -> attn    32 MB
__device__ float g_aT [(size_t)B_ * D_ * D_];   // attn^T            32 MB
__device__ float g_W2 [(size_t)B_ * D_ * D_];   // W2t = attn^T Wv^T 32 MB
__device__ float g_WvT[(size_t)D_ * D_];        // Wv^T               4 MB
__device__ float g_s  [(size_t)B_ * D_];        // s = x^T 1
__device__ float g_u  [(size_t)B_ * D_];        // u = Wq s
__device__ float g_w  [(size_t)B_ * D_];        // w' = Wk s + N*bk
__device__ float g_r  [(size_t)B_ * D_];        // r = bv^T attn

__device__ __forceinline__ void mma16(float* c, const uint32_t* a,
                                      const uint32_t* b) {
    asm("mma.sync.aligned.m16n8k16.row.col.f32.f16.f16.f32 "
        "{%0,%1,%2,%3}, {%4,%5,%6,%7}, {%8,%9}, {%0,%1,%2,%3};"
        : "+f"(c[0]), "+f"(c[1]), "+f"(c[2]), "+f"(c[3])
        : "r"(a[0]), "r"(a[1]), "r"(a[2]), "r"(a[3]), "r"(b[0]), "r"(b[1]));
}

// split x = hi + lo, both fp16 (11-bit mantissa each -> ~22-bit coverage)
__device__ __forceinline__ void split_h(float x, uint16_t& h, uint16_t& l) {
    __half hh = __float2half_rn(x);
    float hf = __half2float(hh);
    h = __half_as_ushort(hh);
    l = __half_as_ushort(__float2half_rn(x - hf));
}
__device__ __forceinline__ uint32_t pack2h(uint16_t lo, uint16_t hi) {
    return (uint32_t)lo | ((uint32_t)hi << 16);
}

// ---------------------------------------------------------------------------
// FP16 (3x split) mma.sync m16n8k16 GEMM: C[M,N] = A * B^T (+bias per batch)
// NATURAL layouts only: A [M,K] k-contig, B [N,K] k-contig.
// CTA 128x128, 256 threads, 8 warps (grid 2x4), warp tile 64x32.
// K-stage 32 (2 k16-steps), double-buffered; hi/lo split once at store time.
// 2 CTAs/SM.  SYM: C symmetric (A==B) -> lower triangle + mirror write.
// Fragment-order SMEM, words are f16x2 pairs:
//   A: word idx = ks*1060 + mt*132 + lane*4 + reg   (mt<8, reg<4)
//   B: word idx = ks*1058 + nt*66  + lane*2 + reg   (nt<16, reg<2)
// ---------------------------------------------------------------------------
constexpr int ASTG = 2120, BSTG = 2116;
constexpr int AHI0 = 0;
constexpr int ALO0 = 2 * ASTG;
constexpr int BHI0 = 4 * ASTG;
constexpr int BLO0 = 4 * ASTG + 2 * BSTG;
constexpr int SMEM_BYTES = (4 * ASTG + 4 * BSTG) * 4;  // 67,776 B

template <bool HAS_BIAS, bool SYM>
__global__ void __launch_bounds__(256, 2)
mma_gemm(const float* __restrict__ A, const float* __restrict__ Bm,
         const float* __restrict__ bias, float* __restrict__ C,
         int M, int Nn, int K, int lda, int ldb,
         size_t aB, size_t bB, size_t cB, size_t biasB) {
    if (SYM && blockIdx.y < blockIdx.x) return;  // lower triangle only
    extern __shared__ float sm[];
    uint32_t* smu = reinterpret_cast<uint32_t*>(sm);
    const int tid = threadIdx.x;
    const int lane = tid & 31, wid = tid >> 5;
    const int wm = wid & 1, wn = wid >> 1;  // warp grid 2(M) x 4(N)
    const float* Ab = A + (size_t)blockIdx.z * aB;
    const float* Bb = Bm + (size_t)blockIdx.z * bB;
    const float* biasb = HAS_BIAS ? bias + (size_t)blockIdx.z * biasB : nullptr;
    const int m0 = blockIdx.y * 128;
    const int n0 = blockIdx.x * 128;

    float acc[4][4][4];
#pragma unroll
    for (int i = 0; i < 4; ++i)
#pragma unroll
        for (int j = 0; j < 4; ++j)
#pragma unroll
            for (int e = 0; e < 4; ++e) acc[i][j][e] = 0.f;

    float4 ra[4], rb[4];
    auto ldg = [&](int kt) {
#pragma unroll
        for (int it = 0; it < 4; ++it) {
            int idx = tid + (it << 8);
            int mm = idx >> 3, k4 = idx & 7;
            ra[it] = *reinterpret_cast<const float4*>(
                Ab + (size_t)(m0 + mm) * lda + kt * 32 + (k4 << 2));
            rb[it] = *reinterpret_cast<const float4*>(
                Bb + (size_t)(n0 + mm) * ldb + kt * 32 + (k4 << 2));
        }
    };
    auto sts = [&](int buf) {
        uint32_t* Ah = smu + AHI0 + buf * ASTG;
        uint32_t* Al = smu + ALO0 + buf * ASTG;
        uint32_t* Bh = smu + BHI0 + buf * BSTG;
        uint32_t* Bl = smu + BLO0 + buf * BSTG;
#pragma unroll
        for (int it = 0; it < 4; ++it) {
            int idx = tid + (it << 8);
            int mm = idx >> 3, k4 = idx & 7;
            float va[4] = {ra[it].x, ra[it].y, ra[it].z, ra[it].w};
            float vb[4] = {rb[it].x, rb[it].y, rb[it].z, rb[it].w};
            uint16_t hA[4], lA[4], hB[4], lB[4];
#pragma unroll
            for (int c = 0; c < 4; ++c) {
                split_h(va[c], hA[c], lA[c]);
                split_h(vb[c], hB[c], lB[c]);
            }
            {   // A: (row mm, k0..k0+3) -> 2 packed words
                int k0 = k4 << 2;
                int ks = k0 >> 4, kk = k0 & 15;
                int rr = mm & 15, mt = mm >> 4;
                int reg = (rr >> 3) + ((kk >> 3) << 1);
                int o = ks * 1060 + mt * 132 +
                        (((rr & 7) << 2) + ((kk & 7) >> 1)) * 4 + reg;
                Ah[o] = pack2h(hA[0], hA[1]);
                Ah[o + 4] = pack2h(hA[2], hA[3]);
                Al[o] = pack2h(lA[0], lA[1]);
                Al[o + 4] = pack2h(lA[2], lA[3]);
            }
            {   // B: (row nn, k0..k0+3) -> 2 packed words
                int k0 = k4 << 2;
                int ks = k0 >> 4, kk = k0 & 15;
                int nt = mm >> 3;
                int reg = kk >> 3;
                int o = ks * 1058 + nt * 66 +
                        (((mm & 7) << 2) + ((kk & 7) >> 1)) * 2 + reg;
                Bh[o] = pack2h(hB[0], hB[1]);
                Bh[o + 2] = pack2h(hB[2], hB[3]);
                Bl[o] = pack2h(lB[0], lB[1]);
                Bl[o + 2] = pack2h(lB[2], lB[3]);
            }
        }
    };
    auto compute = [&](int buf) {
        const uint32_t* Ah = smu + AHI0 + buf * ASTG;
        const uint32_t* Al = smu + ALO0 + buf * ASTG;
        const uint32_t* Bh = smu + BHI0 + buf * BSTG;
        const uint32_t* Bl = smu + BLO0 + buf * BSTG;
#pragma unroll
        for (int ks = 0; ks < 2; ++ks) {
            uint32_t bh[4][2], bl[4][2];
#pragma unroll
            for (int j = 0; j < 4; ++j) {
                const int o = ks * 1058 + ((wn << 2) + j) * 66 + (lane << 1);
                *reinterpret_cast<uint2*>(bh[j]) =
                    *reinterpret_cast<const uint2*>(Bh + o);
                *reinterpret_cast<uint2*>(bl[j]) =
                    *reinterpret_cast<const uint2*>(Bl + o);
            }
#pragma unroll
            for (int i = 0; i < 4; ++i) {
                uint32_t ah[4], al[4];
                const int o = ks * 1060 + ((wm << 2) + i) * 132 + (lane << 2);
                *reinterpret_cast<uint4*>(ah) =
                    *reinterpret_cast<const uint4*>(Ah + o);
                *reinterpret_cast<uint4*>(al) =
                    *reinterpret_cast<const uint4*>(Al + o);
#pragma unroll
                for (int j = 0; j < 4; ++j) {
                    mma16(acc[i][j], ah, bh[j]);
                    mma16(acc[i][j], ah, bl[j]);
                    mma16(acc[i][j], al, bh[j]);
                }
            }
        }
    };

    ldg(0);
    sts(0);
    __syncthreads();
    const int nt = K >> 5;
    for (int t = 0; t < nt; ++t) {
        if (t + 1 < nt) ldg(t + 1);
        compute(t & 1);
        if (t + 1 < nt) sts((t + 1) & 1);  // other buffer: no conflict
        __syncthreads();
    }

    const int r = lane >> 2, cq = (lane & 3) << 1;
    float* Cb = C + (size_t)blockIdx.z * cB;
    const bool mirror = SYM && (blockIdx.y != blockIdx.x);
#pragma unroll
    for (int i = 0; i < 4; ++i) {
#pragma unroll
        for (int j = 0; j < 4; ++j) {
            const int row = m0 + (wm << 6) + (i << 4) + r;
            const int col = n0 + (wn << 5) + (j << 3) + cq;
            float o0 = acc[i][j][0], o1 = acc[i][j][1];
            float o2 = acc[i][j][2], o3 = acc[i][j][3];
            if (HAS_BIAS) {
                float b0 = biasb[col], b1 = biasb[col + 1];
                o0 += b0; o1 += b1; o2 += b0; o3 += b1;
            }
            *reinterpret_cast<float2*>(Cb + (size_t)row * Nn + col) =
                make_float2(o0, o1);
            *reinterpret_cast<float2*>(Cb + (size_t)(row + 8) * Nn + col) =
                make_float2(o2, o3);
            if (mirror) {  // C[col][row] = C[row][col] (G symmetric)
                Cb[(size_t)col * Nn + row] = o0;
                Cb[(size_t)(col + 1) * Nn + row] = o1;
                Cb[(size_t)col * Nn + row + 8] = o2;
                Cb[(size_t)(col + 1) * Nn + row + 8] = o3;
            }
        }
    }
}

// ---------------------------------------------------------------------------
// tiled transpose: out[b][j][i] = in[b][i][j], per-batch RxCc -> CcxR
// ---------------------------------------------------------------------------
__global__ void __launch_bounds__(256)
transpose_kernel(const float* __restrict__ in, float* __restrict__ out,
                 int R, int Cc) {
    __shared__ float t[32][33];
    const float* ib = in + (size_t)blockIdx.z * R * Cc;
    float* ob = out + (size_t)blockIdx.z * R * Cc;
    const int c = blockIdx.x * 32 + threadIdx.x;   // col in input
    const int r0 = blockIdx.y * 32;
#pragma unroll
    for (int j = threadIdx.y; j < 32; j += 8)
        t[j][threadIdx.x] = ib[(size_t)(r0 + j) * Cc + c];
    __syncthreads();
    const int ro = blockIdx.x * 32;                 // row in output
    const int co = r0 + threadIdx.x;                // col in output
#pragma unroll
    for (int j = threadIdx.y; j < 32; j += 8)
        ob[(size_t)(ro + j) * R + co] = t[threadIdx.x][j];
}

// ---------------------------------------------------------------------------
// s[b][e] = sum_n x[b][n][e]
// ---------------------------------------------------------------------------
__global__ void __launch_bounds__(256)
colsum_kernel(const float* __restrict__ x, float* __restrict__ s) {
    const int e = blockIdx.x * 256 + threadIdx.x;
    const int b = blockIdx.y;
    const float* p = x + (size_t)b * N_ * D_ + e;
    float a0 = 0.f, a1 = 0.f, a2 = 0.f, a3 = 0.f;
    for (int n = 0; n < N_; n += 4) {
        a0 += p[(size_t)n * D_];
        a1 += p[(size_t)(n + 1) * D_];
        a2 += p[(size_t)(n + 2) * D_];
        a3 += p[(size_t)(n + 3) * D_];
    }
    s[b * D_ + e] = (a0 + a1) + (a2 + a3);
}

// r[b][f] = sum_e bv[e] * attn[b][e][f]   (weighted column sum)
__global__ void __launch_bounds__(256)
rsum_kernel(const float* __restrict__ attn, const float* __restrict__ bv,
            float* __restrict__ r) {
    const int f = blockIdx.x * 256 + threadIdx.x;
    const int b = blockIdx.y;
    const float* p = attn + (size_t)b * D_ * D_ + f;
    float a0 = 0.f, a1 = 0.f;
    for (int e = 0; e < D_; e += 2) {
        a0 += bv[e] * p[(size_t)e * D_];
        a1 += bv[e + 1] * p[(size_t)(e + 1) * D_];
    }
    r[b * D_ + f] = a0 + a1;
}

// u[b][e] = Wq[e].s[b] ;  w'[b][f] = Wk[f].s[b] + N*bk[f]
__global__ void __launch_bounds__(256)
gemv_kernel(const float* __restrict__ Wq, const float* __restrict__ Wk,
            const float* __restrict__ bk, const float* __restrict__ s,
            float* __restrict__ u, float* __restrict__ w) {
    const int wg = blockIdx.x * 8 + (threadIdx.x >> 5);
    const int lane = threadIdx.x & 31;
    const int b = wg >> 11;           // 2048 outputs per batch
    const int o = wg & 2047;
    const bool is_u = o < 1024;
    const int row = is_u ? o : o - 1024;
    const float* W = (is_u ? Wq : Wk) + (size_t)row * D_;
    const float* sb = s + b * D_;
    float acc = 0.f;
#pragma unroll
    for (int i = 0; i < 32; ++i) acc += W[lane + (i << 5)] * sb[lane + (i << 5)];
#pragma unroll
    for (int off = 16; off; off >>= 1)
        acc += __shfl_xor_sync(0xffffffffu, acc, off);
    if (lane == 0) {
        if (is_u) u[b * D_ + row] = acc;
        else      w[b * D_ + row] = acc + (float)N_ * bk[row];
    }
}

// ---------------------------------------------------------------------------
// softmax with fused rank-1 corrections:
// logit[b][e][f] = L + u[b][e]*bk[f] + bq[e]*w'[b][f]; softmax over f, inplace
// ---------------------------------------------------------------------------
__global__ void __launch_bounds__(256)
softmax_fused(float* __restrict__ L, const float* __restrict__ u,
              const float* __restrict__ w, const float* __restrict__ bq,
              const float* __restrict__ bk) {
    const int row = blockIdx.x;
    const int b = row >> 10, e = row & 1023;
    float* p = L + (size_t)row * 1024;
    const float uu = u[b * D_ + e];
    const float bb = bq[e];
    const float* wb = w + b * D_;
    const int t = threadIdx.x;
    const int lane = t & 31, wid = t >> 5;
    __shared__ float red[8];

    float v[4];
#pragma unroll
    for (int i = 0; i < 4; ++i) {
        const int f = t + (i << 8);
        v[i] = p[f] + uu * bk[f] + bb * wb[f];
    }

    float m = fmaxf(fmaxf(v[0], v[1]), fmaxf(v[2], v[3]));
#pragma unroll
    for (int o = 16; o; o >>= 1) m = fmaxf(m, __shfl_xor_sync(0xffffffffu, m, o));
    if (lane == 0) red[wid] = m;
    __syncthreads();
    if (t < 32) {
        float x = (t < 8) ? red[t] : -3.4e38f;
#pragma unroll
        for (int o = 4; o; o >>= 1) x = fmaxf(x, __shfl_xor_sync(0xffffffffu, x, o));
        if (t == 0) red[0] = x;
    }
    __syncthreads();
    m = red[0];
    __syncthreads();

    float ssum = 0.f;
#pragma unroll
    for (int i = 0; i < 4; ++i) {
        v[i] = expf(v[i] - m);
        ssum += v[i];
    }
#pragma unroll
    for (int o = 16; o; o >>= 1) ssum += __shfl_xor_sync(0xffffffffu, ssum, o);
    if (lane == 0) red[wid] = ssum;
    __syncthreads();
    if (t < 32) {
        float x = (t < 8) ? red[t] : 0.f;
#pragma unroll
        for (int o = 4; o; o >>= 1) x += __shfl_xor_sync(0xffffffffu, x, o);
        if (t == 0) red[0] = x;
    }
    __syncthreads();
    const float inv = 1.0f / red[0];
#pragma unroll
    for (int i = 0; i < 4; ++i) p[t + (i << 8)] = v[i] * inv;
}

extern "C" void kernel_launch(void* const* d_in, const int* in_sizes, int n_in,
                              void* d_out, int out_size) {
    const float* x  = (const float*)d_in[0];
    const float* Wq = (const float*)d_in[1];
    const float* bq = (const float*)d_in[2];
    const float* Wk = (const float*)d_in[3];
    const float* bk = (const float*)d_in[4];
    const float* Wv = (const float*)d_in[5];
    const float* bv = (const float*)d_in[6];
    float* out = (float*)d_out;

    float *xT, *G, *T1, *L, *aT, *W2, *WvT, *s, *u, *w, *r;
    cudaGetSymbolAddress((void**)&xT, g_xT);
    cudaGetSymbolAddress((void**)&G, g_G);
    cudaGetSymbolAddress((void**)&T1, g_T1);
    cudaGetSymbolAddress((void**)&L, g_L);
    cudaGetSymbolAddress((void**)&aT, g_aT);
    cudaGetSymbolAddress((void**)&W2, g_W2);
    cudaGetSymbolAddress((void**)&WvT, g_WvT);
    cudaGetSymbolAddress((void**)&s, g_s);
    cudaGetSymbolAddress((void**)&u, g_u);
    cudaGetSymbolAddress((void**)&w, g_w);
    cudaGetSymbolAddress((void**)&r, g_r);

    cudaFuncSetAttribute(mma_gemm<true, false>,
                         cudaFuncAttributeMaxDynamicSharedMemorySize, SMEM_BYTES);
    cudaFuncSetAttribute(mma_gemm<false, false>,
                         cudaFuncAttributeMaxDynamicSharedMemorySize, SMEM_BYTES);
    cudaFuncSetAttribute(mma_gemm<false, true>,
                         cudaFuncAttributeMaxDynamicSharedMemorySize, SMEM_BYTES);

    const dim3 blk(256);

    // xT[b][e][n] = x[b][n][e] ; WvT[d][e] = Wv[e][d]
    transpose_kernel<<<dim3(32, 128, B_), dim3(32, 8)>>>(x, xT, N_, D_);
    transpose_kernel<<<dim3(32, 32, 1), dim3(32, 8)>>>(Wv, WvT, D_, D_);

    // s = x^T 1 ; u = Wq s ; w' = Wk s + N bk
    colsum_kernel<<<dim3(4, 8), 256>>>(x, s);
    gemv_kernel<<<2048, 256>>>(Wq, Wk, bk, s, u, w);

    // G[b] = xT[b] @ xT[b]^T  (M=N=1024, K=4096), symmetric -> triangle+mirror
    mma_gemm<false, true><<<dim3(8, 8, B_), blk, SMEM_BYTES>>>(
        xT, xT, nullptr, G, D_, D_, N_, N_, N_,
        (size_t)D_ * N_, (size_t)D_ * N_, (size_t)D_ * D_, 0);

    // T1t[b][f][g] = sum_h Wk[f][h] G[b][g][h]  (G symmetric: = (Wk G)[f][g])
    mma_gemm<false, false><<<dim3(8, 8, B_), blk, SMEM_BYTES>>>(
        Wk, G, nullptr, T1, D_, D_, D_, D_, D_,
        0, (size_t)D_ * D_, (size_t)D_ * D_, 0);

    // L[b][e][f] = sum_g Wq[e][g] T1t[b][f][g]
    mma_gemm<false, false><<<dim3(8, 8, B_), blk, SMEM_BYTES>>>(
        Wq, T1, nullptr, L, D_, D_, D_, D_, D_,
        0, (size_t)D_ * D_, (size_t)D_ * D_, 0);

    // softmax with rank-1 corrections, in place -> attn
    softmax_fused<<<B_ * D_, 256>>>(L, u, w, bq, bk);

    // aT[b][f][e] = attn[b][e][f] ; r[b][f] = sum_e bv[e] attn[b][e][f]
    transpose_kernel<<<dim3(32, 32, B_), dim3(32, 8)>>>(L, aT, D_, D_);
    rsum_kernel<<<dim3(4, 8), 256>>>(L, bv, r);

    // W2t[b][f][d] = sum_e aT[b][f][e] WvT[d][e]   (= (Wv^T attn)^T)
    mma_gemm<false, false><<<dim3(8, 8, B_), blk, SMEM_BYTES>>>(
        aT, WvT, nullptr, W2, D_, D_, D_, D_, D_,
        (size_t)D_ * D_, 0, (size_t)D_ * D_, 0);

    // out[b][n][f] = sum_d x[b][n][d] W2t[b][f][d] + r[b][f]
    mma_gemm<true, false><<<dim3(8, 32, B_), blk, SMEM_BYTES>>>(
        x, W2, r, out, N_, D_, D_, D_, D_,
        (size_t)N_ * D_, (size_t)D_ * D_, (size_t)N_ * D_, D_);
}

// round 12
// speedup vs baseline: 2.4200x; 1.1699x over previous
#include <cuda_runtime.h>
#include <cuda_fp16.h>
#include <cstdint>

#define B_   8
#define N_   4096
#define D_   1024

// scratch (device globals; no allocations allowed)
__device__ float g_xT [(size_t)B_ * D_ * N_];   // x^T per batch    128 MB
__device__ float g_G  [(size_t)B_ * D_ * D_];   // G = x^T x         32 MB
__device__ float g_T1 [(size_t)B_ * D_ * D_];   // T1t = Wk G        32 MB
__device__ float g_L  [(size_t)B_ * D_ * D_];   // logits -> attn    32 MB
__device__ float g_aT [(size_t)B_ * D_ * D_];   // attn^T            32 MB
__device__ float g_W2 [(size_t)B_ * D_ * D_];   // W2t = attn^T Wv^T 32 MB
__device__ float g_WvT[(size_t)D_ * D_];        // Wv^T               4 MB
__device__ float g_s  [(size_t)B_ * D_];        // s = x^T 1
__device__ float g_u  [(size_t)B_ * D_];        // u = Wq s
__device__ float g_w  [(size_t)B_ * D_];        // w' = Wk s + N*bk
__device__ float g_r  [(size_t)B_ * D_];        // r = bv^T attn

__device__ __forceinline__ void mma16(float* c, const uint32_t* a,
                                      const uint32_t* b) {
    asm("mma.sync.aligned.m16n8k16.row.col.f32.f16.f16.f32 "
        "{%0,%1,%2,%3}, {%4,%5,%6,%7}, {%8,%9}, {%0,%1,%2,%3};"
        : "+f"(c[0]), "+f"(c[1]), "+f"(c[2]), "+f"(c[3])
        : "r"(a[0]), "r"(a[1]), "r"(a[2]), "r"(a[3]), "r"(b[0]), "r"(b[1]));
}

// split x = hi + lo, both fp16 (11-bit mantissa each -> ~22-bit coverage)
__device__ __forceinline__ void split_h(float x, uint16_t& h, uint16_t& l) {
    __half hh = __float2half_rn(x);
    float hf = __half2float(hh);
    h = __half_as_ushort(hh);
    l = __half_as_ushort(__float2half_rn(x - hf));
}
__device__ __forceinline__ uint32_t pack2h(uint16_t lo, uint16_t hi) {
    return (uint32_t)lo | ((uint32_t)hi << 16);
}

// ---------------------------------------------------------------------------
// FP16 split mma.sync m16n8k16 GEMM: C[M,N] = A * B^T (+bias per batch)
// SPLITS=3: A hi/lo + B hi/lo, 3 products (logit path, ~fp32 precision)
// SPLITS=2: A rounded fp16, B hi/lo, 2 products (post-softmax path,
//           linear error ~2^-11/sqrt(3); no Alo plane: -33% MMA, -25% LDS)
// NATURAL layouts only: A [M,K] k-contig, B [N,K] k-contig.
// CTA 128x128, 256 threads, 8 warps (grid 2x4), warp tile 64x32.
// K-stage 32 (2 k16-steps), double-buffered; split once at store time.
// 2 CTAs/SM.  SYM: C symmetric (A==B) -> lower triangle + mirror write.
// Fragment-order SMEM, words are f16x2 pairs:
//   A: word idx = ks*1060 + mt*132 + lane*4 + reg   (mt<8, reg<4)
//   B: word idx = ks*1058 + nt*66  + lane*2 + reg   (nt<16, reg<2)
// ---------------------------------------------------------------------------
constexpr int ASTG = 2120, BSTG = 2116;
constexpr int AHI0 = 0;
constexpr int ALO0 = 2 * ASTG;
constexpr int BHI0 = 4 * ASTG;
constexpr int BLO0 = 4 * ASTG + 2 * BSTG;
constexpr int SMEM_BYTES = (4 * ASTG + 4 * BSTG) * 4;  // 67,776 B

template <bool HAS_BIAS, bool SYM, int SPLITS>
__global__ void __launch_bounds__(256, 2)
mma_gemm(const float* __restrict__ A, const float* __restrict__ Bm,
         const float* __restrict__ bias, float* __restrict__ C,
         int M, int Nn, int K, int lda, int ldb,
         size_t aB, size_t bB, size_t cB, size_t biasB) {
    if (SYM && blockIdx.y < blockIdx.x) return;  // lower triangle only
    extern __shared__ float sm[];
    uint32_t* smu = reinterpret_cast<uint32_t*>(sm);
    const int tid = threadIdx.x;
    const int lane = tid & 31, wid = tid >> 5;
    const int wm = wid & 1, wn = wid >> 1;  // warp grid 2(M) x 4(N)
    const float* Ab = A + (size_t)blockIdx.z * aB;
    const float* Bb = Bm + (size_t)blockIdx.z * bB;
    const float* biasb = HAS_BIAS ? bias + (size_t)blockIdx.z * biasB : nullptr;
    const int m0 = blockIdx.y * 128;
    const int n0 = blockIdx.x * 128;

    float acc[4][4][4];
#pragma unroll
    for (int i = 0; i < 4; ++i)
#pragma unroll
        for (int j = 0; j < 4; ++j)
#pragma unroll
            for (int e = 0; e < 4; ++e) acc[i][j][e] = 0.f;

    float4 ra[4], rb[4];
    auto ldg = [&](int kt) {
#pragma unroll
        for (int it = 0; it < 4; ++it) {
            int idx = tid + (it << 8);
            int mm = idx >> 3, k4 = idx & 7;
            ra[it] = *reinterpret_cast<const float4*>(
                Ab + (size_t)(m0 + mm) * lda + kt * 32 + (k4 << 2));
            rb[it] = *reinterpret_cast<const float4*>(
                Bb + (size_t)(n0 + mm) * ldb + kt * 32 + (k4 << 2));
        }
    };
    auto sts = [&](int buf) {
        uint32_t* Ah = smu + AHI0 + buf * ASTG;
        uint32_t* Al = smu + ALO0 + buf * ASTG;
        uint32_t* Bh = smu + BHI0 + buf * BSTG;
        uint32_t* Bl = smu + BLO0 + buf * BSTG;
#pragma unroll
        for (int it = 0; it < 4; ++it) {
            int idx = tid + (it << 8);
            int mm = idx >> 3, k4 = idx & 7;
            float va[4] = {ra[it].x, ra[it].y, ra[it].z, ra[it].w};
            float vb[4] = {rb[it].x, rb[it].y, rb[it].z, rb[it].w};
            uint16_t hA[4], lA[4], hB[4], lB[4];
#pragma unroll
            for (int c = 0; c < 4; ++c) {
                if (SPLITS == 3) {
                    split_h(va[c], hA[c], lA[c]);
                } else {
                    hA[c] = __half_as_ushort(__float2half_rn(va[c]));
                }
                split_h(vb[c], hB[c], lB[c]);
            }
            {   // A: (row mm, k0..k0+3) -> 2 packed words
                int k0 = k4 << 2;
                int ks = k0 >> 4, kk = k0 & 15;
                int rr = mm & 15, mt = mm >> 4;
                int reg = (rr >> 3) + ((kk >> 3) << 1);
                int o = ks * 1060 + mt * 132 +
                        (((rr & 7) << 2) + ((kk & 7) >> 1)) * 4 + reg;
                Ah[o] = pack2h(hA[0], hA[1]);
                Ah[o + 4] = pack2h(hA[2], hA[3]);
                if (SPLITS == 3) {
                    Al[o] = pack2h(lA[0], lA[1]);
                    Al[o + 4] = pack2h(lA[2], lA[3]);
                }
            }
            {   // B: (row nn, k0..k0+3) -> 2 packed words
                int k0 = k4 << 2;
                int ks = k0 >> 4, kk = k0 & 15;
                int nt = mm >> 3;
                int reg = kk >> 3;
                int o = ks * 1058 + nt * 66 +
                        (((mm & 7) << 2) + ((kk & 7) >> 1)) * 2 + reg;
                Bh[o] = pack2h(hB[0], hB[1]);
                Bh[o + 2] = pack2h(hB[2], hB[3]);
                Bl[o] = pack2h(lB[0], lB[1]);
                Bl[o + 2] = pack2h(lB[2], lB[3]);
            }
        }
    };
    auto compute = [&](int buf) {
        const uint32_t* Ah = smu + AHI0 + buf * ASTG;
        const uint32_t* Al = smu + ALO0 + buf * ASTG;
        const uint32_t* Bh = smu + BHI0 + buf * BSTG;
        const uint32_t* Bl = smu + BLO0 + buf * BSTG;
#pragma unroll
        for (int ks = 0; ks < 2; ++ks) {
            uint32_t bh[4][2], bl[4][2];
#pragma unroll
            for (int j = 0; j < 4; ++j) {
                const int o = ks * 1058 + ((wn << 2) + j) * 66 + (lane << 1);
                *reinterpret_cast<uint2*>(bh[j]) =
                    *reinterpret_cast<const uint2*>(Bh + o);
                *reinterpret_cast<uint2*>(bl[j]) =
                    *reinterpret_cast<const uint2*>(Bl + o);
            }
#pragma unroll
            for (int i = 0; i < 4; ++i) {
                uint32_t ah[4], al[4];
                const int o = ks * 1060 + ((wm << 2) + i) * 132 + (lane << 2);
                *reinterpret_cast<uint4*>(ah) =
                    *reinterpret_cast<const uint4*>(Ah + o);
                if (SPLITS == 3)
                    *reinterpret_cast<uint4*>(al) =
                        *reinterpret_cast<const uint4*>(Al + o);
#pragma unroll
                for (int j = 0; j < 4; ++j) {
                    mma16(acc[i][j], ah, bh[j]);
                    mma16(acc[i][j], ah, bl[j]);
                    if (SPLITS == 3) mma16(acc[i][j], al, bh[j]);
                }
            }
        }
    };

    ldg(0);
    sts(0);
    __syncthreads();
    const int nt = K >> 5;
    for (int t = 0; t < nt; ++t) {
        if (t + 1 < nt) ldg(t + 1);
        compute(t & 1);
        if (t + 1 < nt) sts((t + 1) & 1);  // other buffer: no conflict
        __syncthreads();
    }

    const int r = lane >> 2, cq = (lane & 3) << 1;
    float* Cb = C + (size_t)blockIdx.z * cB;
    const bool mirror = SYM && (blockIdx.y != blockIdx.x);
#pragma unroll
    for (int i = 0; i < 4; ++i) {
#pragma unroll
        for (int j = 0; j < 4; ++j) {
            const int row = m0 + (wm << 6) + (i << 4) + r;
            const int col = n0 + (wn << 5) + (j << 3) + cq;
            float o0 = acc[i][j][0], o1 = acc[i][j][1];
            float o2 = acc[i][j][2], o3 = acc[i][j][3];
            if (HAS_BIAS) {
                float b0 = biasb[col], b1 = biasb[col + 1];
                o0 += b0; o1 += b1; o2 += b0; o3 += b1;
            }
            *reinterpret_cast<float2*>(Cb + (size_t)row * Nn + col) =
                make_float2(o0, o1);
            *reinterpret_cast<float2*>(Cb + (size_t)(row + 8) * Nn + col) =
                make_float2(o2, o3);
            if (mirror) {  // C[col][row] = C[row][col] (G symmetric)
                Cb[(size_t)col * Nn + row] = o0;
                Cb[(size_t)(col + 1) * Nn + row] = o1;
                Cb[(size_t)col * Nn + row + 8] = o2;
                Cb[(size_t)(col + 1) * Nn + row + 8] = o3;
            }
        }
    }
}

// ---------------------------------------------------------------------------
// tiled transpose: out[b][j][i] = in[b][i][j], per-batch RxCc -> CcxR
// ---------------------------------------------------------------------------
__global__ void __launch_bounds__(256)
transpose_kernel(const float* __restrict__ in, float* __restrict__ out,
                 int R, int Cc) {
    __shared__ float t[32][33];
    const float* ib = in + (size_t)blockIdx.z * R * Cc;
    float* ob = out + (size_t)blockIdx.z * R * Cc;
    const int c = blockIdx.x * 32 + threadIdx.x;   // col in input
    const int r0 = blockIdx.y * 32;
#pragma unroll
    for (int j = threadIdx.y; j < 32; j += 8)
        t[j][threadIdx.x] = ib[(size_t)(r0 + j) * Cc + c];
    __syncthreads();
    const int ro = blockIdx.x * 32;                 // row in output
    const int co = r0 + threadIdx.x;                // col in output
#pragma unroll
    for (int j = threadIdx.y; j < 32; j += 8)
        ob[(size_t)(ro + j) * R + co] = t[threadIdx.x][j];
}

// ---------------------------------------------------------------------------
// s[b][e] = sum_n x[b][n][e]
// ---------------------------------------------------------------------------
__global__ void __launch_bounds__(256)
colsum_kernel(const float* __restrict__ x, float* __restrict__ s) {
    const int e = blockIdx.x * 256 + threadIdx.x;
    const int b = blockIdx.y;
    const float* p = x + (size_t)b * N_ * D_ + e;
    float a0 = 0.f, a1 = 0.f, a2 = 0.f, a3 = 0.f;
    for (int n = 0; n < N_; n += 4) {
        a0 += p[(size_t)n * D_];
        a1 += p[(size_t)(n + 1) * D_];
        a2 += p[(size_t)(n + 2) * D_];
        a3 += p[(size_t)(n + 3) * D_];
    }
    s[b * D_ + e] = (a0 + a1) + (a2 + a3);
}

// r[b][f] = sum_e bv[e] * attn[b][e][f]   (weighted column sum)
__global__ void __launch_bounds__(256)
rsum_kernel(const float* __restrict__ attn, const float* __restrict__ bv,
            float* __restrict__ r) {
    const int f = blockIdx.x * 256 + threadIdx.x;
    const int b = blockIdx.y;
    const float* p = attn + (size_t)b * D_ * D_ + f;
    float a0 = 0.f, a1 = 0.f;
    for (int e = 0; e < D_; e += 2) {
        a0 += bv[e] * p[(size_t)e * D_];
        a1 += bv[e + 1] * p[(size_t)(e + 1) * D_];
    }
    r[b * D_ + f] = a0 + a1;
}

// u[b][e] = Wq[e].s[b] ;  w'[b][f] = Wk[f].s[b] + N*bk[f]
__global__ void __launch_bounds__(256)
gemv_kernel(const float* __restrict__ Wq, const float* __restrict__ Wk,
            const float* __restrict__ bk, const float* __restrict__ s,
            float* __restrict__ u, float* __restrict__ w) {
    const int wg = blockIdx.x * 8 + (threadIdx.x >> 5);
    const int lane = threadIdx.x & 31;
    const int b = wg >> 11;           // 2048 outputs per batch
    const int o = wg & 2047;
    const bool is_u = o < 1024;
    const int row = is_u ? o : o - 1024;
    const float* W = (is_u ? Wq : Wk) + (size_t)row * D_;
    const float* sb = s + b * D_;
    float acc = 0.f;
#pragma unroll
    for (int i = 0; i < 32; ++i) acc += W[lane + (i << 5)] * sb[lane + (i << 5)];
#pragma unroll
    for (int off = 16; off; off >>= 1)
        acc += __shfl_xor_sync(0xffffffffu, acc, off);
    if (lane == 0) {
        if (is_u) u[b * D_ + row] = acc;
        else      w[b * D_ + row] = acc + (float)N_ * bk[row];
    }
}

// ---------------------------------------------------------------------------
// softmax with fused rank-1 corrections:
// logit[b][e][f] = L + u[b][e]*bk[f] + bq[e]*w'[b][f]; softmax over f, inplace
// ---------------------------------------------------------------------------
__global__ void __launch_bounds__(256)
softmax_fused(float* __restrict__ L, const float* __restrict__ u,
              const float* __restrict__ w, const float* __restrict__ bq,
              const float* __restrict__ bk) {
    const int row = blockIdx.x;
    const int b = row >> 10, e = row & 1023;
    float* p = L + (size_t)row * 1024;
    const float uu = u[b * D_ + e];
    const float bb = bq[e];
    const float* wb = w + b * D_;
    const int t = threadIdx.x;
    const int lane = t & 31, wid = t >> 5;
    __shared__ float red[8];

    float v[4];
#pragma unroll
    for (int i = 0; i < 4; ++i) {
        const int f = t + (i << 8);
        v[i] = p[f] + uu * bk[f] + bb * wb[f];
    }

    float m = fmaxf(fmaxf(v[0], v[1]), fmaxf(v[2], v[3]));
#pragma unroll
    for (int o = 16; o; o >>= 1) m = fmaxf(m, __shfl_xor_sync(0xffffffffu, m, o));
    if (lane == 0) red[wid] = m;
    __syncthreads();
    if (t < 32) {
        float x = (t < 8) ? red[t] : -3.4e38f;
#pragma unroll
        for (int o = 4; o; o >>= 1) x = fmaxf(x, __shfl_xor_sync(0xffffffffu, x, o));
        if (t == 0) red[0] = x;
    }
    __syncthreads();
    m = red[0];
    __syncthreads();

    float ssum = 0.f;
#pragma unroll
    for (int i = 0; i < 4; ++i) {
        v[i] = expf(v[i] - m);
        ssum += v[i];
    }
#pragma unroll
    for (int o = 16; o; o >>= 1) ssum += __shfl_xor_sync(0xffffffffu, ssum, o);
    if (lane == 0) red[wid] = ssum;
    __syncthreads();
    if (t < 32) {
        float x = (t < 8) ? red[t] : 0.f;
#pragma unroll
        for (int o = 4; o; o >>= 1) x += __shfl_xor_sync(0xffffffffu, x, o);
        if (t == 0) red[0] = x;
    }
    __syncthreads();
    const float inv = 1.0f / red[0];
#pragma unroll
    for (int i = 0; i < 4; ++i) p[t + (i << 8)] = v[i] * inv;
}

extern "C" void kernel_launch(void* const* d_in, const int* in_sizes, int n_in,
                              void* d_out, int out_size) {
    const float* x  = (const float*)d_in[0];
    const float* Wq = (const float*)d_in[1];
    const float* bq = (const float*)d_in[2];
    const float* Wk = (const float*)d_in[3];
    const float* bk = (const float*)d_in[4];
    const float* Wv = (const float*)d_in[5];
    const float* bv = (const float*)d_in[6];
    float* out = (float*)d_out;

    float *xT, *G, *T1, *L, *aT, *W2, *WvT, *s, *u, *w, *r;
    cudaGetSymbolAddress((void**)&xT, g_xT);
    cudaGetSymbolAddress((void**)&G, g_G);
    cudaGetSymbolAddress((void**)&T1, g_T1);
    cudaGetSymbolAddress((void**)&L, g_L);
    cudaGetSymbolAddress((void**)&aT, g_aT);
    cudaGetSymbolAddress((void**)&W2, g_W2);
    cudaGetSymbolAddress((void**)&WvT, g_WvT);
    cudaGetSymbolAddress((void**)&s, g_s);
    cudaGetSymbolAddress((void**)&u, g_u);
    cudaGetSymbolAddress((void**)&w, g_w);
    cudaGetSymbolAddress((void**)&r, g_r);

    cudaFuncSetAttribute(mma_gemm<false, true, 3>,
                         cudaFuncAttributeMaxDynamicSharedMemorySize, SMEM_BYTES);
    cudaFuncSetAttribute(mma_gemm<false, false, 3>,
                         cudaFuncAttributeMaxDynamicSharedMemorySize, SMEM_BYTES);
    cudaFuncSetAttribute(mma_gemm<false, false, 2>,
                         cudaFuncAttributeMaxDynamicSharedMemorySize, SMEM_BYTES);
    cudaFuncSetAttribute(mma_gemm<true, false, 2>,
                         cudaFuncAttributeMaxDynamicSharedMemorySize, SMEM_BYTES);

    const dim3 blk(256);

    // xT[b][e][n] = x[b][n][e] ; WvT[d][e] = Wv[e][d]
    transpose_kernel<<<dim3(32, 128, B_), dim3(32, 8)>>>(x, xT, N_, D_);
    transpose_kernel<<<dim3(32, 32, 1), dim3(32, 8)>>>(Wv, WvT, D_, D_);

    // s = x^T 1 ; u = Wq s ; w' = Wk s + N bk
    colsum_kernel<<<dim3(4, 8), 256>>>(x, s);
    gemv_kernel<<<2048, 256>>>(Wq, Wk, bk, s, u, w);

    // G[b] = xT[b] @ xT[b]^T  (sym, 3-split: logit path)
    mma_gemm<false, true, 3><<<dim3(8, 8, B_), blk, SMEM_BYTES>>>(
        xT, xT, nullptr, G, D_, D_, N_, N_, N_,
        (size_t)D_ * N_, (size_t)D_ * N_, (size_t)D_ * D_, 0);

    // T1t[b][f][g] = sum_h Wk[f][h] G[b][g][h]   (3-split)
    mma_gemm<false, false, 3><<<dim3(8, 8, B_), blk, SMEM_BYTES>>>(
        Wk, G, nullptr, T1, D_, D_, D_, D_, D_,
        0, (size_t)D_ * D_, (size_t)D_ * D_, 0);

    // L[b][e][f] = sum_g Wq[e][g] T1t[b][f][g]   (3-split)
    mma_gemm<false, false, 3><<<dim3(8, 8, B_), blk, SMEM_BYTES>>>(
        Wq, T1, nullptr, L, D_, D_, D_, D_, D_,
        0, (size_t)D_ * D_, (size_t)D_ * D_, 0);

    // softmax with rank-1 corrections, in place -> attn
    softmax_fused<<<B_ * D_, 256>>>(L, u, w, bq, bk);

    // aT[b][f][e] = attn[b][e][f] ; r[b][f] = sum_e bv[e] attn[b][e][f]
    transpose_kernel<<<dim3(32, 32, B_), dim3(32, 8)>>>(L, aT, D_, D_);
    rsum_kernel<<<dim3(4, 8), 256>>>(L, bv, r);

    // W2t[b][f][d] = sum_e aT[b][f][e] WvT[d][e]   (2-split: linear path)
    mma_gemm<false, false, 2><<<dim3(8, 8, B_), blk, SMEM_BYTES>>>(
        aT, WvT, nullptr, W2, D_, D_, D_, D_, D_,
        (size_t)D_ * D_, 0, (size_t)D_ * D_, 0);

    // out[b][n][f] = sum_d x[b][n][d] W2t[b][f][d] + r[b][f]   (2-split)
    mma_gemm<true, false, 2><<<dim3(8, 32, B_), blk, SMEM_BYTES>>>(
        x, W2, r, out, N_, D_, D_, D_, D_,
        (size_t)N_ * D_, (size_t)D_ * D_, (size_t)N_ * D_, D_);
}

// round 13
// speedup vs baseline: 2.8392x; 1.1732x over previous
#include <cuda_runtime.h>
#include <cuda_fp16.h>
#include <cstdint>

#define B_   8
#define N_   4096
#define D_   1024

// ---------------------------------------------------------------------------
// fp32 scratch
// ---------------------------------------------------------------------------
__device__ float g_xT [(size_t)B_ * D_ * N_];   // x^T per batch    128 MB
__device__ float g_G  [(size_t)B_ * D_ * D_];   // G = x^T x
__device__ float g_T1 [(size_t)B_ * D_ * D_];   // T1t = Wk G
__device__ float g_L  [(size_t)B_ * D_ * D_];   // logits -> attn
__device__ float g_aT [(size_t)B_ * D_ * D_];   // attn^T
__device__ float g_W2 [(size_t)B_ * D_ * D_];   // W2t = attn^T Wv^T
__device__ float g_WvT[(size_t)D_ * D_];        // Wv^T
__device__ float g_s  [(size_t)B_ * D_];        // s = x^T 1
__device__ float g_u  [(size_t)B_ * D_];        // u = Wq s
__device__ float g_w  [(size_t)B_ * D_];        // w' = Wk s + N*bk
__device__ float g_r  [(size_t)B_ * D_];        // r = bv^T attn

// ---------------------------------------------------------------------------
// pre-split fp16 plane buffers (fragment-order GMEM; words = f16x2)
// A-role block: [hi 2048][lo 2048 if 3-split] per (tile,kstage)
// B-role block: [hi 2048][lo 2048]            per (tile,kstage)
// ---------------------------------------------------------------------------
__device__ uint32_t g_xTA[(size_t)8 * 8 * 128 * 4096];   // 134 MB
__device__ uint32_t g_xTB[(size_t)8 * 8 * 128 * 4096];   // 134 MB
__device__ uint32_t g_xA [(size_t)256 * 32 * 2048];      //  64 MB
__device__ uint32_t g_GB [(size_t)8 * 8 * 32 * 4096];    //  33 MB
__device__ uint32_t g_T1B[(size_t)8 * 8 * 32 * 4096];    //  33 MB
__device__ uint32_t g_W2B[(size_t)8 * 8 * 32 * 4096];    //  33 MB
__device__ uint32_t g_aTA[(size_t)8 * 8 * 32 * 2048];    //  17 MB
__device__ uint32_t g_WqA[(size_t)8 * 32 * 4096];        //   4 MB
__device__ uint32_t g_WkA[(size_t)8 * 32 * 4096];        //   4 MB
__device__ uint32_t g_WvB[(size_t)8 * 32 * 4096];        //   4 MB

__device__ __forceinline__ uint32_t smem_u32(const void* p) {
    uint32_t a;
    asm("{ .reg .u64 t; cvta.to.shared.u64 t, %1; cvt.u32.u64 %0, t; }"
        : "=r"(a) : "l"(p));
    return a;
}
__device__ __forceinline__ void cpa16(uint32_t saddr, const void* g) {
    asm volatile("cp.async.cg.shared.global [%0], [%1], 16;"
                 :: "r"(saddr), "l"(g));
}
__device__ __forceinline__ void mma16(float* c, const uint32_t* a,
                                      const uint32_t* b) {
    asm("mma.sync.aligned.m16n8k16.row.col.f32.f16.f16.f32 "
        "{%0,%1,%2,%3}, {%4,%5,%6,%7}, {%8,%9}, {%0,%1,%2,%3};"
        : "+f"(c[0]), "+f"(c[1]), "+f"(c[2]), "+f"(c[3])
        : "r"(a[0]), "r"(a[1]), "r"(a[2]), "r"(a[3]), "r"(b[0]), "r"(b[1]));
}
__device__ __forceinline__ void split_h(float x, uint16_t& h, uint16_t& l) {
    __half hh = __float2half_rn(x);
    float hf = __half2float(hh);
    h = __half_as_ushort(hh);
    l = __half_as_ushort(__float2half_rn(x - hf));
}
__device__ __forceinline__ uint32_t pack2h(uint16_t lo, uint16_t hi) {
    return (uint32_t)lo | ((uint32_t)hi << 16);
}

// ---------------------------------------------------------------------------
// converter: fp32 [rows,K] tile (128x32) -> fragment-order fp16 planes
// ROLE_A: A fragment layout (4 words/lane-grp); else B layout (2 words).
// WITH_LO: write lo plane at +2048 (3-split operands; B-role always true).
// grid (ntiles, nkst, nb), block 256.
// ---------------------------------------------------------------------------
template <bool ROLE_A, bool WITH_LO>
__global__ void __launch_bounds__(256)
conv_kernel(const float* __restrict__ src, uint32_t* __restrict__ dst,
            int ld, size_t srcBatch, int nkst) {
    const int tid = threadIdx.x;
    const int tileR = blockIdx.x, kst = blockIdx.y, bz = blockIdx.z;
    constexpr int WORDS = ROLE_A ? (WITH_LO ? 4096 : 2048) : 4096;
    const float* sb =
        src + (size_t)bz * srcBatch + (size_t)tileR * 128 * ld + kst * 32;
    uint32_t* db =
        dst + (((size_t)bz * gridDim.x + tileR) * nkst + kst) * WORDS;
#pragma unroll
    for (int it = 0; it < 4; ++it) {
        int idx = tid + (it << 8);
        int mm = idx >> 3, k4 = idx & 7;
        float4 v = *reinterpret_cast<const float4*>(sb + (size_t)mm * ld +
                                                    (k4 << 2));
        float va[4] = {v.x, v.y, v.z, v.w};
        uint16_t h[4], l[4];
#pragma unroll
        for (int c = 0; c < 4; ++c) {
            if (WITH_LO) split_h(va[c], h[c], l[c]);
            else h[c] = __half_as_ushort(__float2half_rn(va[c]));
        }
        int k0 = k4 << 2, ks = k0 >> 4, kk = k0 & 15;
        if (ROLE_A) {
            int rr = mm & 15, mt = mm >> 4;
            int reg = (rr >> 3) + ((kk >> 3) << 1);
            int o = ks * 1024 + mt * 128 +
                    (((rr & 7) << 2) + ((kk & 7) >> 1)) * 4 + reg;
            db[o] = pack2h(h[0], h[1]);
            db[o + 4] = pack2h(h[2], h[3]);
            if (WITH_LO) {
                db[2048 + o] = pack2h(l[0], l[1]);
                db[2048 + o + 4] = pack2h(l[2], l[3]);
            }
        } else {
            int nt = mm >> 3, reg = kk >> 3;
            int o = ks * 1024 + nt * 64 +
                    (((mm & 7) << 2) + ((kk & 7) >> 1)) * 2 + reg;
            db[o] = pack2h(h[0], h[1]);
            db[o + 2] = pack2h(h[2], h[3]);
            db[2048 + o] = pack2h(l[0], l[1]);
            db[2048 + o + 2] = pack2h(l[2], l[3]);
        }
    }
}

// ---------------------------------------------------------------------------
// async GEMM: C[M,N] = A*B^T from PRE-SPLIT fragment-order planes.
// cp.async 3-stage pipeline; mainloop = cp.async + LDS + MMA only.
// CTA 128x128, 256 thr, 8 warps (2x4), warp tile 64x32, k-stage 32.
// SPLITS=3: ah*bh + ah*bl + al*bh. SPLITS=2: ah*bh + ah*bl (A pre-rounded).
// smem/stage: [Ahi][Alo?][Bhi][Blo] unpadded (no STS -> no scatter conflicts)
// ---------------------------------------------------------------------------
template <int SPLITS, bool HAS_BIAS, bool SYM>
__global__ void __launch_bounds__(256, 2)
gemm_async(const uint32_t* __restrict__ Ap, const uint32_t* __restrict__ Bp,
           const float* __restrict__ bias, float* __restrict__ C,
           int Nn, int nkst, size_t aBatch, size_t bBatch, size_t cB,
           size_t biasB) {
    if (SYM && blockIdx.y < blockIdx.x) return;
    extern __shared__ uint32_t smw[];
    const uint32_t sbase = smem_u32(smw);
    constexpr int AW = (SPLITS == 3) ? 4096 : 2048;
    constexpr int SW = AW + 4096;          // words per stage
    constexpr int NCHUNK = SW / 4 / 256;   // 16B chunks per thread per stage
    const int tid = threadIdx.x;
    const int lane = tid & 31, wid = tid >> 5;
    const int wm = wid & 1, wn = wid >> 1;
    const uint32_t* Abase =
        Ap + blockIdx.z * aBatch + (size_t)blockIdx.y * nkst * AW;
    const uint32_t* Bbase =
        Bp + blockIdx.z * bBatch + (size_t)blockIdx.x * nkst * 4096;
    const float* biasb = HAS_BIAS ? bias + blockIdx.z * biasB : nullptr;

    float acc[4][4][4];
#pragma unroll
    for (int i = 0; i < 4; ++i)
#pragma unroll
        for (int j = 0; j < 4; ++j)
#pragma unroll
            for (int e = 0; e < 4; ++e) acc[i][j][e] = 0.f;

    auto issue = [&](int t, int buf) {
        const uint32_t* As = Abase + (size_t)t * AW;
        const uint32_t* Bs = Bbase + (size_t)t * 4096;
        const uint32_t sb = sbase + (uint32_t)(buf * SW) * 4u;
#pragma unroll
        for (int c = 0; c < NCHUNK; ++c) {
            int id = tid + (c << 8);
            if (id < AW / 4) cpa16(sb + id * 16, As + id * 4);
            else cpa16(sb + id * 16, Bs + (size_t)(id - AW / 4) * 4);
        }
    };
    auto compute = [&](int buf) {
        const uint32_t* S = smw + buf * SW;
        const uint32_t* Ah = S;
        const uint32_t* Al = S + 2048;
        const uint32_t* Bh = S + AW;
        const uint32_t* Bl = S + AW + 2048;
#pragma unroll
        for (int ks = 0; ks < 2; ++ks) {
            uint32_t bh[4][2], bl[4][2];
#pragma unroll
            for (int j = 0; j < 4; ++j) {
                const int o = ks * 1024 + ((wn << 2) + j) * 64 + (lane << 1);
                *reinterpret_cast<uint2*>(bh[j]) =
                    *reinterpret_cast<const uint2*>(Bh + o);
                *reinterpret_cast<uint2*>(bl[j]) =
                    *reinterpret_cast<const uint2*>(Bl + o);
            }
#pragma unroll
            for (int i = 0; i < 4; ++i) {
                uint32_t ah[4], al[4];
                const int o = ks * 1024 + ((wm << 2) + i) * 128 + (lane << 2);
                *reinterpret_cast<uint4*>(ah) =
                    *reinterpret_cast<const uint4*>(Ah + o);
                if (SPLITS == 3)
                    *reinterpret_cast<uint4*>(al) =
                        *reinterpret_cast<const uint4*>(Al + o);
#pragma unroll
                for (int j = 0; j < 4; ++j) {
                    mma16(acc[i][j], ah, bh[j]);
                    mma16(acc[i][j], ah, bl[j]);
                    if (SPLITS == 3) mma16(acc[i][j], al, bh[j]);
                }
            }
        }
    };

    // 3-stage pipeline
    issue(0, 0);
    asm volatile("cp.async.commit_group;" ::: "memory");
    issue(1, 1);
    asm volatile("cp.async.commit_group;" ::: "memory");
    for (int t = 0; t < nkst; ++t) {
        if (t + 1 < nkst)
            asm volatile("cp.async.wait_group 1;" ::: "memory");
        else
            asm volatile("cp.async.wait_group 0;" ::: "memory");
        __syncthreads();
        if (t + 2 < nkst) {
            issue(t + 2, (t + 2) % 3);
            asm volatile("cp.async.commit_group;" ::: "memory");
        }
        compute(t % 3);
    }

    const int r = lane >> 2, cq = (lane & 3) << 1;
    const int m0 = blockIdx.y * 128, n0 = blockIdx.x * 128;
    float* Cb = C + (size_t)blockIdx.z * cB;
    const bool mirror = SYM && (blockIdx.y != blockIdx.x);
#pragma unroll
    for (int i = 0; i < 4; ++i) {
#pragma unroll
        for (int j = 0; j < 4; ++j) {
            const int row = m0 + (wm << 6) + (i << 4) + r;
            const int col = n0 + (wn << 5) + (j << 3) + cq;
            float o0 = acc[i][j][0], o1 = acc[i][j][1];
            float o2 = acc[i][j][2], o3 = acc[i][j][3];
            if (HAS_BIAS) {
                float b0 = biasb[col], b1 = biasb[col + 1];
                o0 += b0; o1 += b1; o2 += b0; o3 += b1;
            }
            *reinterpret_cast<float2*>(Cb + (size_t)row * Nn + col) =
                make_float2(o0, o1);
            *reinterpret_cast<float2*>(Cb + (size_t)(row + 8) * Nn + col) =
                make_float2(o2, o3);
            if (mirror) {
                Cb[(size_t)col * Nn + row] = o0;
                Cb[(size_t)(col + 1) * Nn + row] = o1;
                Cb[(size_t)col * Nn + row + 8] = o2;
                Cb[(size_t)(col + 1) * Nn + row + 8] = o3;
            }
        }
    }
}

// ---------------------------------------------------------------------------
// helpers (unchanged)
// ---------------------------------------------------------------------------
__global__ void __launch_bounds__(256)
transpose_kernel(const float* __restrict__ in, float* __restrict__ out,
                 int R, int Cc) {
    __shared__ float t[32][33];
    const float* ib = in + (size_t)blockIdx.z * R * Cc;
    float* ob = out + (size_t)blockIdx.z * R * Cc;
    const int c = blockIdx.x * 32 + threadIdx.x;
    const int r0 = blockIdx.y * 32;
#pragma unroll
    for (int j = threadIdx.y; j < 32; j += 8)
        t[j][threadIdx.x] = ib[(size_t)(r0 + j) * Cc + c];
    __syncthreads();
    const int ro = blockIdx.x * 32;
    const int co = r0 + threadIdx.x;
#pragma unroll
    for (int j = threadIdx.y; j < 32; j += 8)
        ob[(size_t)(ro + j) * R + co] = t[threadIdx.x][j];
}

__global__ void __launch_bounds__(256)
colsum_kernel(const float* __restrict__ x, float* __restrict__ s) {
    const int e = blockIdx.x * 256 + threadIdx.x;
    const int b = blockIdx.y;
    const float* p = x + (size_t)b * N_ * D_ + e;
    float a0 = 0.f, a1 = 0.f, a2 = 0.f, a3 = 0.f;
    for (int n = 0; n < N_; n += 4) {
        a0 += p[(size_t)n * D_];
        a1 += p[(size_t)(n + 1) * D_];
        a2 += p[(size_t)(n + 2) * D_];
        a3 += p[(size_t)(n + 3) * D_];
    }
    s[b * D_ + e] = (a0 + a1) + (a2 + a3);
}

__global__ void __launch_bounds__(256)
rsum_kernel(const float* __restrict__ attn, const float* __restrict__ bv,
            float* __restrict__ r) {
    const int f = blockIdx.x * 256 + threadIdx.x;
    const int b = blockIdx.y;
    const float* p = attn + (size_t)b * D_ * D_ + f;
    float a0 = 0.f, a1 = 0.f;
    for (int e = 0; e < D_; e += 2) {
        a0 += bv[e] * p[(size_t)e * D_];
        a1 += bv[e + 1] * p[(size_t)(e + 1) * D_];
    }
    r[b * D_ + f] = a0 + a1;
}

__global__ void __launch_bounds__(256)
gemv_kernel(const float* __restrict__ Wq, const float* __restrict__ Wk,
            const float* __restrict__ bk, const float* __restrict__ s,
            float* __restrict__ u, float* __restrict__ w) {
    const int wg = blockIdx.x * 8 + (threadIdx.x >> 5);
    const int lane = threadIdx.x & 31;
    const int b = wg >> 11;
    const int o = wg & 2047;
    const bool is_u = o < 1024;
    const int row = is_u ? o : o - 1024;
    const float* W = (is_u ? Wq : Wk) + (size_t)row * D_;
    const float* sb = s + b * D_;
    float acc = 0.f;
#pragma unroll
    for (int i = 0; i < 32; ++i) acc += W[lane + (i << 5)] * sb[lane + (i << 5)];
#pragma unroll
    for (int off = 16; off; off >>= 1)
        acc += __shfl_xor_sync(0xffffffffu, acc, off);
    if (lane == 0) {
        if (is_u) u[b * D_ + row] = acc;
        else      w[b * D_ + row] = acc + (float)N_ * bk[row];
    }
}

__global__ void __launch_bounds__(256)
softmax_fused(float* __restrict__ L, const float* __restrict__ u,
              const float* __restrict__ w, const float* __restrict__ bq,
              const float* __restrict__ bk) {
    const int row = blockIdx.x;
    const int b = row >> 10, e = row & 1023;
    float* p = L + (size_t)row * 1024;
    const float uu = u[b * D_ + e];
    const float bb = bq[e];
    const float* wb = w + b * D_;
    const int t = threadIdx.x;
    const int lane = t & 31, wid = t >> 5;
    __shared__ float red[8];

    float v[4];
#pragma unroll
    for (int i = 0; i < 4; ++i) {
        const int f = t + (i << 8);
        v[i] = p[f] + uu * bk[f] + bb * wb[f];
    }
    float m = fmaxf(fmaxf(v[0], v[1]), fmaxf(v[2], v[3]));
#pragma unroll
    for (int o = 16; o; o >>= 1) m = fmaxf(m, __shfl_xor_sync(0xffffffffu, m, o));
    if (lane == 0) red[wid] = m;
    __syncthreads();
    if (t < 32) {
        float x = (t < 8) ? red[t] : -3.4e38f;
#pragma unroll
        for (int o = 4; o; o >>= 1) x = fmaxf(x, __shfl_xor_sync(0xffffffffu, x, o));
        if (t == 0) red[0] = x;
    }
    __syncthreads();
    m = red[0];
    __syncthreads();
    float ssum = 0.f;
#pragma unroll
    for (int i = 0; i < 4; ++i) {
        v[i] = expf(v[i] - m);
        ssum += v[i];
    }
#pragma unroll
    for (int o = 16; o; o >>= 1) ssum += __shfl_xor_sync(0xffffffffu, ssum, o);
    if (lane == 0) red[wid] = ssum;
    __syncthreads();
    if (t < 32) {
        float x = (t < 8) ? red[t] : 0.f;
#pragma unroll
        for (int o = 4; o; o >>= 1) x += __shfl_xor_sync(0xffffffffu, x, o);
        if (t == 0) red[0] = x;
    }
    __syncthreads();
    const float inv = 1.0f / red[0];
#pragma unroll
    for (int i = 0; i < 4; ++i) p[t + (i << 8)] = v[i] * inv;
}

extern "C" void kernel_launch(void* const* d_in, const int* in_sizes, int n_in,
                              void* d_out, int out_size) {
    const float* x  = (const float*)d_in[0];
    const float* Wq = (const float*)d_in[1];
    const float* bq = (const float*)d_in[2];
    const float* Wk = (const float*)d_in[3];
    const float* bk = (const float*)d_in[4];
    const float* Wv = (const float*)d_in[5];
    const float* bv = (const float*)d_in[6];
    float* out = (float*)d_out;

    float *xT, *G, *T1, *L, *aT, *W2, *WvT, *s, *u, *w, *r;
    cudaGetSymbolAddress((void**)&xT, g_xT);
    cudaGetSymbolAddress((void**)&G, g_G);
    cudaGetSymbolAddress((void**)&T1, g_T1);
    cudaGetSymbolAddress((void**)&L, g_L);
    cudaGetSymbolAddress((void**)&aT, g_aT);
    cudaGetSymbolAddress((void**)&W2, g_W2);
    cudaGetSymbolAddress((void**)&WvT, g_WvT);
    cudaGetSymbolAddress((void**)&s, g_s);
    cudaGetSymbolAddress((void**)&u, g_u);
    cudaGetSymbolAddress((void**)&w, g_w);
    cudaGetSymbolAddress((void**)&r, g_r);
    uint32_t *xTA, *xTB, *xA, *GB, *T1B, *W2B, *aTA, *WqA, *WkA, *WvB;
    cudaGetSymbolAddress((void**)&xTA, g_xTA);
    cudaGetSymbolAddress((void**)&xTB, g_xTB);
    cudaGetSymbolAddress((void**)&xA, g_xA);
    cudaGetSymbolAddress((void**)&GB, g_GB);
    cudaGetSymbolAddress((void**)&T1B, g_T1B);
    cudaGetSymbolAddress((void**)&W2B, g_W2B);
    cudaGetSymbolAddress((void**)&aTA, g_aTA);
    cudaGetSymbolAddress((void**)&WqA, g_WqA);
    cudaGetSymbolAddress((void**)&WkA, g_WkA);
    cudaGetSymbolAddress((void**)&WvB, g_WvB);

    constexpr int SMEM3 = 3 * (4096 + 4096) * 4;  // 98,304 B
    constexpr int SMEM2 = 3 * (2048 + 4096) * 4;  // 73,728 B
    cudaFuncSetAttribute(gemm_async<3, false, true>,
                         cudaFuncAttributeMaxDynamicSharedMemorySize, SMEM3);
    cudaFuncSetAttribute(gemm_async<3, false, false>,
                         cudaFuncAttributeMaxDynamicSharedMemorySize, SMEM3);
    cudaFuncSetAttribute(gemm_async<2, false, false>,
                         cudaFuncAttributeMaxDynamicSharedMemorySize, SMEM2);
    cudaFuncSetAttribute(gemm_async<2, true, false>,
                         cudaFuncAttributeMaxDynamicSharedMemorySize, SMEM2);

    const dim3 blk(256);

    // transposes + small precomputes
    transpose_kernel<<<dim3(32, 128, B_), dim3(32, 8)>>>(x, xT, N_, D_);
    transpose_kernel<<<dim3(32, 32, 1), dim3(32, 8)>>>(Wv, WvT, D_, D_);
    colsum_kernel<<<dim3(4, 8), 256>>>(x, s);
    gemv_kernel<<<2048, 256>>>(Wq, Wk, bk, s, u, w);

    // pre-split input-side operands
    conv_kernel<true, true><<<dim3(8, 128, B_), blk>>>(
        xT, xTA, N_, (size_t)D_ * N_, 128);
    conv_kernel<false, true><<<dim3(8, 128, B_), blk>>>(
        xT, xTB, N_, (size_t)D_ * N_, 128);
    conv_kernel<true, true><<<dim3(8, 32, 1), blk>>>(Wk, WkA, D_, 0, 32);
    conv_kernel<true, true><<<dim3(8, 32, 1), blk>>>(Wq, WqA, D_, 0, 32);
    conv_kernel<false, true><<<dim3(8, 32, 1), blk>>>(WvT, WvB, D_, 0, 32);
    conv_kernel<true, false><<<dim3(256, 32, 1), blk>>>(x, xA, D_, 0, 32);

    // G[b] = xT[b] xT[b]^T  (sym, 3-split)
    gemm_async<3, false, true><<<dim3(8, 8, B_), blk, SMEM3>>>(
        xTA, xTB, nullptr, G, D_, 128,
        (size_t)8 * 128 * 4096, (size_t)8 * 128 * 4096, (size_t)D_ * D_, 0);
    conv_kernel<false, true><<<dim3(8, 32, B_), blk>>>(
        G, GB, D_, (size_t)D_ * D_, 32);

    // T1t[b] = Wk G[b]  (3-split)
    gemm_async<3, false, false><<<dim3(8, 8, B_), blk, SMEM3>>>(
        WkA, GB, nullptr, T1, D_, 32,
        0, (size_t)8 * 32 * 4096, (size_t)D_ * D_, 0);
    conv_kernel<false, true><<<dim3(8, 32, B_), blk>>>(
        T1, T1B, D_, (size_t)D_ * D_, 32);

    // L[b] = Wq T1t[b]^T  (3-split)
    gemm_async<3, false, false><<<dim3(8, 8, B_), blk, SMEM3>>>(
        WqA, T1B, nullptr, L, D_, 32,
        0, (size_t)8 * 32 * 4096, (size_t)D_ * D_, 0);

    // softmax with rank-1 corrections -> attn (in place)
    softmax_fused<<<B_ * D_, 256>>>(L, u, w, bq, bk);

    // attn^T, r, and their planes
    transpose_kernel<<<dim3(32, 32, B_), dim3(32, 8)>>>(L, aT, D_, D_);
    rsum_kernel<<<dim3(4, 8), 256>>>(L, bv, r);
    conv_kernel<true, false><<<dim3(8, 32, B_), blk>>>(
        aT, aTA, D_, (size_t)D_ * D_, 32);

    // W2t[b] = aT[b] WvT^T  (2-split)
    gemm_async<2, false, false><<<dim3(8, 8, B_), blk, SMEM2>>>(
        aTA, WvB, nullptr, W2, D_, 32,
        (size_t)8 * 32 * 2048, 0, (size_t)D_ * D_, 0);
    conv_kernel<false, true><<<dim3(8, 32, B_), blk>>>(
        W2, W2B, D_, (size_t)D_ * D_, 32);

    // out[b] = x[b] W2t[b]^T + r[b]  (2-split)
    gemm_async<2, true, false><<<dim3(8, 32, B_), blk, SMEM2>>>(
        xA, W2B, r, out, D_, 32,
        (size_t)32 * 32 * 2048, (size_t)8 * 32 * 4096,
        (size_t)N_ * D_, D_);
}

// round 14
// speedup vs baseline: 3.0986x; 1.0914x over previous
#include <cuda_runtime.h>
#include <cuda_fp16.h>
#include <cstdint>

#define B_   8
#define N_   4096
#define D_   1024

// ---------------------------------------------------------------------------
// fp32 scratch
// ---------------------------------------------------------------------------
__device__ float g_L  [(size_t)B_ * D_ * D_];   // logits -> attn
__device__ float g_aT [(size_t)B_ * D_ * D_];   // attn^T
__device__ float g_WvT[(size_t)D_ * D_];        // Wv^T
__device__ float g_s  [(size_t)B_ * D_];        // s = x^T 1
__device__ float g_u  [(size_t)B_ * D_];        // u = Wq s
__device__ float g_w  [(size_t)B_ * D_];        // w' = Wk s + N*bk
__device__ float g_r  [(size_t)B_ * D_];        // r = bv^T attn

// ---------------------------------------------------------------------------
// fp16 plane buffers (fragment-order GMEM; words = f16x2)
// block = one (128-row tile, 32-k stage): [hi 2048][lo 2048] (A-nolo: 2048)
// ---------------------------------------------------------------------------
__device__ uint32_t g_xTA[(size_t)8 * 8 * 128 * 4096];   // 134 MB
__device__ uint32_t g_xTB[(size_t)8 * 8 * 128 * 4096];   // 134 MB
__device__ uint32_t g_xA [(size_t)256 * 32 * 2048];      //  64 MB
__device__ uint32_t g_GB [(size_t)8 * 8 * 32 * 4096];    //  33 MB
__device__ uint32_t g_T1B[(size_t)8 * 8 * 32 * 4096];    //  33 MB
__device__ uint32_t g_W2B[(size_t)8 * 8 * 32 * 4096];    //  33 MB
__device__ uint32_t g_aTA[(size_t)8 * 8 * 32 * 2048];    //  17 MB
__device__ uint32_t g_WqA[(size_t)8 * 32 * 4096];        //   4 MB
__device__ uint32_t g_WkA[(size_t)8 * 32 * 4096];        //   4 MB
__device__ uint32_t g_WvB[(size_t)8 * 32 * 4096];        //   4 MB

__device__ __forceinline__ uint32_t smem_u32(const void* p) {
    uint32_t a;
    asm("{ .reg .u64 t; cvta.to.shared.u64 t, %1; cvt.u32.u64 %0, t; }"
        : "=r"(a) : "l"(p));
    return a;
}
__device__ __forceinline__ void cpa16(uint32_t saddr, const void* g) {
    asm volatile("cp.async.cg.shared.global [%0], [%1], 16;"
                 :: "r"(saddr), "l"(g));
}
__device__ __forceinline__ void mma16(float* c, const uint32_t* a,
                                      const uint32_t* b) {
    asm("mma.sync.aligned.m16n8k16.row.col.f32.f16.f16.f32 "
        "{%0,%1,%2,%3}, {%4,%5,%6,%7}, {%8,%9}, {%0,%1,%2,%3};"
        : "+f"(c[0]), "+f"(c[1]), "+f"(c[2]), "+f"(c[3])
        : "r"(a[0]), "r"(a[1]), "r"(a[2]), "r"(a[3]), "r"(b[0]), "r"(b[1]));
}
__device__ __forceinline__ void split_h(float x, uint16_t& h, uint16_t& l) {
    __half hh = __float2half_rn(x);
    float hf = __half2float(hh);
    h = __half_as_ushort(hh);
    l = __half_as_ushort(__float2half_rn(x - hf));
}
__device__ __forceinline__ uint32_t pack2h(uint16_t lo, uint16_t hi) {
    return (uint32_t)lo | ((uint32_t)hi << 16);
}

// ---------------------------------------------------------------------------
// fused split-transpose: x [b][n][e] -> xTA (A-role hi/lo) + xTB (B-role
// hi/lo) fragment planes of xT[b][e][n]. One read of x, no fp32 intermediate.
// grid (8 e-tiles, 128 n-kstages, B_), block 256.
// ---------------------------------------------------------------------------
__global__ void __launch_bounds__(256)
xsplit_kernel(const float* __restrict__ x, uint32_t* __restrict__ dA,
              uint32_t* __restrict__ dB) {
    __shared__ float st[32][132];  // [n_local][e_local]
    const int tid = threadIdx.x;
    const int e0 = blockIdx.x * 128, n0 = blockIdx.y * 32;
    const int bz = blockIdx.z;
    // load 32 n x 128 e tile (coalesced float4 along e)
#pragma unroll
    for (int it = 0; it < 4; ++it) {
        int idx = tid + (it << 8);
        int nl = idx >> 5, e4 = idx & 31;
        float4 v = *reinterpret_cast<const float4*>(
            x + ((size_t)bz * N_ + n0 + nl) * D_ + e0 + (e4 << 2));
        *reinterpret_cast<float4*>(&st[nl][e4 << 2]) = v;
    }
    __syncthreads();
    const size_t blk = ((size_t)bz * 8 + blockIdx.x) * 128 + blockIdx.y;
    uint32_t* dbA = dA + blk * 4096;
    uint32_t* dbB = dB + blk * 4096;
#pragma unroll
    for (int it = 0; it < 4; ++it) {
        int idx = tid + (it << 8);
        int mm = idx >> 3, k4 = idx & 7, k0 = k4 << 2;
        float va[4];
#pragma unroll
        for (int c = 0; c < 4; ++c) va[c] = st[k0 + c][mm];
        uint16_t h[4], l[4];
#pragma unroll
        for (int c = 0; c < 4; ++c) split_h(va[c], h[c], l[c]);
        int ks = k0 >> 4, kk = k0 & 15;
        {   // A-role
            int rr = mm & 15, mt = mm >> 4;
            int reg = (rr >> 3) + ((kk >> 3) << 1);
            int o = ks * 1024 + mt * 128 +
                    (((rr & 7) << 2) + ((kk & 7) >> 1)) * 4 + reg;
            dbA[o] = pack2h(h[0], h[1]);
            dbA[o + 4] = pack2h(h[2], h[3]);
            dbA[2048 + o] = pack2h(l[0], l[1]);
            dbA[2048 + o + 4] = pack2h(l[2], l[3]);
        }
        {   // B-role
            int nt = mm >> 3, reg = kk >> 3;
            int o = ks * 1024 + nt * 64 +
                    (((mm & 7) << 2) + ((kk & 7) >> 1)) * 2 + reg;
            dbB[o] = pack2h(h[0], h[1]);
            dbB[o + 2] = pack2h(h[2], h[3]);
            dbB[2048 + o] = pack2h(l[0], l[1]);
            dbB[2048 + o + 2] = pack2h(l[2], l[3]);
        }
    }
}

// ---------------------------------------------------------------------------
// converter (kept for weight/natural operands): fp32 [rows,K] -> planes
// ---------------------------------------------------------------------------
template <bool ROLE_A, bool WITH_LO>
__global__ void __launch_bounds__(256)
conv_kernel(const float* __restrict__ src, uint32_t* __restrict__ dst,
            int ld, size_t srcBatch, int nkst) {
    const int tid = threadIdx.x;
    const int tileR = blockIdx.x, kst = blockIdx.y, bz = blockIdx.z;
    constexpr int WORDS = ROLE_A ? (WITH_LO ? 4096 : 2048) : 4096;
    const float* sb =
        src + (size_t)bz * srcBatch + (size_t)tileR * 128 * ld + kst * 32;
    uint32_t* db =
        dst + (((size_t)bz * gridDim.x + tileR) * nkst + kst) * WORDS;
#pragma unroll
    for (int it = 0; it < 4; ++it) {
        int idx = tid + (it << 8);
        int mm = idx >> 3, k4 = idx & 7;
        float4 v = *reinterpret_cast<const float4*>(sb + (size_t)mm * ld +
                                                    (k4 << 2));
        float va[4] = {v.x, v.y, v.z, v.w};
        uint16_t h[4], l[4];
#pragma unroll
        for (int c = 0; c < 4; ++c) {
            if (WITH_LO) split_h(va[c], h[c], l[c]);
            else h[c] = __half_as_ushort(__float2half_rn(va[c]));
        }
        int k0 = k4 << 2, ks = k0 >> 4, kk = k0 & 15;
        if (ROLE_A) {
            int rr = mm & 15, mt = mm >> 4;
            int reg = (rr >> 3) + ((kk >> 3) << 1);
            int o = ks * 1024 + mt * 128 +
                    (((rr & 7) << 2) + ((kk & 7) >> 1)) * 4 + reg;
            db[o] = pack2h(h[0], h[1]);
            db[o + 4] = pack2h(h[2], h[3]);
            if (WITH_LO) {
                db[2048 + o] = pack2h(l[0], l[1]);
                db[2048 + o + 4] = pack2h(l[2], l[3]);
            }
        } else {
            int nt = mm >> 3, reg = kk >> 3;
            int o = ks * 1024 + nt * 64 +
                    (((mm & 7) << 2) + ((kk & 7) >> 1)) * 2 + reg;
            db[o] = pack2h(h[0], h[1]);
            db[o + 2] = pack2h(h[2], h[3]);
            db[2048 + o] = pack2h(l[0], l[1]);
            db[2048 + o + 2] = pack2h(l[2], l[3]);
        }
    }
}

// ---------------------------------------------------------------------------
// async GEMM from pre-split planes. cp.async 3-stage; LDS+MMA mainloop.
// PLANES: epilogue writes B-role fp16 hi/lo planes (element n=row, k=col)
// into Cp directly (no fp32 C, no converter). SYM+PLANES mirror: u16 scatter.
// ---------------------------------------------------------------------------
template <int SPLITS, bool HAS_BIAS, bool SYM, bool PLANES>
__global__ void __launch_bounds__(256, 2)
gemm_async(const uint32_t* __restrict__ Ap, const uint32_t* __restrict__ Bp,
           const float* __restrict__ bias, float* __restrict__ C,
           uint32_t* __restrict__ Cp,
           int Nn, int nkst, size_t aBatch, size_t bBatch, size_t cB,
           size_t biasB) {
    if (SYM && blockIdx.y < blockIdx.x) return;
    extern __shared__ uint32_t smw[];
    const uint32_t sbase = smem_u32(smw);
    constexpr int AW = (SPLITS == 3) ? 4096 : 2048;
    constexpr int SW = AW + 4096;
    constexpr int NCHUNK = SW / 4 / 256;
    const int tid = threadIdx.x;
    const int lane = tid & 31, wid = tid >> 5;
    const int wm = wid & 1, wn = wid >> 1;
    const uint32_t* Abase =
        Ap + blockIdx.z * aBatch + (size_t)blockIdx.y * nkst * AW;
    const uint32_t* Bbase =
        Bp + blockIdx.z * bBatch + (size_t)blockIdx.x * nkst * 4096;
    const float* biasb = HAS_BIAS ? bias + blockIdx.z * biasB : nullptr;

    float acc[4][4][4];
#pragma unroll
    for (int i = 0; i < 4; ++i)
#pragma unroll
        for (int j = 0; j < 4; ++j)
#pragma unroll
            for (int e = 0; e < 4; ++e) acc[i][j][e] = 0.f;

    auto issue = [&](int t, int buf) {
        const uint32_t* As = Abase + (size_t)t * AW;
        const uint32_t* Bs = Bbase + (size_t)t * 4096;
        const uint32_t sb = sbase + (uint32_t)(buf * SW) * 4u;
#pragma unroll
        for (int c = 0; c < NCHUNK; ++c) {
            int id = tid + (c << 8);
            if (id < AW / 4) cpa16(sb + id * 16, As + id * 4);
            else cpa16(sb + id * 16, Bs + (size_t)(id - AW / 4) * 4);
        }
    };
    auto compute = [&](int buf) {
        const uint32_t* S = smw + buf * SW;
        const uint32_t* Ah = S;
        const uint32_t* Al = S + 2048;
        const uint32_t* Bh = S + AW;
        const uint32_t* Bl = S + AW + 2048;
#pragma unroll
        for (int ks = 0; ks < 2; ++ks) {
            uint32_t bh[4][2], bl[4][2];
#pragma unroll
            for (int j = 0; j < 4; ++j) {
                const int o = ks * 1024 + ((wn << 2) + j) * 64 + (lane << 1);
                *reinterpret_cast<uint2*>(bh[j]) =
                    *reinterpret_cast<const uint2*>(Bh + o);
                *reinterpret_cast<uint2*>(bl[j]) =
                    *reinterpret_cast<const uint2*>(Bl + o);
            }
#pragma unroll
            for (int i = 0; i < 4; ++i) {
                uint32_t ah[4], al[4];
                const int o = ks * 1024 + ((wm << 2) + i) * 128 + (lane << 2);
                *reinterpret_cast<uint4*>(ah) =
                    *reinterpret_cast<const uint4*>(Ah + o);
                if (SPLITS == 3)
                    *reinterpret_cast<uint4*>(al) =
                        *reinterpret_cast<const uint4*>(Al + o);
#pragma unroll
                for (int j = 0; j < 4; ++j) {
                    mma16(acc[i][j], ah, bh[j]);
                    mma16(acc[i][j], ah, bl[j]);
                    if (SPLITS == 3) mma16(acc[i][j], al, bh[j]);
                }
            }
        }
    };

    issue(0, 0);
    asm volatile("cp.async.commit_group;" ::: "memory");
    issue(1, 1);
    asm volatile("cp.async.commit_group;" ::: "memory");
    for (int t = 0; t < nkst; ++t) {
        if (t + 1 < nkst)
            asm volatile("cp.async.wait_group 1;" ::: "memory");
        else
            asm volatile("cp.async.wait_group 0;" ::: "memory");
        __syncthreads();
        if (t + 2 < nkst) {
            issue(t + 2, (t + 2) % 3);
            asm volatile("cp.async.commit_group;" ::: "memory");
        }
        compute(t % 3);
    }

    const int r = lane >> 2, cq = (lane & 3) << 1;
    const int m0 = blockIdx.y * 128, n0 = blockIdx.x * 128;
    const bool mirror = SYM && (blockIdx.y != blockIdx.x);
    if (PLANES) {
        const int NKSTD = Nn >> 5;
        uint32_t* Pb =
            Cp + (size_t)blockIdx.z * gridDim.y * NKSTD * 4096;
#pragma unroll
        for (int i = 0; i < 4; ++i) {
#pragma unroll
            for (int j = 0; j < 4; ++j) {
                const int row0 = m0 + (wm << 6) + (i << 4) + r;
                const int col = n0 + (wn << 5) + (j << 3) + cq;
                uint16_t h[4], l[4];
#pragma unroll
                for (int e = 0; e < 4; ++e) split_h(acc[i][j][e], h[e], l[e]);
                // normal: element (n=row, k=col)
                uint32_t* blk =
                    Pb + ((size_t)(row0 >> 7) * NKSTD + (col >> 5)) * 4096;
                const int kk = col & 15;
                const int nl = row0 & 127;
                const int wo = ((col >> 4) & 1) * 1024 + (nl >> 3) * 64 +
                               (((nl & 7) << 2) + ((kk & 7) >> 1)) * 2 +
                               ((kk >> 3) & 1);
                blk[wo] = pack2h(h[0], h[1]);
                blk[2048 + wo] = pack2h(l[0], l[1]);
                blk[wo + 64] = pack2h(h[2], h[3]);
                blk[2048 + wo + 64] = pack2h(l[2], l[3]);
                if (mirror) {  // element (n=col', k=row')
                    const int rws[4] = {row0, row0, row0 + 8, row0 + 8};
                    const int cls[4] = {col, col + 1, col, col + 1};
#pragma unroll
                    for (int e = 0; e < 4; ++e) {
                        const int rw = rws[e], cl = cls[e];
                        uint32_t* mb =
                            Pb + ((size_t)(cl >> 7) * NKSTD + (rw >> 5)) * 4096;
                        const int kkm = rw & 15, nlm = cl & 127;
                        const int wm2 = ((rw >> 4) & 1) * 1024 +
                                        (nlm >> 3) * 64 +
                                        (((nlm & 7) << 2) + ((kkm & 7) >> 1)) *
                                            2 +
                                        ((kkm >> 3) & 1);
                        reinterpret_cast<uint16_t*>(mb)[2 * wm2 + (rw & 1)] =
                            h[e];
                        reinterpret_cast<uint16_t*>(mb)[2 * (2048 + wm2) +
                                                        (rw & 1)] = l[e];
                    }
                }
            }
        }
    } else {
        float* Cb = C + (size_t)blockIdx.z * cB;
#pragma unroll
        for (int i = 0; i < 4; ++i) {
#pragma unroll
            for (int j = 0; j < 4; ++j) {
                const int row = m0 + (wm << 6) + (i << 4) + r;
                const int col = n0 + (wn << 5) + (j << 3) + cq;
                float o0 = acc[i][j][0], o1 = acc[i][j][1];
                float o2 = acc[i][j][2], o3 = acc[i][j][3];
                if (HAS_BIAS) {
                    float b0 = biasb[col], b1 = biasb[col + 1];
                    o0 += b0; o1 += b1; o2 += b0; o3 += b1;
                }
                *reinterpret_cast<float2*>(Cb + (size_t)row * Nn + col) =
                    make_float2(o0, o1);
                *reinterpret_cast<float2*>(Cb + (size_t)(row + 8) * Nn + col) =
                    make_float2(o2, o3);
            }
        }
    }
}

// ---------------------------------------------------------------------------
// helpers
// ---------------------------------------------------------------------------
__global__ void __launch_bounds__(256)
transpose_kernel(const float* __restrict__ in, float* __restrict__ out,
                 int R, int Cc) {
    __shared__ float t[32][33];
    const float* ib = in + (size_t)blockIdx.z * R * Cc;
    float* ob = out + (size_t)blockIdx.z * R * Cc;
    const int c = blockIdx.x * 32 + threadIdx.x;
    const int r0 = blockIdx.y * 32;
#pragma unroll
    for (int j = threadIdx.y; j < 32; j += 8)
        t[j][threadIdx.x] = ib[(size_t)(r0 + j) * Cc + c];
    __syncthreads();
    const int ro = blockIdx.x * 32;
    const int co = r0 + threadIdx.x;
#pragma unroll
    for (int j = threadIdx.y; j < 32; j += 8)
        ob[(size_t)(ro + j) * R + co] = t[threadIdx.x][j];
}

__global__ void __launch_bounds__(256)
colsum_kernel(const float* __restrict__ x, float* __restrict__ s) {
    const int e = blockIdx.x * 256 + threadIdx.x;
    const int b = blockIdx.y;
    const float* p = x + (size_t)b * N_ * D_ + e;
    float a0 = 0.f, a1 = 0.f, a2 = 0.f, a3 = 0.f;
    for (int n = 0; n < N_; n += 4) {
        a0 += p[(size_t)n * D_];
        a1 += p[(size_t)(n + 1) * D_];
        a2 += p[(size_t)(n + 2) * D_];
        a3 += p[(size_t)(n + 3) * D_];
    }
    s[b * D_ + e] = (a0 + a1) + (a2 + a3);
}

__global__ void __launch_bounds__(256)
rsum_kernel(const float* __restrict__ attn, const float* __restrict__ bv,
            float* __restrict__ r) {
    const int f = blockIdx.x * 256 + threadIdx.x;
    const int b = blockIdx.y;
    const float* p = attn + (size_t)b * D_ * D_ + f;
    float a0 = 0.f, a1 = 0.f;
    for (int e = 0; e < D_; e += 2) {
        a0 += bv[e] * p[(size_t)e * D_];
        a1 += bv[e + 1] * p[(size_t)(e + 1) * D_];
    }
    r[b * D_ + f] = a0 + a1;
}

__global__ void __launch_bounds__(256)
gemv_kernel(const float* __restrict__ Wq, const float* __restrict__ Wk,
            const float* __restrict__ bk, const float* __restrict__ s,
            float* __restrict__ u, float* __restrict__ w) {
    const int wg = blockIdx.x * 8 + (threadIdx.x >> 5);
    const int lane = threadIdx.x & 31;
    const int b = wg >> 11;
    const int o = wg & 2047;
    const bool is_u = o < 1024;
    const int row = is_u ? o : o - 1024;
    const float* W = (is_u ? Wq : Wk) + (size_t)row * D_;
    const float* sb = s + b * D_;
    float acc = 0.f;
#pragma unroll
    for (int i = 0; i < 32; ++i) acc += W[lane + (i << 5)] * sb[lane + (i << 5)];
#pragma unroll
    for (int off = 16; off; off >>= 1)
        acc += __shfl_xor_sync(0xffffffffu, acc, off);
    if (lane == 0) {
        if (is_u) u[b * D_ + row] = acc;
        else      w[b * D_ + row] = acc + (float)N_ * bk[row];
    }
}

__global__ void __launch_bounds__(256)
softmax_fused(float* __restrict__ L, const float* __restrict__ u,
              const float* __restrict__ w, const float* __restrict__ bq,
              const float* __restrict__ bk) {
    const int row = blockIdx.x;
    const int b = row >> 10, e = row & 1023;
    float* p = L + (size_t)row * 1024;
    const float uu = u[b * D_ + e];
    const float bb = bq[e];
    const float* wb = w + b * D_;
    const int t = threadIdx.x;
    const int lane = t & 31, wid = t >> 5;
    __shared__ float red[8];

    float v[4];
#pragma unroll
    for (int i = 0; i < 4; ++i) {
        const int f = t + (i << 8);
        v[i] = p[f] + uu * bk[f] + bb * wb[f];
    }
    float m = fmaxf(fmaxf(v[0], v[1]), fmaxf(v[2], v[3]));
#pragma unroll
    for (int o = 16; o; o >>= 1) m = fmaxf(m, __shfl_xor_sync(0xffffffffu, m, o));
    if (lane == 0) red[wid] = m;
    __syncthreads();
    if (t < 32) {
        float x = (t < 8) ? red[t] : -3.4e38f;
#pragma unroll
        for (int o = 4; o; o >>= 1) x = fmaxf(x, __shfl_xor_sync(0xffffffffu, x, o));
        if (t == 0) red[0] = x;
    }
    __syncthreads();
    m = red[0];
    __syncthreads();
    float ssum = 0.f;
#pragma unroll
    for (int i = 0; i < 4; ++i) {
        v[i] = expf(v[i] - m);
        ssum += v[i];
    }
#pragma unroll
    for (int o = 16; o; o >>= 1) ssum += __shfl_xor_sync(0xffffffffu, ssum, o);
    if (lane == 0) red[wid] = ssum;
    __syncthreads();
    if (t < 32) {
        float x = (t < 8) ? red[t] : 0.f;
#pragma unroll
        for (int o = 4; o; o >>= 1) x += __shfl_xor_sync(0xffffffffu, x, o);
        if (t == 0) red[0] = x;
    }
    __syncthreads();
    const float inv = 1.0f / red[0];
#pragma unroll
    for (int i = 0; i < 4; ++i) p[t + (i << 8)] = v[i] * inv;
}

extern "C" void kernel_launch(void* const* d_in, const int* in_sizes, int n_in,
                              void* d_out, int out_size) {
    const float* x  = (const float*)d_in[0];
    const float* Wq = (const float*)d_in[1];
    const float* bq = (const float*)d_in[2];
    const float* Wk = (const float*)d_in[3];
    const float* bk = (const float*)d_in[4];
    const float* Wv = (const float*)d_in[5];
    const float* bv = (const float*)d_in[6];
    float* out = (float*)d_out;

    float *L, *aT, *WvT, *s, *u, *w, *r;
    cudaGetSymbolAddress((void**)&L, g_L);
    cudaGetSymbolAddress((void**)&aT, g_aT);
    cudaGetSymbolAddress((void**)&WvT, g_WvT);
    cudaGetSymbolAddress((void**)&s, g_s);
    cudaGetSymbolAddress((void**)&u, g_u);
    cudaGetSymbolAddress((void**)&w, g_w);
    cudaGetSymbolAddress((void**)&r, g_r);
    uint32_t *xTA, *xTB, *xA, *GB, *T1B, *W2B, *aTA, *WqA, *WkA, *WvB;
    cudaGetSymbolAddress((void**)&xTA, g_xTA);
    cudaGetSymbolAddress((void**)&xTB, g_xTB);
    cudaGetSymbolAddress((void**)&xA, g_xA);
    cudaGetSymbolAddress((void**)&GB, g_GB);
    cudaGetSymbolAddress((void**)&T1B, g_T1B);
    cudaGetSymbolAddress((void**)&W2B, g_W2B);
    cudaGetSymbolAddress((void**)&aTA, g_aTA);
    cudaGetSymbolAddress((void**)&WqA, g_WqA);
    cudaGetSymbolAddress((void**)&WkA, g_WkA);
    cudaGetSymbolAddress((void**)&WvB, g_WvB);

    constexpr int SMEM3 = 3 * (4096 + 4096) * 4;  // 98,304 B
    constexpr int SMEM2 = 3 * (2048 + 4096) * 4;  // 73,728 B
    cudaFuncSetAttribute(gemm_async<3, false, true, true>,
                         cudaFuncAttributeMaxDynamicSharedMemorySize, SMEM3);
    cudaFuncSetAttribute(gemm_async<3, false, false, true>,
                         cudaFuncAttributeMaxDynamicSharedMemorySize, SMEM3);
    cudaFuncSetAttribute(gemm_async<3, false, false, false>,
                         cudaFuncAttributeMaxDynamicSharedMemorySize, SMEM3);
    cudaFuncSetAttribute(gemm_async<2, false, false, true>,
                         cudaFuncAttributeMaxDynamicSharedMemorySize, SMEM2);
    cudaFuncSetAttribute(gemm_async<2, true, false, false>,
                         cudaFuncAttributeMaxDynamicSharedMemorySize, SMEM2);

    const dim3 blk(256);

    // fused split-transpose of x -> xTA/xTB planes (no fp32 xT)
    xsplit_kernel<<<dim3(8, 128, B_), blk>>>(x, xTA, xTB);

    // weight/natural-layout plane converters
    transpose_kernel<<<dim3(32, 32, 1), dim3(32, 8)>>>(Wv, WvT, D_, D_);
    conv_kernel<true, true><<<dim3(8, 32, 1), blk>>>(Wk, WkA, D_, 0, 32);
    conv_kernel<true, true><<<dim3(8, 32, 1), blk>>>(Wq, WqA, D_, 0, 32);
    conv_kernel<false, true><<<dim3(8, 32, 1), blk>>>(WvT, WvB, D_, 0, 32);
    conv_kernel<true, false><<<dim3(256, 32, 1), blk>>>(x, xA, D_, 0, 32);

    // small precomputes
    colsum_kernel<<<dim3(4, 8), 256>>>(x, s);
    gemv_kernel<<<2048, 256>>>(Wq, Wk, bk, s, u, w);

    // G[b] = xT xT^T  (sym, 3-split) -> GB planes directly
    gemm_async<3, false, true, true><<<dim3(8, 8, B_), blk, SMEM3>>>(
        xTA, xTB, nullptr, nullptr, GB, D_, 128,
        (size_t)8 * 128 * 4096, (size_t)8 * 128 * 4096, 0, 0);

    // T1t[b] = Wk G[b]  (3-split) -> T1B planes directly
    gemm_async<3, false, false, true><<<dim3(8, 8, B_), blk, SMEM3>>>(
        WkA, GB, nullptr, nullptr, T1B, D_, 32,
        0, (size_t)8 * 32 * 4096, 0, 0);

    // L[b] = Wq T1t[b]^T  (3-split, fp32 out for softmax)
    gemm_async<3, false, false, false><<<dim3(8, 8, B_), blk, SMEM3>>>(
        WqA, T1B, nullptr, L, nullptr, D_, 32,
        0, (size_t)8 * 32 * 4096, (size_t)D_ * D_, 0);

    // softmax with rank-1 corrections -> attn (in place)
    softmax_fused<<<B_ * D_, 256>>>(L, u, w, bq, bk);

    // attn^T + r + aTA planes
    transpose_kernel<<<dim3(32, 32, B_), dim3(32, 8)>>>(L, aT, D_, D_);
    rsum_kernel<<<dim3(4, 8), 256>>>(L, bv, r);
    conv_kernel<true, false><<<dim3(8, 32, B_), blk>>>(
        aT, aTA, D_, (size_t)D_ * D_, 32);

    // W2t[b] = aT[b] WvT^T  (2-split) -> W2B planes directly
    gemm_async<2, false, false, true><<<dim3(8, 8, B_), blk, SMEM2>>>(
        aTA, WvB, nullptr, nullptr, W2B, D_, 32,
        (size_t)8 * 32 * 2048, 0, 0, 0);

    // out[b] = x[b] W2t[b]^T + r[b]  (2-split, fp32 out)
    gemm_async<2, true, false, false><<<dim3(8, 32, B_), blk, SMEM2>>>(
        xA, W2B, r, out, nullptr, D_, 32,
        (size_t)32 * 32 * 2048, (size_t)8 * 32 * 4096,
        (size_t)N_ * D_, D_);
}

// round 15
// speedup vs baseline: 3.6229x; 1.1692x over previous
#include <cuda_runtime.h>
#include <cuda_fp16.h>
#include <cstdint>

#define B_   8
#define N_   4096
#define D_   1024

// ---------------------------------------------------------------------------
// fp32 scratch
// ---------------------------------------------------------------------------
__device__ float g_L  [(size_t)B_ * D_ * D_];   // logits -> attn
__device__ float g_WvT[(size_t)D_ * D_];        // Wv^T
__device__ float g_s  [(size_t)B_ * D_];        // s = x^T 1
__device__ float g_u  [(size_t)B_ * D_];        // u = Wq s
__device__ float g_w  [(size_t)B_ * D_];        // w' = Wk s + N*bk
__device__ float g_r  [(size_t)B_ * D_];        // r = bv^T attn

// ---------------------------------------------------------------------------
// fp16 plane buffers (fragment-order GMEM; words = f16x2)
// hi/lo block = 4096 words; hi-only block = 2048 words
// ---------------------------------------------------------------------------
__device__ uint32_t g_xTA[(size_t)8 * 8 * 128 * 4096];   // 134 MB (hi/lo A)
__device__ uint32_t g_xTB[(size_t)8 * 8 * 128 * 4096];   // 134 MB (hi/lo B)
__device__ uint32_t g_xA [(size_t)256 * 32 * 2048];      //  64 MB (hi A)
__device__ uint32_t g_GB [(size_t)8 * 8 * 32 * 4096];    //  33 MB (hi/lo B)
__device__ uint32_t g_T1B[(size_t)8 * 8 * 32 * 4096];    //  33 MB (hi/lo B)
__device__ uint32_t g_W2B[(size_t)8 * 8 * 32 * 2048];    //  17 MB (hi B)
__device__ uint32_t g_aTA[(size_t)8 * 8 * 32 * 2048];    //  17 MB (hi A)
__device__ uint32_t g_WqA[(size_t)8 * 32 * 4096];        //   4 MB (hi/lo A)
__device__ uint32_t g_WkA[(size_t)8 * 32 * 4096];        //   4 MB (hi/lo A)
__device__ uint32_t g_WvB[(size_t)8 * 32 * 2048];        //   2 MB (hi B)

__device__ __forceinline__ uint32_t smem_u32(const void* p) {
    uint32_t a;
    asm("{ .reg .u64 t; cvta.to.shared.u64 t, %1; cvt.u32.u64 %0, t; }"
        : "=r"(a) : "l"(p));
    return a;
}
__device__ __forceinline__ void cpa16(uint32_t saddr, const void* g) {
    asm volatile("cp.async.cg.shared.global [%0], [%1], 16;"
                 :: "r"(saddr), "l"(g));
}
__device__ __forceinline__ void mma16(float* c, const uint32_t* a,
                                      const uint32_t* b) {
    asm("mma.sync.aligned.m16n8k16.row.col.f32.f16.f16.f32 "
        "{%0,%1,%2,%3}, {%4,%5,%6,%7}, {%8,%9}, {%0,%1,%2,%3};"
        : "+f"(c[0]), "+f"(c[1]), "+f"(c[2]), "+f"(c[3])
        : "r"(a[0]), "r"(a[1]), "r"(a[2]), "r"(a[3]), "r"(b[0]), "r"(b[1]));
}
__device__ __forceinline__ void split_h(float x, uint16_t& h, uint16_t& l) {
    __half hh = __float2half_rn(x);
    float hf = __half2float(hh);
    h = __half_as_ushort(hh);
    l = __half_as_ushort(__float2half_rn(x - hf));
}
__device__ __forceinline__ uint32_t pack2h(uint16_t lo, uint16_t hi) {
    return (uint32_t)lo | ((uint32_t)hi << 16);
}

// ---------------------------------------------------------------------------
// fused split-transpose: x [b][n][e] -> xTA (A-role hi/lo) + xTB (B-role
// hi/lo) fragment planes of xT[b][e][n].
// ---------------------------------------------------------------------------
__global__ void __launch_bounds__(256)
xsplit_kernel(const float* __restrict__ x, uint32_t* __restrict__ dA,
              uint32_t* __restrict__ dB) {
    __shared__ float st[32][132];
    const int tid = threadIdx.x;
    const int e0 = blockIdx.x * 128, n0 = blockIdx.y * 32;
    const int bz = blockIdx.z;
#pragma unroll
    for (int it = 0; it < 4; ++it) {
        int idx = tid + (it << 8);
        int nl = idx >> 5, e4 = idx & 31;
        float4 v = *reinterpret_cast<const float4*>(
            x + ((size_t)bz * N_ + n0 + nl) * D_ + e0 + (e4 << 2));
        *reinterpret_cast<float4*>(&st[nl][e4 << 2]) = v;
    }
    __syncthreads();
    const size_t blk = ((size_t)bz * 8 + blockIdx.x) * 128 + blockIdx.y;
    uint32_t* dbA = dA + blk * 4096;
    uint32_t* dbB = dB + blk * 4096;
#pragma unroll
    for (int it = 0; it < 4; ++it) {
        int idx = tid + (it << 8);
        int mm = idx >> 3, k4 = idx & 7, k0 = k4 << 2;
        float va[4];
#pragma unroll
        for (int c = 0; c < 4; ++c) va[c] = st[k0 + c][mm];
        uint16_t h[4], l[4];
#pragma unroll
        for (int c = 0; c < 4; ++c) split_h(va[c], h[c], l[c]);
        int ks = k0 >> 4, kk = k0 & 15;
        {   // A-role
            int rr = mm & 15, mt = mm >> 4;
            int reg = (rr >> 3) + ((kk >> 3) << 1);
            int o = ks * 1024 + mt * 128 +
                    (((rr & 7) << 2) + ((kk & 7) >> 1)) * 4 + reg;
            dbA[o] = pack2h(h[0], h[1]);
            dbA[o + 4] = pack2h(h[2], h[3]);
            dbA[2048 + o] = pack2h(l[0], l[1]);
            dbA[2048 + o + 4] = pack2h(l[2], l[3]);
        }
        {   // B-role
            int nt = mm >> 3, reg = kk >> 3;
            int o = ks * 1024 + nt * 64 +
                    (((mm & 7) << 2) + ((kk & 7) >> 1)) * 2 + reg;
            dbB[o] = pack2h(h[0], h[1]);
            dbB[o + 2] = pack2h(h[2], h[3]);
            dbB[2048 + o] = pack2h(l[0], l[1]);
            dbB[2048 + o + 2] = pack2h(l[2], l[3]);
        }
    }
}

// ---------------------------------------------------------------------------
// fused transpose+round: attn [b][e][f] -> aTA = A-role hi-only planes of
// attn^T (rows f, k = e). Deletes fp32 aT + converter round trip.
// grid (8 f-tiles, 32 e-kstages, B_)
// ---------------------------------------------------------------------------
__global__ void __launch_bounds__(256)
atsplit_kernel(const float* __restrict__ attn, uint32_t* __restrict__ dA) {
    __shared__ float st[32][132];  // [e_local][f_local]
    const int tid = threadIdx.x;
    const int f0 = blockIdx.x * 128, e0 = blockIdx.y * 32;
    const int bz = blockIdx.z;
#pragma unroll
    for (int it = 0; it < 4; ++it) {
        int idx = tid + (it << 8);
        int el = idx >> 5, f4 = idx & 31;
        float4 v = *reinterpret_cast<const float4*>(
            attn + ((size_t)bz * D_ + e0 + el) * D_ + f0 + (f4 << 2));
        *reinterpret_cast<float4*>(&st[el][f4 << 2]) = v;
    }
    __syncthreads();
    const size_t blk = ((size_t)bz * 8 + blockIdx.x) * 32 + blockIdx.y;
    uint32_t* db = dA + blk * 2048;
#pragma unroll
    for (int it = 0; it < 4; ++it) {
        int idx = tid + (it << 8);
        int mm = idx >> 3, k4 = idx & 7, k0 = k4 << 2;
        uint16_t h[4];
#pragma unroll
        for (int c = 0; c < 4; ++c)
            h[c] = __half_as_ushort(__float2half_rn(st[k0 + c][mm]));
        int ks = k0 >> 4, kk = k0 & 15;
        int rr = mm & 15, mt = mm >> 4;
        int reg = (rr >> 3) + ((kk >> 3) << 1);
        int o = ks * 1024 + mt * 128 +
                (((rr & 7) << 2) + ((kk & 7) >> 1)) * 4 + reg;
        db[o] = pack2h(h[0], h[1]);
        db[o + 4] = pack2h(h[2], h[3]);
    }
}

// ---------------------------------------------------------------------------
// converter: fp32 [rows,K] -> planes. ROLE_A/B layouts, optional lo plane.
// ---------------------------------------------------------------------------
template <bool ROLE_A, bool WITH_LO>
__global__ void __launch_bounds__(256)
conv_kernel(const float* __restrict__ src, uint32_t* __restrict__ dst,
            int ld, size_t srcBatch, int nkst) {
    const int tid = threadIdx.x;
    const int tileR = blockIdx.x, kst = blockIdx.y, bz = blockIdx.z;
    constexpr int WORDS = WITH_LO ? 4096 : 2048;
    const float* sb =
        src + (size_t)bz * srcBatch + (size_t)tileR * 128 * ld + kst * 32;
    uint32_t* db =
        dst + (((size_t)bz * gridDim.x + tileR) * nkst + kst) * WORDS;
#pragma unroll
    for (int it = 0; it < 4; ++it) {
        int idx = tid + (it << 8);
        int mm = idx >> 3, k4 = idx & 7;
        float4 v = *reinterpret_cast<const float4*>(sb + (size_t)mm * ld +
                                                    (k4 << 2));
        float va[4] = {v.x, v.y, v.z, v.w};
        uint16_t h[4], l[4];
#pragma unroll
        for (int c = 0; c < 4; ++c) {
            if (WITH_LO) split_h(va[c], h[c], l[c]);
            else h[c] = __half_as_ushort(__float2half_rn(va[c]));
        }
        int k0 = k4 << 2, ks = k0 >> 4, kk = k0 & 15;
        if (ROLE_A) {
            int rr = mm & 15, mt = mm >> 4;
            int reg = (rr >> 3) + ((kk >> 3) << 1);
            int o = ks * 1024 + mt * 128 +
                    (((rr & 7) << 2) + ((kk & 7) >> 1)) * 4 + reg;
            db[o] = pack2h(h[0], h[1]);
            db[o + 4] = pack2h(h[2], h[3]);
            if (WITH_LO) {
                db[2048 + o] = pack2h(l[0], l[1]);
                db[2048 + o + 4] = pack2h(l[2], l[3]);
            }
        } else {
            int nt = mm >> 3, reg = kk >> 3;
            int o = ks * 1024 + nt * 64 +
                    (((mm & 7) << 2) + ((kk & 7) >> 1)) * 2 + reg;
            db[o] = pack2h(h[0], h[1]);
            db[o + 2] = pack2h(h[2], h[3]);
            if (WITH_LO) {
                db[2048 + o] = pack2h(l[0], l[1]);
                db[2048 + o + 2] = pack2h(l[2], l[3]);
            }
        }
    }
}

// ---------------------------------------------------------------------------
// async GEMM from pre-split planes. cp.async 3-stage; LDS+MMA mainloop.
// SPLITS=3: A hi/lo, B hi/lo, 3 products.  SPLITS=2: A hi, B hi/lo, 2.
// SPLITS=1: A hi, B hi, 1 product (pure fp16; exact fp32 accumulation).
// PLANES: epilogue writes B-role fp16 planes into Cp (PLO: also lo plane).
// ---------------------------------------------------------------------------
template <int SPLITS, bool HAS_BIAS, bool SYM, bool PLANES, bool PLO>
__global__ void __launch_bounds__(256, 2)
gemm_async(const uint32_t* __restrict__ Ap, const uint32_t* __restrict__ Bp,
           const float* __restrict__ bias, float* __restrict__ C,
           uint32_t* __restrict__ Cp,
           int Nn, int nkst, size_t aBatch, size_t bBatch, size_t cB,
           size_t biasB) {
    if (SYM && blockIdx.y < blockIdx.x) return;
    extern __shared__ uint32_t smw[];
    const uint32_t sbase = smem_u32(smw);
    constexpr int AW = (SPLITS == 3) ? 4096 : 2048;
    constexpr int BW = (SPLITS >= 2) ? 4096 : 2048;
    constexpr int SW = AW + BW;
    constexpr int NCHUNK = SW / 4 / 256;
    const int tid = threadIdx.x;
    const int lane = tid & 31, wid = tid >> 5;
    const int wm = wid & 1, wn = wid >> 1;
    const uint32_t* Abase =
        Ap + blockIdx.z * aBatch + (size_t)blockIdx.y * nkst * AW;
    const uint32_t* Bbase =
        Bp + blockIdx.z * bBatch + (size_t)blockIdx.x * nkst * BW;
    const float* biasb = HAS_BIAS ? bias + blockIdx.z * biasB : nullptr;

    float acc[4][4][4];
#pragma unroll
    for (int i = 0; i < 4; ++i)
#pragma unroll
        for (int j = 0; j < 4; ++j)
#pragma unroll
            for (int e = 0; e < 4; ++e) acc[i][j][e] = 0.f;

    auto issue = [&](int t, int buf) {
        const uint32_t* As = Abase + (size_t)t * AW;
        const uint32_t* Bs = Bbase + (size_t)t * BW;
        const uint32_t sb = sbase + (uint32_t)(buf * SW) * 4u;
#pragma unroll
        for (int c = 0; c < NCHUNK; ++c) {
            int id = tid + (c << 8);
            if (id < AW / 4) cpa16(sb + id * 16, As + id * 4);
            else cpa16(sb + id * 16, Bs + (size_t)(id - AW / 4) * 4);
        }
    };
    auto compute = [&](int buf) {
        const uint32_t* S = smw + buf * SW;
        const uint32_t* Ah = S;
        const uint32_t* Al = S + 2048;
        const uint32_t* Bh = S + AW;
        const uint32_t* Bl = S + AW + 2048;
#pragma unroll
        for (int ks = 0; ks < 2; ++ks) {
            uint32_t bh[4][2], bl[4][2];
#pragma unroll
            for (int j = 0; j < 4; ++j) {
                const int o = ks * 1024 + ((wn << 2) + j) * 64 + (lane << 1);
                *reinterpret_cast<uint2*>(bh[j]) =
                    *reinterpret_cast<const uint2*>(Bh + o);
                if (SPLITS >= 2)
                    *reinterpret_cast<uint2*>(bl[j]) =
                        *reinterpret_cast<const uint2*>(Bl + o);
            }
#pragma unroll
            for (int i = 0; i < 4; ++i) {
                uint32_t ah[4], al[4];
                const int o = ks * 1024 + ((wm << 2) + i) * 128 + (lane << 2);
                *reinterpret_cast<uint4*>(ah) =
                    *reinterpret_cast<const uint4*>(Ah + o);
                if (SPLITS == 3)
                    *reinterpret_cast<uint4*>(al) =
                        *reinterpret_cast<const uint4*>(Al + o);
#pragma unroll
                for (int j = 0; j < 4; ++j) {
                    mma16(acc[i][j], ah, bh[j]);
                    if (SPLITS >= 2) mma16(acc[i][j], ah, bl[j]);
                    if (SPLITS == 3) mma16(acc[i][j], al, bh[j]);
                }
            }
        }
    };

    issue(0, 0);
    asm volatile("cp.async.commit_group;" ::: "memory");
    issue(1, 1);
    asm volatile("cp.async.commit_group;" ::: "memory");
    for (int t = 0; t < nkst; ++t) {
        if (t + 1 < nkst)
            asm volatile("cp.async.wait_group 1;" ::: "memory");
        else
            asm volatile("cp.async.wait_group 0;" ::: "memory");
        __syncthreads();
        if (t + 2 < nkst) {
            issue(t + 2, (t + 2) % 3);
            asm volatile("cp.async.commit_group;" ::: "memory");
        }
        compute(t % 3);
    }

    const int r = lane >> 2, cq = (lane & 3) << 1;
    const int m0 = blockIdx.y * 128, n0 = blockIdx.x * 128;
    const bool mirror = SYM && (blockIdx.y != blockIdx.x);
    if (PLANES) {
        constexpr int PW = PLO ? 4096 : 2048;
        const int NKSTD = Nn >> 5;
        uint32_t* Pb = Cp + (size_t)blockIdx.z * gridDim.y * NKSTD * PW;
#pragma unroll
        for (int i = 0; i < 4; ++i) {
#pragma unroll
            for (int j = 0; j < 4; ++j) {
                const int row0 = m0 + (wm << 6) + (i << 4) + r;
                const int col = n0 + (wn << 5) + (j << 3) + cq;
                uint16_t h[4], l[4];
#pragma unroll
                for (int e = 0; e < 4; ++e) split_h(acc[i][j][e], h[e], l[e]);
                uint32_t* blk =
                    Pb + ((size_t)(row0 >> 7) * NKSTD + (col >> 5)) * PW;
                const int kk = col & 15;
                const int nl = row0 & 127;
                const int wo = ((col >> 4) & 1) * 1024 + (nl >> 3) * 64 +
                               (((nl & 7) << 2) + ((kk & 7) >> 1)) * 2 +
                               ((kk >> 3) & 1);
                blk[wo] = pack2h(h[0], h[1]);
                blk[wo + 64] = pack2h(h[2], h[3]);
                if (PLO) {
                    blk[2048 + wo] = pack2h(l[0], l[1]);
                    blk[2048 + wo + 64] = pack2h(l[2], l[3]);
                }
                if (mirror) {
                    const int rws[4] = {row0, row0, row0 + 8, row0 + 8};
                    const int cls[4] = {col, col + 1, col, col + 1};
#pragma unroll
                    for (int e = 0; e < 4; ++e) {
                        const int rw = rws[e], cl = cls[e];
                        uint32_t* mb =
                            Pb + ((size_t)(cl >> 7) * NKSTD + (rw >> 5)) * PW;
                        const int kkm = rw & 15, nlm = cl & 127;
                        const int wm2 = ((rw >> 4) & 1) * 1024 +
                                        (nlm >> 3) * 64 +
                                        (((nlm & 7) << 2) + ((kkm & 7) >> 1)) *
                                            2 +
                                        ((kkm >> 3) & 1);
                        reinterpret_cast<uint16_t*>(mb)[2 * wm2 + (rw & 1)] =
                            h[e];
                        if (PLO)
                            reinterpret_cast<uint16_t*>(
                                mb)[2 * (2048 + wm2) + (rw & 1)] = l[e];
                    }
                }
            }
        }
    } else {
        float* Cb = C + (size_t)blockIdx.z * cB;
#pragma unroll
        for (int i = 0; i < 4; ++i) {
#pragma unroll
            for (int j = 0; j < 4; ++j) {
                const int row = m0 + (wm << 6) + (i << 4) + r;
                const int col = n0 + (wn << 5) + (j << 3) + cq;
                float o0 = acc[i][j][0], o1 = acc[i][j][1];
                float o2 = acc[i][j][2], o3 = acc[i][j][3];
                if (HAS_BIAS) {
                    float b0 = biasb[col], b1 = biasb[col + 1];
                    o0 += b0; o1 += b1; o2 += b0; o3 += b1;
                }
                *reinterpret_cast<float2*>(Cb + (size_t)row * Nn + col) =
                    make_float2(o0, o1);
                *reinterpret_cast<float2*>(Cb + (size_t)(row + 8) * Nn + col) =
                    make_float2(o2, o3);
            }
        }
    }
}

// ---------------------------------------------------------------------------
// helpers
// ---------------------------------------------------------------------------
__global__ void __launch_bounds__(256)
transpose_kernel(const float* __restrict__ in, float* __restrict__ out,
                 int R, int Cc) {
    __shared__ float t[32][33];
    const float* ib = in + (size_t)blockIdx.z * R * Cc;
    float* ob = out + (size_t)blockIdx.z * R * Cc;
    const int c = blockIdx.x * 32 + threadIdx.x;
    const int r0 = blockIdx.y * 32;
#pragma unroll
    for (int j = threadIdx.y; j < 32; j += 8)
        t[j][threadIdx.x] = ib[(size_t)(r0 + j) * Cc + c];
    __syncthreads();
    const int ro = blockIdx.x * 32;
    const int co = r0 + threadIdx.x;
#pragma unroll
    for (int j = threadIdx.y; j < 32; j += 8)
        ob[(size_t)(ro + j) * R + co] = t[threadIdx.x][j];
}

__global__ void __launch_bounds__(256)
colsum_kernel(const float* __restrict__ x, float* __restrict__ s) {
    const int e = blockIdx.x * 256 + threadIdx.x;
    const int b = blockIdx.y;
    const float* p = x + (size_t)b * N_ * D_ + e;
    float a0 = 0.f, a1 = 0.f, a2 = 0.f, a3 = 0.f;
    for (int n = 0; n < N_; n += 4) {
        a0 += p[(size_t)n * D_];
        a1 += p[(size_t)(n + 1) * D_];
        a2 += p[(size_t)(n + 2) * D_];
        a3 += p[(size_t)(n + 3) * D_];
    }
    s[b * D_ + e] = (a0 + a1) + (a2 + a3);
}

__global__ void __launch_bounds__(256)
rsum_kernel(const float* __restrict__ attn, const float* __restrict__ bv,
            float* __restrict__ r) {
    const int f = blockIdx.x * 256 + threadIdx.x;
    const int b = blockIdx.y;
    const float* p = attn + (size_t)b * D_ * D_ + f;
    float a0 = 0.f, a1 = 0.f;
    for (int e = 0; e < D_; e += 2) {
        a0 += bv[e] * p[(size_t)e * D_];
        a1 += bv[e + 1] * p[(size_t)(e + 1) * D_];
    }
    r[b * D_ + f] = a0 + a1;
}

__global__ void __launch_bounds__(256)
gemv_kernel(const float* __restrict__ Wq, const float* __restrict__ Wk,
            const float* __restrict__ bk, const float* __restrict__ s,
            float* __restrict__ u, float* __restrict__ w) {
    const int wg = blockIdx.x * 8 + (threadIdx.x >> 5);
    const int lane = threadIdx.x & 31;
    const int b = wg >> 11;
    const int o = wg & 2047;
    const bool is_u = o < 1024;
    const int row = is_u ? o : o - 1024;
    const float* W = (is_u ? Wq : Wk) + (size_t)row * D_;
    const float* sb = s + b * D_;
    float acc = 0.f;
#pragma unroll
    for (int i = 0; i < 32; ++i) acc += W[lane + (i << 5)] * sb[lane + (i << 5)];
#pragma unroll
    for (int off = 16; off; off >>= 1)
        acc += __shfl_xor_sync(0xffffffffu, acc, off);
    if (lane == 0) {
        if (is_u) u[b * D_ + row] = acc;
        else      w[b * D_ + row] = acc + (float)N_ * bk[row];
    }
}

__global__ void __launch_bounds__(256)
softmax_fused(float* __restrict__ L, const float* __restrict__ u,
              const float* __restrict__ w, const float* __restrict__ bq,
              const float* __restrict__ bk) {
    const int row = blockIdx.x;
    const int b = row >> 10, e = row & 1023;
    float* p = L + (size_t)row * 1024;
    const float uu = u[b * D_ + e];
    const float bb = bq[e];
    const float* wb = w + b * D_;
    const int t = threadIdx.x;
    const int lane = t & 31, wid = t >> 5;
    __shared__ float red[8];

    float v[4];
#pragma unroll
    for (int i = 0; i < 4; ++i) {
        const int f = t + (i << 8);
        v[i] = p[f] + uu * bk[f] + bb * wb[f];
    }
    float m = fmaxf(fmaxf(v[0], v[1]), fmaxf(v[2], v[3]));
#pragma unroll
    for (int o = 16; o; o >>= 1) m = fmaxf(m, __shfl_xor_sync(0xffffffffu, m, o));
    if (lane == 0) red[wid] = m;
    __syncthreads();
    if (t < 32) {
        float x = (t < 8) ? red[t] : -3.4e38f;
#pragma unroll
        for (int o = 4; o; o >>= 1) x = fmaxf(x, __shfl_xor_sync(0xffffffffu, x, o));
        if (t == 0) red[0] = x;
    }
    __syncthreads();
    m = red[0];
    __syncthreads();
    float ssum = 0.f;
#pragma unroll
    for (int i = 0; i < 4; ++i) {
        v[i] = expf(v[i] - m);
        ssum += v[i];
    }
#pragma unroll
    for (int o = 16; o; o >>= 1) ssum += __shfl_xor_sync(0xffffffffu, ssum, o);
    if (lane == 0) red[wid] = ssum;
    __syncthreads();
    if (t < 32) {
        float x = (t < 8) ? red[t] : 0.f;
#pragma unroll
        for (int o = 4; o; o >>= 1) x += __shfl_xor_sync(0xffffffffu, x, o);
        if (t == 0) red[0] = x;
    }
    __syncthreads();
    const float inv = 1.0f / red[0];
#pragma unroll
    for (int i = 0; i < 4; ++i) p[t + (i << 8)] = v[i] * inv;
}

extern "C" void kernel_launch(void* const* d_in, const int* in_sizes, int n_in,
                              void* d_out, int out_size) {
    const float* x  = (const float*)d_in[0];
    const float* Wq = (const float*)d_in[1];
    const float* bq = (const float*)d_in[2];
    const float* Wk = (const float*)d_in[3];
    const float* bk = (const float*)d_in[4];
    const float* Wv = (const float*)d_in[5];
    const float* bv = (const float*)d_in[6];
    float* out = (float*)d_out;

    float *L, *WvT, *s, *u, *w, *r;
    cudaGetSymbolAddress((void**)&L, g_L);
    cudaGetSymbolAddress((void**)&WvT, g_WvT);
    cudaGetSymbolAddress((void**)&s, g_s);
    cudaGetSymbolAddress((void**)&u, g_u);
    cudaGetSymbolAddress((void**)&w, g_w);
    cudaGetSymbolAddress((void**)&r, g_r);
    uint32_t *xTA, *xTB, *xA, *GB, *T1B, *W2B, *aTA, *WqA, *WkA, *WvB;
    cudaGetSymbolAddress((void**)&xTA, g_xTA);
    cudaGetSymbolAddress((void**)&xTB, g_xTB);
    cudaGetSymbolAddress((void**)&xA, g_xA);
    cudaGetSymbolAddress((void**)&GB, g_GB);
    cudaGetSymbolAddress((void**)&T1B, g_T1B);
    cudaGetSymbolAddress((void**)&W2B, g_W2B);
    cudaGetSymbolAddress((void**)&aTA, g_aTA);
    cudaGetSymbolAddress((void**)&WqA, g_WqA);
    cudaGetSymbolAddress((void**)&WkA, g_WkA);
    cudaGetSymbolAddress((void**)&WvB, g_WvB);

    constexpr int SMEM3 = 3 * (4096 + 4096) * 4;  // 98,304 B
    constexpr int SMEM1 = 3 * (2048 + 2048) * 4;  // 49,152 B
    cudaFuncSetAttribute(gemm_async<3, false, true, true, true>,
                         cudaFuncAttributeMaxDynamicSharedMemorySize, SMEM3);
    cudaFuncSetAttribute(gemm_async<3, false, false, true, true>,
                         cudaFuncAttributeMaxDynamicSharedMemorySize, SMEM3);
    cudaFuncSetAttribute(gemm_async<3, false, false, false, false>,
                         cudaFuncAttributeMaxDynamicSharedMemorySize, SMEM3);
    cudaFuncSetAttribute(gemm_async<1, false, false, true, false>,
                         cudaFuncAttributeMaxDynamicSharedMemorySize, SMEM1);
    cudaFuncSetAttribute(gemm_async<1, true, false, false, false>,
                         cudaFuncAttributeMaxDynamicSharedMemorySize, SMEM1);

    const dim3 blk(256);

    // fused split-transpose of x -> xTA/xTB planes
    xsplit_kernel<<<dim3(8, 128, B_), blk>>>(x, xTA, xTB);

    // weight/natural-layout plane converters
    transpose_kernel<<<dim3(32, 32, 1), dim3(32, 8)>>>(Wv, WvT, D_, D_);
    conv_kernel<true, true><<<dim3(8, 32, 1), blk>>>(Wk, WkA, D_, 0, 32);
    conv_kernel<true, true><<<dim3(8, 32, 1), blk>>>(Wq, WqA, D_, 0, 32);
    conv_kernel<false, false><<<dim3(8, 32, 1), blk>>>(WvT, WvB, D_, 0, 32);
    conv_kernel<true, false><<<dim3(256, 32, 1), blk>>>(x, xA, D_, 0, 32);

    // small precomputes
    colsum_kernel<<<dim3(4, 8), 256>>>(x, s);
    gemv_kernel<<<2048, 256>>>(Wq, Wk, bk, s, u, w);

    // G[b] = xT xT^T  (sym, 3-split) -> GB planes
    gemm_async<3, false, true, true, true><<<dim3(8, 8, B_), blk, SMEM3>>>(
        xTA, xTB, nullptr, nullptr, GB, D_, 128,
        (size_t)8 * 128 * 4096, (size_t)8 * 128 * 4096, 0, 0);

    // T1t[b] = Wk G[b]  (3-split) -> T1B planes
    gemm_async<3, false, false, true, true><<<dim3(8, 8, B_), blk, SMEM3>>>(
        WkA, GB, nullptr, nullptr, T1B, D_, 32,
        0, (size_t)8 * 32 * 4096, 0, 0);

    // L[b] = Wq T1t[b]^T  (3-split, fp32 out for softmax)
    gemm_async<3, false, false, false, false><<<dim3(8, 8, B_), blk, SMEM3>>>(
        WqA, T1B, nullptr, L, nullptr, D_, 32,
        0, (size_t)8 * 32 * 4096, (size_t)D_ * D_, 0);

    // softmax with rank-1 corrections -> attn (in place)
    softmax_fused<<<B_ * D_, 256>>>(L, u, w, bq, bk);

    // fused transpose+round attn -> aTA planes ; r = bv^T attn
    atsplit_kernel<<<dim3(8, 32, B_), blk>>>(L, aTA);
    rsum_kernel<<<dim3(4, 8), 256>>>(L, bv, r);

    // W2t[b] = aT[b] WvT^T  (pure fp16, 1 product) -> W2B hi planes
    gemm_async<1, false, false, true, false><<<dim3(8, 8, B_), blk, SMEM1>>>(
        aTA, WvB, nullptr, nullptr, W2B, D_, 32,
        (size_t)8 * 32 * 2048, 0, 0, 0);

    // out[b] = x[b] W2t[b]^T + r[b]  (pure fp16, 1 product, fp32 out)
    gemm_async<1, true, false, false, false><<<dim3(8, 32, B_), blk, SMEM1>>>(
        xA, W2B, r, out, nullptr, D_, 32,
        (size_t)32 * 32 * 2048, (size_t)8 * 32 * 2048,
        (size_t)N_ * D_, D_);
}

// round 16
// speedup vs baseline: 3.6653x; 1.0117x over previous
#include <cuda_runtime.h>
#include <cuda_fp16.h>
#include <cstdint>
#include <math.h>

#define B_   8
#define N_   4096
#define D_   1024

// ---------------------------------------------------------------------------
// fp32 scratch
// ---------------------------------------------------------------------------
__device__ float g_L  [(size_t)B_ * D_ * D_];   // logits -> attn
__device__ float g_WvT[(size_t)D_ * D_];        // Wv^T
__device__ float g_s  [(size_t)B_ * D_];        // s = x^T 1
__device__ float g_u  [(size_t)B_ * D_];        // u = Wq s
__device__ float g_w  [(size_t)B_ * D_];        // w' = Wk s + N*bk
__device__ float g_r  [(size_t)B_ * D_];        // r = bv^T attn

// ---------------------------------------------------------------------------
// fp16 plane buffers (fragment-order GMEM; words = f16x2)
// hi/lo block = 4096 words; hi-only block = 2048 words; blocks keyed (tile,k32)
// ---------------------------------------------------------------------------
__device__ uint32_t g_xTA[(size_t)8 * 8 * 128 * 4096];   // 134 MB (hi/lo A)
__device__ uint32_t g_xTB[(size_t)8 * 8 * 128 * 4096];   // 134 MB (hi/lo B)
__device__ uint32_t g_xA [(size_t)256 * 32 * 2048];      //  64 MB (hi A)
__device__ uint32_t g_GB [(size_t)8 * 8 * 32 * 4096];    //  33 MB (hi/lo B)
__device__ uint32_t g_T1B[(size_t)8 * 8 * 32 * 4096];    //  33 MB (hi/lo B)
__device__ uint32_t g_W2B[(size_t)8 * 8 * 32 * 2048];    //  17 MB (hi B)
__device__ uint32_t g_aTA[(size_t)8 * 8 * 32 * 2048];    //  17 MB (hi A)
__device__ uint32_t g_WqA[(size_t)8 * 32 * 4096];        //   4 MB (hi/lo A)
__device__ uint32_t g_WkA[(size_t)8 * 32 * 4096];        //   4 MB (hi/lo A)
__device__ uint32_t g_WvB[(size_t)8 * 32 * 2048];        //   2 MB (hi B)

__device__ __forceinline__ uint32_t smem_u32(const void* p) {
    uint32_t a;
    asm("{ .reg .u64 t; cvta.to.shared.u64 t, %1; cvt.u32.u64 %0, t; }"
        : "=r"(a) : "l"(p));
    return a;
}
__device__ __forceinline__ void cpa16(uint32_t saddr, const void* g) {
    asm volatile("cp.async.cg.shared.global [%0], [%1], 16;"
                 :: "r"(saddr), "l"(g));
}
__device__ __forceinline__ void mma16(float* c, const uint32_t* a,
                                      const uint32_t* b) {
    asm("mma.sync.aligned.m16n8k16.row.col.f32.f16.f16.f32 "
        "{%0,%1,%2,%3}, {%4,%5,%6,%7}, {%8,%9}, {%0,%1,%2,%3};"
        : "+f"(c[0]), "+f"(c[1]), "+f"(c[2]), "+f"(c[3])
        : "r"(a[0]), "r"(a[1]), "r"(a[2]), "r"(a[3]), "r"(b[0]), "r"(b[1]));
}
__device__ __forceinline__ void split_h(float x, uint16_t& h, uint16_t& l) {
    __half hh = __float2half_rn(x);
    float hf = __half2float(hh);
    h = __half_as_ushort(hh);
    l = __half_as_ushort(__float2half_rn(x - hf));
}
__device__ __forceinline__ uint32_t pack2h(uint16_t lo, uint16_t hi) {
    return (uint32_t)lo | ((uint32_t)hi << 16);
}

// ---------------------------------------------------------------------------
// fused split-transpose: x [b][n][e] -> xTA (A-role hi/lo) + xTB (B-role
// hi/lo) fragment planes of xT[b][e][n].
// ---------------------------------------------------------------------------
__global__ void __launch_bounds__(256)
xsplit_kernel(const float* __restrict__ x, uint32_t* __restrict__ dA,
              uint32_t* __restrict__ dB) {
    __shared__ float st[32][132];
    const int tid = threadIdx.x;
    const int e0 = blockIdx.x * 128, n0 = blockIdx.y * 32;
    const int bz = blockIdx.z;
#pragma unroll
    for (int it = 0; it < 4; ++it) {
        int idx = tid + (it << 8);
        int nl = idx >> 5, e4 = idx & 31;
        float4 v = *reinterpret_cast<const float4*>(
            x + ((size_t)bz * N_ + n0 + nl) * D_ + e0 + (e4 << 2));
        *reinterpret_cast<float4*>(&st[nl][e4 << 2]) = v;
    }
    __syncthreads();
    const size_t blk = ((size_t)bz * 8 + blockIdx.x) * 128 + blockIdx.y;
    uint32_t* dbA = dA + blk * 4096;
    uint32_t* dbB = dB + blk * 4096;
#pragma unroll
    for (int it = 0; it < 4; ++it) {
        int idx = tid + (it << 8);
        int mm = idx >> 3, k4 = idx & 7, k0 = k4 << 2;
        float va[4];
#pragma unroll
        for (int c = 0; c < 4; ++c) va[c] = st[k0 + c][mm];
        uint16_t h[4], l[4];
#pragma unroll
        for (int c = 0; c < 4; ++c) split_h(va[c], h[c], l[c]);
        int ks = k0 >> 4, kk = k0 & 15;
        {   // A-role
            int rr = mm & 15, mt = mm >> 4;
            int reg = (rr >> 3) + ((kk >> 3) << 1);
            int o = ks * 1024 + mt * 128 +
                    (((rr & 7) << 2) + ((kk & 7) >> 1)) * 4 + reg;
            dbA[o] = pack2h(h[0], h[1]);
            dbA[o + 4] = pack2h(h[2], h[3]);
            dbA[2048 + o] = pack2h(l[0], l[1]);
            dbA[2048 + o + 4] = pack2h(l[2], l[3]);
        }
        {   // B-role
            int nt = mm >> 3, reg = kk >> 3;
            int o = ks * 1024 + nt * 64 +
                    (((mm & 7) << 2) + ((kk & 7) >> 1)) * 2 + reg;
            dbB[o] = pack2h(h[0], h[1]);
            dbB[o + 2] = pack2h(h[2], h[3]);
            dbB[2048 + o] = pack2h(l[0], l[1]);
            dbB[2048 + o + 2] = pack2h(l[2], l[3]);
        }
    }
}

// ---------------------------------------------------------------------------
// fused transpose+round: attn [b][e][f] -> aTA = A-role hi-only planes of
// attn^T (rows f, k = e).
// ---------------------------------------------------------------------------
__global__ void __launch_bounds__(256)
atsplit_kernel(const float* __restrict__ attn, uint32_t* __restrict__ dA) {
    __shared__ float st[32][132];
    const int tid = threadIdx.x;
    const int f0 = blockIdx.x * 128, e0 = blockIdx.y * 32;
    const int bz = blockIdx.z;
#pragma unroll
    for (int it = 0; it < 4; ++it) {
        int idx = tid + (it << 8);
        int el = idx >> 5, f4 = idx & 31;
        float4 v = *reinterpret_cast<const float4*>(
            attn + ((size_t)bz * D_ + e0 + el) * D_ + f0 + (f4 << 2));
        *reinterpret_cast<float4*>(&st[el][f4 << 2]) = v;
    }
    __syncthreads();
    const size_t blk = ((size_t)bz * 8 + blockIdx.x) * 32 + blockIdx.y;
    uint32_t* db = dA + blk * 2048;
#pragma unroll
    for (int it = 0; it < 4; ++it) {
        int idx = tid + (it << 8);
        int mm = idx >> 3, k4 = idx & 7, k0 = k4 << 2;
        uint16_t h[4];
#pragma unroll
        for (int c = 0; c < 4; ++c)
            h[c] = __half_as_ushort(__float2half_rn(st[k0 + c][mm]));
        int ks = k0 >> 4, kk = k0 & 15;
        int rr = mm & 15, mt = mm >> 4;
        int reg = (rr >> 3) + ((kk >> 3) << 1);
        int o = ks * 1024 + mt * 128 +
                (((rr & 7) << 2) + ((kk & 7) >> 1)) * 4 + reg;
        db[o] = pack2h(h[0], h[1]);
        db[o + 4] = pack2h(h[2], h[3]);
    }
}

// ---------------------------------------------------------------------------
// converter: fp32 [rows,K] -> planes.
// ---------------------------------------------------------------------------
template <bool ROLE_A, bool WITH_LO>
__global__ void __launch_bounds__(256)
conv_kernel(const float* __restrict__ src, uint32_t* __restrict__ dst,
            int ld, size_t srcBatch, int nkst) {
    const int tid = threadIdx.x;
    const int tileR = blockIdx.x, kst = blockIdx.y, bz = blockIdx.z;
    constexpr int WORDS = WITH_LO ? 4096 : 2048;
    const float* sb =
        src + (size_t)bz * srcBatch + (size_t)tileR * 128 * ld + kst * 32;
    uint32_t* db =
        dst + (((size_t)bz * gridDim.x + tileR) * nkst + kst) * WORDS;
#pragma unroll
    for (int it = 0; it < 4; ++it) {
        int idx = tid + (it << 8);
        int mm = idx >> 3, k4 = idx & 7;
        float4 v = *reinterpret_cast<const float4*>(sb + (size_t)mm * ld +
                                                    (k4 << 2));
        float va[4] = {v.x, v.y, v.z, v.w};
        uint16_t h[4], l[4];
#pragma unroll
        for (int c = 0; c < 4; ++c) {
            if (WITH_LO) split_h(va[c], h[c], l[c]);
            else h[c] = __half_as_ushort(__float2half_rn(va[c]));
        }
        int k0 = k4 << 2, ks = k0 >> 4, kk = k0 & 15;
        if (ROLE_A) {
            int rr = mm & 15, mt = mm >> 4;
            int reg = (rr >> 3) + ((kk >> 3) << 1);
            int o = ks * 1024 + mt * 128 +
                    (((rr & 7) << 2) + ((kk & 7) >> 1)) * 4 + reg;
            db[o] = pack2h(h[0], h[1]);
            db[o + 4] = pack2h(h[2], h[3]);
            if (WITH_LO) {
                db[2048 + o] = pack2h(l[0], l[1]);
                db[2048 + o + 4] = pack2h(l[2], l[3]);
            }
        } else {
            int nt = mm >> 3, reg = kk >> 3;
            int o = ks * 1024 + nt * 64 +
                    (((mm & 7) << 2) + ((kk & 7) >> 1)) * 2 + reg;
            db[o] = pack2h(h[0], h[1]);
            db[o + 2] = pack2h(h[2], h[3]);
            if (WITH_LO) {
                db[2048 + o] = pack2h(l[0], l[1]);
                db[2048 + o + 2] = pack2h(l[2], l[3]);
            }
        }
    }
}

// ---------------------------------------------------------------------------
// async GEMM from pre-split planes. cp.async 3-stage; LDS+MMA mainloop.
// SPLITS=3: A hi/lo, B hi/lo, 3 products.  SPLITS=1: A hi, B hi, 1 product.
// KST: k16-steps per pipeline stage (2 -> k32 stage, 4 -> k64 stage).
// SYM: triangular grid (36 CTAs/batch), decode (by,bx) with by>=bx; mirror.
// PLANES: epilogue writes B-role fp16 planes into Cp (PLO: also lo plane).
// nst = number of pipeline stages = K/(16*KST).
// ---------------------------------------------------------------------------
template <int SPLITS, bool HAS_BIAS, bool SYM, bool PLANES, bool PLO, int KST>
__global__ void __launch_bounds__(256, 2)
gemm_async(const uint32_t* __restrict__ Ap, const uint32_t* __restrict__ Bp,
           const float* __restrict__ bias, float* __restrict__ C,
           uint32_t* __restrict__ Cp,
           int Nn, int nst, int mtiles, size_t aBatch, size_t bBatch,
           size_t cB, size_t biasB) {
    int bx, by;
    if (SYM) {  // triangular decode: t -> (by, bx), by >= bx
        int t = blockIdx.x;
        int i = (int)((sqrtf(8.f * (float)t + 1.f) - 1.f) * 0.5f);
        while ((i + 1) * (i + 2) / 2 <= t) ++i;
        while (i * (i + 1) / 2 > t) --i;
        by = i;
        bx = t - i * (i + 1) / 2;
    } else {
        bx = blockIdx.x;
        by = blockIdx.y;
    }
    extern __shared__ uint32_t smw[];
    const uint32_t sbase = smem_u32(smw);
    constexpr int AW = 1024 * KST * ((SPLITS == 3) ? 2 : 1);
    constexpr int BW = 1024 * KST * ((SPLITS >= 2) ? 2 : 1);
    constexpr int SW = AW + BW;
    constexpr int NCHUNK = SW / 4 / 256;
    const int tid = threadIdx.x;
    const int lane = tid & 31, wid = tid >> 5;
    const int wm = wid & 1, wn = wid >> 1;
    const uint32_t* Abase =
        Ap + blockIdx.z * aBatch + (size_t)by * nst * AW;
    const uint32_t* Bbase =
        Bp + blockIdx.z * bBatch + (size_t)bx * nst * BW;
    const float* biasb = HAS_BIAS ? bias + blockIdx.z * biasB : nullptr;

    float acc[4][4][4];
#pragma unroll
    for (int i = 0; i < 4; ++i)
#pragma unroll
        for (int j = 0; j < 4; ++j)
#pragma unroll
            for (int e = 0; e < 4; ++e) acc[i][j][e] = 0.f;

    auto issue = [&](int t, int buf) {
        const uint32_t* As = Abase + (size_t)t * AW;
        const uint32_t* Bs = Bbase + (size_t)t * BW;
        const uint32_t sb = sbase + (uint32_t)(buf * SW) * 4u;
#pragma unroll
        for (int c = 0; c < NCHUNK; ++c) {
            int id = tid + (c << 8);
            if (id < AW / 4) cpa16(sb + id * 16, As + id * 4);
            else cpa16(sb + id * 16, Bs + (size_t)(id - AW / 4) * 4);
        }
    };
    auto compute = [&](int buf) {
        const uint32_t* S = smw + buf * SW;
        const uint32_t* Ah = S;
        const uint32_t* Al = S + 2048;   // valid layout only for SPLITS==3
        const uint32_t* Bh = S + AW;
        const uint32_t* Bl = S + AW + 2048;
#pragma unroll
        for (int ks = 0; ks < KST; ++ks) {
            uint32_t bh[4][2], bl[4][2];
#pragma unroll
            for (int j = 0; j < 4; ++j) {
                const int o = ks * 1024 + ((wn << 2) + j) * 64 + (lane << 1);
                *reinterpret_cast<uint2*>(bh[j]) =
                    *reinterpret_cast<const uint2*>(Bh + o);
                if (SPLITS >= 2)
                    *reinterpret_cast<uint2*>(bl[j]) =
                        *reinterpret_cast<const uint2*>(Bl + o);
            }
#pragma unroll
            for (int i = 0; i < 4; ++i) {
                uint32_t ah[4], al[4];
                const int o = ks * 1024 + ((wm << 2) + i) * 128 + (lane << 2);
                *reinterpret_cast<uint4*>(ah) =
                    *reinterpret_cast<const uint4*>(Ah + o);
                if (SPLITS == 3)
                    *reinterpret_cast<uint4*>(al) =
                        *reinterpret_cast<const uint4*>(Al + o);
#pragma unroll
                for (int j = 0; j < 4; ++j) {
                    mma16(acc[i][j], ah, bh[j]);
                    if (SPLITS >= 2) mma16(acc[i][j], ah, bl[j]);
                    if (SPLITS == 3) mma16(acc[i][j], al, bh[j]);
                }
            }
        }
    };

    issue(0, 0);
    asm volatile("cp.async.commit_group;" ::: "memory");
    issue(1, 1);
    asm volatile("cp.async.commit_group;" ::: "memory");
    for (int t = 0; t < nst; ++t) {
        if (t + 1 < nst)
            asm volatile("cp.async.wait_group 1;" ::: "memory");
        else
            asm volatile("cp.async.wait_group 0;" ::: "memory");
        __syncthreads();
        if (t + 2 < nst) {
            issue(t + 2, (t + 2) % 3);
            asm volatile("cp.async.commit_group;" ::: "memory");
        }
        compute(t % 3);
    }

    const int r = lane >> 2, cq = (lane & 3) << 1;
    const int m0 = by * 128, n0 = bx * 128;
    const bool mirror = SYM && (by != bx);
    if (PLANES) {
        constexpr int PW = PLO ? 4096 : 2048;
        const int NKSTD = Nn >> 5;
        uint32_t* Pb = Cp + (size_t)blockIdx.z * mtiles * NKSTD * PW;
#pragma unroll
        for (int i = 0; i < 4; ++i) {
#pragma unroll
            for (int j = 0; j < 4; ++j) {
                const int row0 = m0 + (wm << 6) + (i << 4) + r;
                const int col = n0 + (wn << 5) + (j << 3) + cq;
                uint16_t h[4], l[4];
#pragma unroll
                for (int e = 0; e < 4; ++e) split_h(acc[i][j][e], h[e], l[e]);
                uint32_t* blk =
                    Pb + ((size_t)(row0 >> 7) * NKSTD + (col >> 5)) * PW;
                const int kk = col & 15;
                const int nl = row0 & 127;
                const int wo = ((col >> 4) & 1) * 1024 + (nl >> 3) * 64 +
                               (((nl & 7) << 2) + ((kk & 7) >> 1)) * 2 +
                               ((kk >> 3) & 1);
                blk[wo] = pack2h(h[0], h[1]);
                blk[wo + 64] = pack2h(h[2], h[3]);
                if (PLO) {
                    blk[2048 + wo] = pack2h(l[0], l[1]);
                    blk[2048 + wo + 64] = pack2h(l[2], l[3]);
                }
                if (mirror) {
                    const int rws[4] = {row0, row0, row0 + 8, row0 + 8};
                    const int cls[4] = {col, col + 1, col, col + 1};
#pragma unroll
                    for (int e = 0; e < 4; ++e) {
                        const int rw = rws[e], cl = cls[e];
                        uint32_t* mb =
                            Pb + ((size_t)(cl >> 7) * NKSTD + (rw >> 5)) * PW;
                        const int kkm = rw & 15, nlm = cl & 127;
                        const int wm2 = ((rw >> 4) & 1) * 1024 +
                                        (nlm >> 3) * 64 +
                                        (((nlm & 7) << 2) + ((kkm & 7) >> 1)) *
                                            2 +
                                        ((kkm >> 3) & 1);
                        reinterpret_cast<uint16_t*>(mb)[2 * wm2 + (rw & 1)] =
                            h[e];
                        if (PLO)
                            reinterpret_cast<uint16_t*>(
                                mb)[2 * (2048 + wm2) + (rw & 1)] = l[e];
                    }
                }
            }
        }
    } else {
        float* Cb = C + (size_t)blockIdx.z * cB;
#pragma unroll
        for (int i = 0; i < 4; ++i) {
#pragma unroll
            for (int j = 0; j < 4; ++j) {
                const int row = m0 + (wm << 6) + (i << 4) + r;
                const int col = n0 + (wn << 5) + (j << 3) + cq;
                float o0 = acc[i][j][0], o1 = acc[i][j][1];
                float o2 = acc[i][j][2], o3 = acc[i][j][3];
                if (HAS_BIAS) {
                    float b0 = biasb[col], b1 = biasb[col + 1];
                    o0 += b0; o1 += b1; o2 += b0; o3 += b1;
                }
                *reinterpret_cast<float2*>(Cb + (size_t)row * Nn + col) =
                    make_float2(o0, o1);
                *reinterpret_cast<float2*>(Cb + (size_t)(row + 8) * Nn + col) =
                    make_float2(o2, o3);
            }
        }
    }
}

// ---------------------------------------------------------------------------
// helpers
// ---------------------------------------------------------------------------
__global__ void __launch_bounds__(256)
transpose_kernel(const float* __restrict__ in, float* __restrict__ out,
                 int R, int Cc) {
    __shared__ float t[32][33];
    const float* ib = in + (size_t)blockIdx.z * R * Cc;
    float* ob = out + (size_t)blockIdx.z * R * Cc;
    const int c = blockIdx.x * 32 + threadIdx.x;
    const int r0 = blockIdx.y * 32;
#pragma unroll
    for (int j = threadIdx.y; j < 32; j += 8)
        t[j][threadIdx.x] = ib[(size_t)(r0 + j) * Cc + c];
    __syncthreads();
    const int ro = blockIdx.x * 32;
    const int co = r0 + threadIdx.x;
#pragma unroll
    for (int j = threadIdx.y; j < 32; j += 8)
        ob[(size_t)(ro + j) * R + co] = t[threadIdx.x][j];
}

__global__ void __launch_bounds__(256)
colsum_kernel(const float* __restrict__ x, float* __restrict__ s) {
    const int e = blockIdx.x * 256 + threadIdx.x;
    const int b = blockIdx.y;
    const float* p = x + (size_t)b * N_ * D_ + e;
    float a0 = 0.f, a1 = 0.f, a2 = 0.f, a3 = 0.f;
    for (int n = 0; n < N_; n += 4) {
        a0 += p[(size_t)n * D_];
        a1 += p[(size_t)(n + 1) * D_];
        a2 += p[(size_t)(n + 2) * D_];
        a3 += p[(size_t)(n + 3) * D_];
    }
    s[b * D_ + e] = (a0 + a1) + (a2 + a3);
}

__global__ void __launch_bounds__(256)
rsum_kernel(const float* __restrict__ attn, const float* __restrict__ bv,
            float* __restrict__ r) {
    const int f = blockIdx.x * 256 + threadIdx.x;
    const int b = blockIdx.y;
    const float* p = attn + (size_t)b * D_ * D_ + f;
    float a0 = 0.f, a1 = 0.f;
    for (int e = 0; e < D_; e += 2) {
        a0 += bv[e] * p[(size_t)e * D_];
        a1 += bv[e + 1] * p[(size_t)(e + 1) * D_];
    }
    r[b * D_ + f] = a0 + a1;
}

__global__ void __launch_bounds__(256)
gemv_kernel(const float* __restrict__ Wq, const float* __restrict__ Wk,
            const float* __restrict__ bk, const float* __restrict__ s,
            float* __restrict__ u, float* __restrict__ w) {
    const int wg = blockIdx.x * 8 + (threadIdx.x >> 5);
    const int lane = threadIdx.x & 31;
    const int b = wg >> 11;
    const int o = wg & 2047;
    const bool is_u = o < 1024;
    const int row = is_u ? o : o - 1024;
    const float* W = (is_u ? Wq : Wk) + (size_t)row * D_;
    const float* sb = s + b * D_;
    float acc = 0.f;
#pragma unroll
    for (int i = 0; i < 32; ++i) acc += W[lane + (i << 5)] * sb[lane + (i << 5)];
#pragma unroll
    for (int off = 16; off; off >>= 1)
        acc += __shfl_xor_sync(0xffffffffu, acc, off);
    if (lane == 0) {
        if (is_u) u[b * D_ + row] = acc;
        else      w[b * D_ + row] = acc + (float)N_ * bk[row];
    }
}

__global__ void __launch_bounds__(256)
softmax_fused(float* __restrict__ L, const float* __restrict__ u,
              const float* __restrict__ w, const float* __restrict__ bq,
              const float* __restrict__ bk) {
    const int row = blockIdx.x;
    const int b = row >> 10, e = row & 1023;
    float* p = L + (size_t)row * 1024;
    const float uu = u[b * D_ + e];
    const float bb = bq[e];
    const float* wb = w + b * D_;
    const int t = threadIdx.x;
    const int lane = t & 31, wid = t >> 5;
    __shared__ float red[8];

    float v[4];
#pragma unroll
    for (int i = 0; i < 4; ++i) {
        const int f = t + (i << 8);
        v[i] = p[f] + uu * bk[f] + bb * wb[f];
    }
    float m = fmaxf(fmaxf(v[0], v[1]), fmaxf(v[2], v[3]));
#pragma unroll
    for (int o = 16; o; o >>= 1) m = fmaxf(m, __shfl_xor_sync(0xffffffffu, m, o));
    if (lane == 0) red[wid] = m;
    __syncthreads();
    if (t < 32) {
        float x = (t < 8) ? red[t] : -3.4e38f;
#pragma unroll
        for (int o = 4; o; o >>= 1) x = fmaxf(x, __shfl_xor_sync(0xffffffffu, x, o));
        if (t == 0) red[0] = x;
    }
    __syncthreads();
    m = red[0];
    __syncthreads();
    float ssum = 0.f;
#pragma unroll
    for (int i = 0; i < 4; ++i) {
        v[i] = expf(v[i] - m);
        ssum += v[i];
    }
#pragma unroll
    for (int o = 16; o; o >>= 1) ssum += __shfl_xor_sync(0xffffffffu, ssum, o);
    if (lane == 0) red[wid] = ssum;
    __syncthreads();
    if (t < 32) {
        float x = (t < 8) ? red[t] : 0.f;
#pragma unroll
        for (int o = 4; o; o >>= 1) x += __shfl_xor_sync(0xffffffffu, x, o);
        if (t == 0) red[0] = x;
    }
    __syncthreads();
    const float inv = 1.0f / red[0];
#pragma unroll
    for (int i = 0; i < 4; ++i) p[t + (i << 8)] = v[i] * inv;
}

extern "C" void kernel_launch(void* const* d_in, const int* in_sizes, int n_in,
                              void* d_out, int out_size) {
    const float* x  = (const float*)d_in[0];
    const float* Wq = (const float*)d_in[1];
    const float* bq = (const float*)d_in[2];
    const float* Wk = (const float*)d_in[3];
    const float* bk = (const float*)d_in[4];
    const float* Wv = (const float*)d_in[5];
    const float* bv = (const float*)d_in[6];
    float* out = (float*)d_out;

    float *L, *WvT, *s, *u, *w, *r;
    cudaGetSymbolAddress((void**)&L, g_L);
    cudaGetSymbolAddress((void**)&WvT, g_WvT);
    cudaGetSymbolAddress((void**)&s, g_s);
    cudaGetSymbolAddress((void**)&u, g_u);
    cudaGetSymbolAddress((void**)&w, g_w);
    cudaGetSymbolAddress((void**)&r, g_r);
    uint32_t *xTA, *xTB, *xA, *GB, *T1B, *W2B, *aTA, *WqA, *WkA, *WvB;
    cudaGetSymbolAddress((void**)&xTA, g_xTA);
    cudaGetSymbolAddress((void**)&xTB, g_xTB);
    cudaGetSymbolAddress((void**)&xA, g_xA);
    cudaGetSymbolAddress((void**)&GB, g_GB);
    cudaGetSymbolAddress((void**)&T1B, g_T1B);
    cudaGetSymbolAddress((void**)&W2B, g_W2B);
    cudaGetSymbolAddress((void**)&aTA, g_aTA);
    cudaGetSymbolAddress((void**)&WqA, g_WqA);
    cudaGetSymbolAddress((void**)&WkA, g_WkA);
    cudaGetSymbolAddress((void**)&WvB, g_WvB);

    constexpr int SMEM3 = 3 * (4096 + 4096) * 4;  // 98,304 B (KST=2, 3-split)
    constexpr int SMEM1 = 3 * (4096 + 4096) * 4;  // 98,304 B (KST=4, 1-split)
    cudaFuncSetAttribute(gemm_async<3, false, true, true, true, 2>,
                         cudaFuncAttributeMaxDynamicSharedMemorySize, SMEM3);
    cudaFuncSetAttribute(gemm_async<3, false, false, true, true, 2>,
                         cudaFuncAttributeMaxDynamicSharedMemorySize, SMEM3);
    cudaFuncSetAttribute(gemm_async<3, false, false, false, false, 2>,
                         cudaFuncAttributeMaxDynamicSharedMemorySize, SMEM3);
    cudaFuncSetAttribute(gemm_async<1, false, false, true, false, 4>,
                         cudaFuncAttributeMaxDynamicSharedMemorySize, SMEM1);
    cudaFuncSetAttribute(gemm_async<1, true, false, false, false, 4>,
                         cudaFuncAttributeMaxDynamicSharedMemorySize, SMEM1);

    const dim3 blk(256);

    // fused split-transpose of x -> xTA/xTB planes
    xsplit_kernel<<<dim3(8, 128, B_), blk>>>(x, xTA, xTB);

    // weight/natural-layout plane converters
    transpose_kernel<<<dim3(32, 32, 1), dim3(32, 8)>>>(Wv, WvT, D_, D_);
    conv_kernel<true, true><<<dim3(8, 32, 1), blk>>>(Wk, WkA, D_, 0, 32);
    conv_kernel<true, true><<<dim3(8, 32, 1), blk>>>(Wq, WqA, D_, 0, 32);
    conv_kernel<false, false><<<dim3(8, 32, 1), blk>>>(WvT, WvB, D_, 0, 32);
    conv_kernel<true, false><<<dim3(256, 32, 1), blk>>>(x, xA, D_, 0, 32);

    // small precomputes
    colsum_kernel<<<dim3(4, 8), 256>>>(x, s);
    gemv_kernel<<<2048, 256>>>(Wq, Wk, bk, s, u, w);

    // G[b] = xT xT^T  (triangular grid: 36 CTAs/batch, one clean wave)
    gemm_async<3, false, true, true, true, 2><<<dim3(36, 1, B_), blk, SMEM3>>>(
        xTA, xTB, nullptr, nullptr, GB, D_, 128, 8,
        (size_t)8 * 128 * 4096, (size_t)8 * 128 * 4096, 0, 0);

    // T1t[b] = Wk G[b]  (3-split) -> T1B planes
    gemm_async<3, false, false, true, true, 2><<<dim3(8, 8, B_), blk, SMEM3>>>(
        WkA, GB, nullptr, nullptr, T1B, D_, 32, 8,
        0, (size_t)8 * 32 * 4096, 0, 0);

    // L[b] = Wq T1t[b]^T  (3-split, fp32 out for softmax)
    gemm_async<3, false, false, false, false, 2><<<dim3(8, 8, B_), blk, SMEM3>>>(
        WqA, T1B, nullptr, L, nullptr, D_, 32, 8,
        0, (size_t)8 * 32 * 4096, (size_t)D_ * D_, 0);

    // softmax with rank-1 corrections -> attn (in place)
    softmax_fused<<<B_ * D_, 256>>>(L, u, w, bq, bk);

    // fused transpose+round attn -> aTA planes ; r = bv^T attn
    atsplit_kernel<<<dim3(8, 32, B_), blk>>>(L, aTA);
    rsum_kernel<<<dim3(4, 8), 256>>>(L, bv, r);

    // W2t[b] = aT[b] WvT^T  (pure fp16, k64 stages) -> W2B hi planes
    gemm_async<1, false, false, true, false, 4><<<dim3(8, 8, B_), blk, SMEM1>>>(
        aTA, WvB, nullptr, nullptr, W2B, D_, 16, 8,
        (size_t)8 * 32 * 2048, 0, 0, 0);

    // out[b] = x[b] W2t[b]^T + r[b]  (pure fp16, k64 stages, fp32 out)
    gemm_async<1, true, false, false, false, 4><<<dim3(8, 32, B_), blk, SMEM1>>>(
        xA, W2B, r, out, nullptr, D_, 16, 8,
        (size_t)32 * 32 * 2048, (size_t)8 * 32 * 2048,
        (size_t)N_ * D_, D_);
}

// round 17
// speedup vs baseline: 3.7179x; 1.0144x over previous
#include <cuda_runtime.h>
#include <cuda_fp16.h>
#include <cstdint>
#include <math.h>

#define B_   8
#define N_   4096
#define D_   1024

// ---------------------------------------------------------------------------
// fp32 scratch
// ---------------------------------------------------------------------------
__device__ float g_L  [(size_t)B_ * D_ * D_];   // logits -> attn
__device__ float g_s  [(size_t)B_ * D_];        // s = x^T 1
__device__ float g_u  [(size_t)B_ * D_];        // u = Wq s
__device__ float g_w  [(size_t)B_ * D_];        // w' = Wk s + N*bk
__device__ float g_r  [(size_t)B_ * D_];        // r = bv^T attn

// ---------------------------------------------------------------------------
// fp16 plane buffers (fragment-order GMEM; words = f16x2)
// hi/lo block = 4096 words; hi-only block = 2048 words; blocks keyed (tile,k32)
// ---------------------------------------------------------------------------
__device__ uint32_t g_xTA[(size_t)8 * 8 * 128 * 4096];   // 134 MB (hi/lo A)
__device__ uint32_t g_xTB[(size_t)8 * 8 * 128 * 4096];   // 134 MB (hi/lo B)
__device__ uint32_t g_xA [(size_t)256 * 32 * 2048];      //  64 MB (hi A)
__device__ uint32_t g_GB [(size_t)8 * 8 * 32 * 4096];    //  33 MB (hi/lo B)
__device__ uint32_t g_T1B[(size_t)8 * 8 * 32 * 4096];    //  33 MB (hi/lo B)
__device__ uint32_t g_W2B[(size_t)8 * 8 * 32 * 2048];    //  17 MB (hi B)
__device__ uint32_t g_aTA[(size_t)8 * 8 * 32 * 2048];    //  17 MB (hi A)
__device__ uint32_t g_WqA[(size_t)8 * 32 * 4096];        //   4 MB (hi/lo A)
__device__ uint32_t g_WkA[(size_t)8 * 32 * 4096];        //   4 MB (hi/lo A)
__device__ uint32_t g_WvB[(size_t)8 * 32 * 2048];        //   2 MB (hi B)

__device__ __forceinline__ uint32_t smem_u32(const void* p) {
    uint32_t a;
    asm("{ .reg .u64 t; cvta.to.shared.u64 t, %1; cvt.u32.u64 %0, t; }"
        : "=r"(a) : "l"(p));
    return a;
}
__device__ __forceinline__ void cpa16(uint32_t saddr, const void* g) {
    asm volatile("cp.async.cg.shared.global [%0], [%1], 16;"
                 :: "r"(saddr), "l"(g));
}
__device__ __forceinline__ void mma16(float* c, const uint32_t* a,
                                      const uint32_t* b) {
    asm("mma.sync.aligned.m16n8k16.row.col.f32.f16.f16.f32 "
        "{%0,%1,%2,%3}, {%4,%5,%6,%7}, {%8,%9}, {%0,%1,%2,%3};"
        : "+f"(c[0]), "+f"(c[1]), "+f"(c[2]), "+f"(c[3])
        : "r"(a[0]), "r"(a[1]), "r"(a[2]), "r"(a[3]), "r"(b[0]), "r"(b[1]));
}
__device__ __forceinline__ void split_h(float x, uint16_t& h, uint16_t& l) {
    __half hh = __float2half_rn(x);
    float hf = __half2float(hh);
    h = __half_as_ushort(hh);
    l = __half_as_ushort(__float2half_rn(x - hf));
}
__device__ __forceinline__ uint32_t pack2h(uint16_t lo, uint16_t hi) {
    return (uint32_t)lo | ((uint32_t)hi << 16);
}

// ---------------------------------------------------------------------------
// fused split-transpose: x [b][n][e] -> xTA (A-role hi/lo planes of x^T),
// xTB (B-role hi/lo planes of x^T), AND xA (A-role hi-only planes of x
// itself). Reads x exactly once. grid (8 e-tiles, 128 n-stages, B_).
// ---------------------------------------------------------------------------
__global__ void __launch_bounds__(256)
xsplit_kernel(const float* __restrict__ x, uint32_t* __restrict__ dA,
              uint32_t* __restrict__ dB, uint32_t* __restrict__ dXA) {
    __shared__ float st[32][132];
    const int tid = threadIdx.x;
    const int e0 = blockIdx.x * 128, n0 = blockIdx.y * 32;
    const int bz = blockIdx.z;
#pragma unroll
    for (int it = 0; it < 4; ++it) {
        int idx = tid + (it << 8);
        int nl = idx >> 5, e4 = idx & 31;
        float4 v = *reinterpret_cast<const float4*>(
            x + ((size_t)bz * N_ + n0 + nl) * D_ + e0 + (e4 << 2));
        *reinterpret_cast<float4*>(&st[nl][e4 << 2]) = v;
    }
    __syncthreads();
    const size_t blk = ((size_t)bz * 8 + blockIdx.x) * 128 + blockIdx.y;
    uint32_t* dbA = dA + blk * 4096;
    uint32_t* dbB = dB + blk * 4096;
    // xT planes: element (row m = e, k = n)
#pragma unroll
    for (int it = 0; it < 4; ++it) {
        int idx = tid + (it << 8);
        int mm = idx >> 3, k4 = idx & 7, k0 = k4 << 2;
        float va[4];
#pragma unroll
        for (int c = 0; c < 4; ++c) va[c] = st[k0 + c][mm];
        uint16_t h[4], l[4];
#pragma unroll
        for (int c = 0; c < 4; ++c) split_h(va[c], h[c], l[c]);
        int ks = k0 >> 4, kk = k0 & 15;
        {   // A-role
            int rr = mm & 15, mt = mm >> 4;
            int reg = (rr >> 3) + ((kk >> 3) << 1);
            int o = ks * 1024 + mt * 128 +
                    (((rr & 7) << 2) + ((kk & 7) >> 1)) * 4 + reg;
            dbA[o] = pack2h(h[0], h[1]);
            dbA[o + 4] = pack2h(h[2], h[3]);
            dbA[2048 + o] = pack2h(l[0], l[1]);
            dbA[2048 + o + 4] = pack2h(l[2], l[3]);
        }
        {   // B-role
            int nt = mm >> 3, reg = kk >> 3;
            int o = ks * 1024 + nt * 64 +
                    (((mm & 7) << 2) + ((kk & 7) >> 1)) * 2 + reg;
            dbB[o] = pack2h(h[0], h[1]);
            dbB[o + 2] = pack2h(h[2], h[3]);
            dbB[2048 + o] = pack2h(l[0], l[1]);
            dbB[2048 + o + 2] = pack2h(l[2], l[3]);
        }
    }
    // xA planes: element (row m = n, k = e), hi only
#pragma unroll
    for (int it = 0; it < 4; ++it) {
        int idx = tid + (it << 8);
        int nl = idx & 31, eg = idx >> 5;   // eg in [0,32): group of 4 e
        int e_loc = eg << 2;
        uint16_t h[4];
#pragma unroll
        for (int c = 0; c < 4; ++c)
            h[c] = __half_as_ushort(__float2half_rn(st[nl][e_loc + c]));
        const int tileR = bz * 32 + (blockIdx.y >> 2);
        const int kst = blockIdx.x * 4 + (e_loc >> 5);
        uint32_t* db = dXA + ((size_t)tileR * 32 + kst) * 2048;
        const int e_in = e_loc & 31;
        const int ks = e_in >> 4, kk = e_in & 15;
        const int rf = ((blockIdx.y & 3) << 5) + nl;  // row within 128-block
        const int rr = rf & 15, mt = rf >> 4;
        const int reg = (rr >> 3) + ((kk >> 3) << 1);
        const int o = ks * 1024 + mt * 128 +
                      (((rr & 7) << 2) + ((kk & 7) >> 1)) * 4 + reg;
        db[o] = pack2h(h[0], h[1]);
        db[o + 4] = pack2h(h[2], h[3]);
    }
}

// ---------------------------------------------------------------------------
// fused transpose+round: Wv [e][d] -> WvB = B-role hi planes of Wv^T
// (rows d, k = e). grid (8 d-tiles, 32 e-stages, 1).
// ---------------------------------------------------------------------------
__global__ void __launch_bounds__(256)
wvsplit_kernel(const float* __restrict__ Wv, uint32_t* __restrict__ dB) {
    __shared__ float st[32][132];  // [e_local][d_local]
    const int tid = threadIdx.x;
    const int d0 = blockIdx.x * 128, e0 = blockIdx.y * 32;
#pragma unroll
    for (int it = 0; it < 4; ++it) {
        int idx = tid + (it << 8);
        int el = idx >> 5, d4 = idx & 31;
        float4 v = *reinterpret_cast<const float4*>(
            Wv + (size_t)(e0 + el) * D_ + d0 + (d4 << 2));
        *reinterpret_cast<float4*>(&st[el][d4 << 2]) = v;
    }
    __syncthreads();
    uint32_t* db = dB + ((size_t)blockIdx.x * 32 + blockIdx.y) * 2048;
#pragma unroll
    for (int it = 0; it < 4; ++it) {
        int idx = tid + (it << 8);
        int mm = idx >> 3, k4 = idx & 7, k0 = k4 << 2;
        uint16_t h[4];
#pragma unroll
        for (int c = 0; c < 4; ++c)
            h[c] = __half_as_ushort(__float2half_rn(st[k0 + c][mm]));
        int ks = k0 >> 4, kk = k0 & 15;
        int nt = mm >> 3, reg = kk >> 3;
        int o = ks * 1024 + nt * 64 +
                (((mm & 7) << 2) + ((kk & 7) >> 1)) * 2 + reg;
        db[o] = pack2h(h[0], h[1]);
        db[o + 2] = pack2h(h[2], h[3]);
    }
}

// ---------------------------------------------------------------------------
// fused transpose+round: attn [b][e][f] -> aTA = A-role hi-only planes of
// attn^T (rows f, k = e).
// ---------------------------------------------------------------------------
__global__ void __launch_bounds__(256)
atsplit_kernel(const float* __restrict__ attn, uint32_t* __restrict__ dA) {
    __shared__ float st[32][132];
    const int tid = threadIdx.x;
    const int f0 = blockIdx.x * 128, e0 = blockIdx.y * 32;
    const int bz = blockIdx.z;
#pragma unroll
    for (int it = 0; it < 4; ++it) {
        int idx = tid + (it << 8);
        int el = idx >> 5, f4 = idx & 31;
        float4 v = *reinterpret_cast<const float4*>(
            attn + ((size_t)bz * D_ + e0 + el) * D_ + f0 + (f4 << 2));
        *reinterpret_cast<float4*>(&st[el][f4 << 2]) = v;
    }
    __syncthreads();
    const size_t blk = ((size_t)bz * 8 + blockIdx.x) * 32 + blockIdx.y;
    uint32_t* db = dA + blk * 2048;
#pragma unroll
    for (int it = 0; it < 4; ++it) {
        int idx = tid + (it << 8);
        int mm = idx >> 3, k4 = idx & 7, k0 = k4 << 2;
        uint16_t h[4];
#pragma unroll
        for (int c = 0; c < 4; ++c)
            h[c] = __half_as_ushort(__float2half_rn(st[k0 + c][mm]));
        int ks = k0 >> 4, kk = k0 & 15;
        int rr = mm & 15, mt = mm >> 4;
        int reg = (rr >> 3) + ((kk >> 3) << 1);
        int o = ks * 1024 + mt * 128 +
                (((rr & 7) << 2) + ((kk & 7) >> 1)) * 4 + reg;
        db[o] = pack2h(h[0], h[1]);
        db[o + 4] = pack2h(h[2], h[3]);
    }
}

// ---------------------------------------------------------------------------
// converter (weights, A-role hi/lo): fp32 [rows,K] -> planes
// ---------------------------------------------------------------------------
__global__ void __launch_bounds__(256)
conv_kernel(const float* __restrict__ src, uint32_t* __restrict__ dst,
            int ld, int nkst) {
    const int tid = threadIdx.x;
    const int tileR = blockIdx.x, kst = blockIdx.y;
    const float* sb = src + (size_t)tileR * 128 * ld + kst * 32;
    uint32_t* db = dst + ((size_t)tileR * nkst + kst) * 4096;
#pragma unroll
    for (int it = 0; it < 4; ++it) {
        int idx = tid + (it << 8);
        int mm = idx >> 3, k4 = idx & 7;
        float4 v = *reinterpret_cast<const float4*>(sb + (size_t)mm * ld +
                                                    (k4 << 2));
        float va[4] = {v.x, v.y, v.z, v.w};
        uint16_t h[4], l[4];
#pragma unroll
        for (int c = 0; c < 4; ++c) split_h(va[c], h[c], l[c]);
        int k0 = k4 << 2, ks = k0 >> 4, kk = k0 & 15;
        int rr = mm & 15, mt = mm >> 4;
        int reg = (rr >> 3) + ((kk >> 3) << 1);
        int o = ks * 1024 + mt * 128 +
                (((rr & 7) << 2) + ((kk & 7) >> 1)) * 4 + reg;
        db[o] = pack2h(h[0], h[1]);
        db[o + 4] = pack2h(h[2], h[3]);
        db[2048 + o] = pack2h(l[0], l[1]);
        db[2048 + o + 4] = pack2h(l[2], l[3]);
    }
}

// ---------------------------------------------------------------------------
// async GEMM from pre-split planes. cp.async 3-stage; LDS+MMA mainloop.
// SPLITS=3: A hi/lo, B hi/lo, 3 products.  SPLITS=1: A hi, B hi, 1 product.
// KST: k16-steps per pipeline stage. SYM: triangular grid + mirror write.
// PLANES: epilogue writes B-role fp16 planes into Cp (PLO: also lo plane).
// ---------------------------------------------------------------------------
template <int SPLITS, bool HAS_BIAS, bool SYM, bool PLANES, bool PLO, int KST>
__global__ void __launch_bounds__(256, 2)
gemm_async(const uint32_t* __restrict__ Ap, const uint32_t* __restrict__ Bp,
           const float* __restrict__ bias, float* __restrict__ C,
           uint32_t* __restrict__ Cp,
           int Nn, int nst, int mtiles, size_t aBatch, size_t bBatch,
           size_t cB, size_t biasB) {
    int bx, by;
    if (SYM) {
        int t = blockIdx.x;
        int i = (int)((sqrtf(8.f * (float)t + 1.f) - 1.f) * 0.5f);
        while ((i + 1) * (i + 2) / 2 <= t) ++i;
        while (i * (i + 1) / 2 > t) --i;
        by = i;
        bx = t - i * (i + 1) / 2;
    } else {
        bx = blockIdx.x;
        by = blockIdx.y;
    }
    extern __shared__ uint32_t smw[];
    const uint32_t sbase = smem_u32(smw);
    constexpr int AW = 1024 * KST * ((SPLITS == 3) ? 2 : 1);
    constexpr int BW = 1024 * KST * ((SPLITS >= 2) ? 2 : 1);
    constexpr int SW = AW + BW;
    constexpr int NCHUNK = SW / 4 / 256;
    const int tid = threadIdx.x;
    const int lane = tid & 31, wid = tid >> 5;
    const int wm = wid & 1, wn = wid >> 1;
    const uint32_t* Abase =
        Ap + blockIdx.z * aBatch + (size_t)by * nst * AW;
    const uint32_t* Bbase =
        Bp + blockIdx.z * bBatch + (size_t)bx * nst * BW;
    const float* biasb = HAS_BIAS ? bias + blockIdx.z * biasB : nullptr;

    float acc[4][4][4];
#pragma unroll
    for (int i = 0; i < 4; ++i)
#pragma unroll
        for (int j = 0; j < 4; ++j)
#pragma unroll
            for (int e = 0; e < 4; ++e) acc[i][j][e] = 0.f;

    auto issue = [&](int t, int buf) {
        const uint32_t* As = Abase + (size_t)t * AW;
        const uint32_t* Bs = Bbase + (size_t)t * BW;
        const uint32_t sb = sbase + (uint32_t)(buf * SW) * 4u;
#pragma unroll
        for (int c = 0; c < NCHUNK; ++c) {
            int id = tid + (c << 8);
            if (id < AW / 4) cpa16(sb + id * 16, As + id * 4);
            else cpa16(sb + id * 16, Bs + (size_t)(id - AW / 4) * 4);
        }
    };
    auto compute = [&](int buf) {
        const uint32_t* S = smw + buf * SW;
        const uint32_t* Ah = S;
        const uint32_t* Al = S + 2048;
        const uint32_t* Bh = S + AW;
        const uint32_t* Bl = S + AW + 2048;
#pragma unroll
        for (int ks = 0; ks < KST; ++ks) {
            uint32_t bh[4][2], bl[4][2];
#pragma unroll
            for (int j = 0; j < 4; ++j) {
                const int o = ks * 1024 + ((wn << 2) + j) * 64 + (lane << 1);
                *reinterpret_cast<uint2*>(bh[j]) =
                    *reinterpret_cast<const uint2*>(Bh + o);
                if (SPLITS >= 2)
                    *reinterpret_cast<uint2*>(bl[j]) =
                        *reinterpret_cast<const uint2*>(Bl + o);
            }
#pragma unroll
            for (int i = 0; i < 4; ++i) {
                uint32_t ah[4], al[4];
                const int o = ks * 1024 + ((wm << 2) + i) * 128 + (lane << 2);
                *reinterpret_cast<uint4*>(ah) =
                    *reinterpret_cast<const uint4*>(Ah + o);
                if (SPLITS == 3)
                    *reinterpret_cast<uint4*>(al) =
                        *reinterpret_cast<const uint4*>(Al + o);
#pragma unroll
                for (int j = 0; j < 4; ++j) {
                    mma16(acc[i][j], ah, bh[j]);
                    if (SPLITS >= 2) mma16(acc[i][j], ah, bl[j]);
                    if (SPLITS == 3) mma16(acc[i][j], al, bh[j]);
                }
            }
        }
    };

    issue(0, 0);
    asm volatile("cp.async.commit_group;" ::: "memory");
    issue(1, 1);
    asm volatile("cp.async.commit_group;" ::: "memory");
    for (int t = 0; t < nst; ++t) {
        if (t + 1 < nst)
            asm volatile("cp.async.wait_group 1;" ::: "memory");
        else
            asm volatile("cp.async.wait_group 0;" ::: "memory");
        __syncthreads();
        if (t + 2 < nst) {
            issue(t + 2, (t + 2) % 3);
            asm volatile("cp.async.commit_group;" ::: "memory");
        }
        compute(t % 3);
    }

    const int r = lane >> 2, cq = (lane & 3) << 1;
    const int m0 = by * 128, n0 = bx * 128;
    const bool mirror = SYM && (by != bx);
    if (PLANES) {
        constexpr int PW = PLO ? 4096 : 2048;
        const int NKSTD = Nn >> 5;
        uint32_t* Pb = Cp + (size_t)blockIdx.z * mtiles * NKSTD * PW;
#pragma unroll
        for (int i = 0; i < 4; ++i) {
#pragma unroll
            for (int j = 0; j < 4; ++j) {
                const int row0 = m0 + (wm << 6) + (i << 4) + r;
                const int col = n0 + (wn << 5) + (j << 3) + cq;
                uint16_t h[4], l[4];
#pragma unroll
                for (int e = 0; e < 4; ++e) split_h(acc[i][j][e], h[e], l[e]);
                uint32_t* blk =
                    Pb + ((size_t)(row0 >> 7) * NKSTD + (col >> 5)) * PW;
                const int kk = col & 15;
                const int nl = row0 & 127;
                const int wo = ((col >> 4) & 1) * 1024 + (nl >> 3) * 64 +
                               (((nl & 7) << 2) + ((kk & 7) >> 1)) * 2 +
                               ((kk >> 3) & 1);
                blk[wo] = pack2h(h[0], h[1]);
                blk[wo + 64] = pack2h(h[2], h[3]);
                if (PLO) {
                    blk[2048 + wo] = pack2h(l[0], l[1]);
                    blk[2048 + wo + 64] = pack2h(l[2], l[3]);
                }
                if (mirror) {
                    const int rws[4] = {row0, row0, row0 + 8, row0 + 8};
                    const int cls[4] = {col, col + 1, col, col + 1};
#pragma unroll
                    for (int e = 0; e < 4; ++e) {
                        const int rw = rws[e], cl = cls[e];
                        uint32_t* mb =
                            Pb + ((size_t)(cl >> 7) * NKSTD + (rw >> 5)) * PW;
                        const int kkm = rw & 15, nlm = cl & 127;
                        const int wm2 = ((rw >> 4) & 1) * 1024 +
                                        (nlm >> 3) * 64 +
                                        (((nlm & 7) << 2) + ((kkm & 7) >> 1)) *
                                            2 +
                                        ((kkm >> 3) & 1);
                        reinterpret_cast<uint16_t*>(mb)[2 * wm2 + (rw & 1)] =
                            h[e];
                        if (PLO)
                            reinterpret_cast<uint16_t*>(
                                mb)[2 * (2048 + wm2) + (rw & 1)] = l[e];
                    }
                }
            }
        }
    } else {
        float* Cb = C + (size_t)blockIdx.z * cB;
#pragma unroll
        for (int i = 0; i < 4; ++i) {
#pragma unroll
            for (int j = 0; j < 4; ++j) {
                const int row = m0 + (wm << 6) + (i << 4) + r;
                const int col = n0 + (wn << 5) + (j << 3) + cq;
                float o0 = acc[i][j][0], o1 = acc[i][j][1];
                float o2 = acc[i][j][2], o3 = acc[i][j][3];
                if (HAS_BIAS) {
                    float b0 = biasb[col], b1 = biasb[col + 1];
                    o0 += b0; o1 += b1; o2 += b0; o3 += b1;
                }
                *reinterpret_cast<float2*>(Cb + (size_t)row * Nn + col) =
                    make_float2(o0, o1);
                *reinterpret_cast<float2*>(Cb + (size_t)(row + 8) * Nn + col) =
                    make_float2(o2, o3);
            }
        }
    }
}

// ---------------------------------------------------------------------------
// helpers
// ---------------------------------------------------------------------------
__global__ void __launch_bounds__(256)
colsum_kernel(const float* __restrict__ x, float* __restrict__ s) {
    const int e = blockIdx.x * 256 + threadIdx.x;
    const int b = blockIdx.y;
    const float* p = x + (size_t)b * N_ * D_ + e;
    float a0 = 0.f, a1 = 0.f, a2 = 0.f, a3 = 0.f;
    for (int n = 0; n < N_; n += 4) {
        a0 += p[(size_t)n * D_];
        a1 += p[(size_t)(n + 1) * D_];
        a2 += p[(size_t)(n + 2) * D_];
        a3 += p[(size_t)(n + 3) * D_];
    }
    s[b * D_ + e] = (a0 + a1) + (a2 + a3);
}

__global__ void __launch_bounds__(256)
rsum_kernel(const float* __restrict__ attn, const float* __restrict__ bv,
            float* __restrict__ r) {
    const int f = blockIdx.x * 256 + threadIdx.x;
    const int b = blockIdx.y;
    const float* p = attn + (size_t)b * D_ * D_ + f;
    float a0 = 0.f, a1 = 0.f;
    for (int e = 0; e < D_; e += 2) {
        a0 += bv[e] * p[(size_t)e * D_];
        a1 += bv[e + 1] * p[(size_t)(e + 1) * D_];
    }
    r[b * D_ + f] = a0 + a1;
}

__global__ void __launch_bounds__(256)
gemv_kernel(const float* __restrict__ Wq, const float* __restrict__ Wk,
            const float* __restrict__ bk, const float* __restrict__ s,
            float* __restrict__ u, float* __restrict__ w) {
    const int wg = blockIdx.x * 8 + (threadIdx.x >> 5);
    const int lane = threadIdx.x & 31;
    const int b = wg >> 11;
    const int o = wg & 2047;
    const bool is_u = o < 1024;
    const int row = is_u ? o : o - 1024;
    const float* W = (is_u ? Wq : Wk) + (size_t)row * D_;
    const float* sb = s + b * D_;
    float acc = 0.f;
#pragma unroll
    for (int i = 0; i < 32; ++i) acc += W[lane + (i << 5)] * sb[lane + (i << 5)];
#pragma unroll
    for (int off = 16; off; off >>= 1)
        acc += __shfl_xor_sync(0xffffffffu, acc, off);
    if (lane == 0) {
        if (is_u) u[b * D_ + row] = acc;
        else      w[b * D_ + row] = acc + (float)N_ * bk[row];
    }
}

__global__ void __launch_bounds__(256)
softmax_fused(float* __restrict__ L, const float* __restrict__ u,
              const float* __restrict__ w, const float* __restrict__ bq,
              const float* __restrict__ bk) {
    const int row = blockIdx.x;
    const int b = row >> 10, e = row & 1023;
    float* p = L + (size_t)row * 1024;
    const float uu = u[b * D_ + e];
    const float bb = bq[e];
    const float* wb = w + b * D_;
    const int t = threadIdx.x;
    const int lane = t & 31, wid = t >> 5;
    __shared__ float red[8];

    float v[4];
#pragma unroll
    for (int i = 0; i < 4; ++i) {
        const int f = t + (i << 8);
        v[i] = p[f] + uu * bk[f] + bb * wb[f];
    }
    float m = fmaxf(fmaxf(v[0], v[1]), fmaxf(v[2], v[3]));
#pragma unroll
    for (int o = 16; o; o >>= 1) m = fmaxf(m, __shfl_xor_sync(0xffffffffu, m, o));
    if (lane == 0) red[wid] = m;
    __syncthreads();
    if (t < 32) {
        float x = (t < 8) ? red[t] : -3.4e38f;
#pragma unroll
        for (int o = 4; o; o >>= 1) x = fmaxf(x, __shfl_xor_sync(0xffffffffu, x, o));
        if (t == 0) red[0] = x;
    }
    __syncthreads();
    m = red[0];
    __syncthreads();
    float ssum = 0.f;
#pragma unroll
    for (int i = 0; i < 4; ++i) {
        v[i] = expf(v[i] - m);
        ssum += v[i];
    }
#pragma unroll
    for (int o = 16; o; o >>= 1) ssum += __shfl_xor_sync(0xffffffffu, ssum, o);
    if (lane == 0) red[wid] = ssum;
    __syncthreads();
    if (t < 32) {
        float x = (t < 8) ? red[t] : 0.f;
#pragma unroll
        for (int o = 4; o; o >>= 1) x += __shfl_xor_sync(0xffffffffu, x, o);
        if (t == 0) red[0] = x;
    }
    __syncthreads();
    const float inv = 1.0f / red[0];
#pragma unroll
    for (int i = 0; i < 4; ++i) p[t + (i << 8)] = v[i] * inv;
}

extern "C" void kernel_launch(void* const* d_in, const int* in_sizes, int n_in,
                              void* d_out, int out_size) {
    const float* x  = (const float*)d_in[0];
    const float* Wq = (const float*)d_in[1];
    const float* bq = (const float*)d_in[2];
    const float* Wk = (const float*)d_in[3];
    const float* bk = (const float*)d_in[4];
    const float* Wv = (const float*)d_in[5];
    const float* bv = (const float*)d_in[6];
    float* out = (float*)d_out;

    float *L, *s, *u, *w, *r;
    cudaGetSymbolAddress((void**)&L, g_L);
    cudaGetSymbolAddress((void**)&s, g_s);
    cudaGetSymbolAddress((void**)&u, g_u);
    cudaGetSymbolAddress((void**)&w, g_w);
    cudaGetSymbolAddress((void**)&r, g_r);
    uint32_t *xTA, *xTB, *xA, *GB, *T1B, *W2B, *aTA, *WqA, *WkA, *WvB;
    cudaGetSymbolAddress((void**)&xTA, g_xTA);
    cudaGetSymbolAddress((void**)&xTB, g_xTB);
    cudaGetSymbolAddress((void**)&xA, g_xA);
    cudaGetSymbolAddress((void**)&GB, g_GB);
    cudaGetSymbolAddress((void**)&T1B, g_T1B);
    cudaGetSymbolAddress((void**)&W2B, g_W2B);
    cudaGetSymbolAddress((void**)&aTA, g_aTA);
    cudaGetSymbolAddress((void**)&WqA, g_WqA);
    cudaGetSymbolAddress((void**)&WkA, g_WkA);
    cudaGetSymbolAddress((void**)&WvB, g_WvB);

    constexpr int SMEM3 = 3 * (4096 + 4096) * 4;  // 98,304 B
    constexpr int SMEM1 = 3 * (4096 + 4096) * 4;  // 98,304 B
    cudaFuncSetAttribute(gemm_async<3, false, true, true, true, 2>,
                         cudaFuncAttributeMaxDynamicSharedMemorySize, SMEM3);
    cudaFuncSetAttribute(gemm_async<3, false, false, true, true, 2>,
                         cudaFuncAttributeMaxDynamicSharedMemorySize, SMEM3);
    cudaFuncSetAttribute(gemm_async<3, false, false, false, false, 2>,
                         cudaFuncAttributeMaxDynamicSharedMemorySize, SMEM3);
    cudaFuncSetAttribute(gemm_async<1, false, false, true, false, 4>,
                         cudaFuncAttributeMaxDynamicSharedMemorySize, SMEM1);
    cudaFuncSetAttribute(gemm_async<1, true, false, false, false, 4>,
                         cudaFuncAttributeMaxDynamicSharedMemorySize, SMEM1);

    const dim3 blk(256);

    // fused split-transpose of x -> xTA / xTB / xA planes (x read ONCE)
    xsplit_kernel<<<dim3(8, 128, B_), blk>>>(x, xTA, xTB, xA);

    // weight plane converters (Wv fused transpose+round)
    wvsplit_kernel<<<dim3(8, 32, 1), blk>>>(Wv, WvB);
    conv_kernel<<<dim3(8, 32, 1), blk>>>(Wk, WkA, D_, 32);
    conv_kernel<<<dim3(8, 32, 1), blk>>>(Wq, WqA, D_, 32);

    // small precomputes
    colsum_kernel<<<dim3(4, 8), 256>>>(x, s);
    gemv_kernel<<<2048, 256>>>(Wq, Wk, bk, s, u, w);

    // G[b] = xT xT^T  (triangular grid, 3-split) -> GB planes
    gemm_async<3, false, true, true, true, 2><<<dim3(36, 1, B_), blk, SMEM3>>>(
        xTA, xTB, nullptr, nullptr, GB, D_, 128, 8,
        (size_t)8 * 128 * 4096, (size_t)8 * 128 * 4096, 0, 0);

    // T1t[b] = Wk G[b]  (3-split) -> T1B planes
    gemm_async<3, false, false, true, true, 2><<<dim3(8, 8, B_), blk, SMEM3>>>(
        WkA, GB, nullptr, nullptr, T1B, D_, 32, 8,
        0, (size_t)8 * 32 * 4096, 0, 0);

    // L[b] = Wq T1t[b]^T  (3-split, fp32 out for softmax)
    gemm_async<3, false, false, false, false, 2><<<dim3(8, 8, B_), blk, SMEM3>>>(
        WqA, T1B, nullptr, L, nullptr, D_, 32, 8,
        0, (size_t)8 * 32 * 4096, (size_t)D_ * D_, 0);

    // softmax with rank-1 corrections -> attn (in place)
    softmax_fused<<<B_ * D_, 256>>>(L, u, w, bq, bk);

    // fused transpose+round attn -> aTA planes ; r = bv^T attn
    atsplit_kernel<<<dim3(8, 32, B_), blk>>>(L, aTA);
    rsum_kernel<<<dim3(4, 8), 256>>>(L, bv, r);

    // W2t[b] = aT[b] WvT^T  (pure fp16, k64 stages) -> W2B hi planes
    gemm_async<1, false, false, true, false, 4><<<dim3(8, 8, B_), blk, SMEM1>>>(
        aTA, WvB, nullptr, nullptr, W2B, D_, 16, 8,
        (size_t)8 * 32 * 2048, 0, 0, 0);

    // out[b] = x[b] W2t[b]^T + r[b]  (pure fp16, k64 stages, fp32 out)
    gemm_async<1, true, false, false, false, 4><<<dim3(8, 32, B_), blk, SMEM1>>>(
        xA, W2B, r, out, nullptr, D_, 16, 8,
        (size_t)32 * 32 * 2048, (size_t)8 * 32 * 2048,
        (size_t)N_ * D_, D_);
}